// round 11
// baseline (speedup 1.0000x reference)
#include <cuda_runtime.h>
#include <mma.h>
#include <math.h>

using namespace nvcuda;

#define NN   4096
#define DIMC 128
#define HEADSC 8
#define HGC  1024      // HEADS * GC
#define EC   65536
#define FFNC 2048
#define NPROJ 3200     // 3*1024 + 128 (q|k|v|skip)

// ---------------- scratch (device globals; no allocation allowed) ----------------
__device__ float g_xn[NN*DIMC];
__device__ float g_qkv[NN*3*DIMC];
__device__ float g_attn[NN*DIMC];
__device__ float g_x1[NN*DIMC];
__device__ float g_xn2[NN*DIMC];
__device__ float g_qkvg[(size_t)NN*NPROJ];   // per row: qg|kg|vg|xr
__device__ float g_t[NN*HGC];                // per-head W_h @ qg
__device__ float g_packT[HEADSC*128*128];
__device__ float g_packC[HEADSC*128*128];
__device__ float g_packW[DIMC*NPROJ];        // [wq|wk|wv|wskip] col-concat
__device__ float g_packB[NPROJ];
__device__ float g_cnorm[NN*HGC];
__device__ float g_vsum[NN*DIMC];
__device__ int   g_deg[NN];
__device__ int   g_off[NN+1];
__device__ int   g_cur[NN];
__device__ int   g_eid[EC];
__device__ float g_aggout[NN*DIMC];
__device__ float g_x2[NN*DIMC];
__device__ float g_xn3[NN*DIMC];
__device__ float g_ffn[NN*FFNC];
__device__ float g_x3[NN*DIMC];

// ---------------- helpers ----------------
__device__ __forceinline__ float warp_sum(float v) {
    #pragma unroll
    for (int o = 16; o > 0; o >>= 1) v += __shfl_xor_sync(0xffffffffu, v, o);
    return v;
}

__device__ __forceinline__ void warp_sum4(float& a, float& b, float& c, float& d) {
    #pragma unroll
    for (int o = 16; o > 0; o >>= 1) {
        a += __shfl_xor_sync(0xffffffffu, a, o);
        b += __shfl_xor_sync(0xffffffffu, b, o);
        c += __shfl_xor_sync(0xffffffffu, c, o);
        d += __shfl_xor_sync(0xffffffffu, d, o);
    }
}

// exp(s) for |s| <~ 0.7 : degree-5 Taylor
__device__ __forceinline__ float exp_poly(float s) {
    float p = fmaf(8.333333333e-3f, s, 4.166666667e-2f);
    p = fmaf(p, s, 1.666666667e-1f);
    p = fmaf(p, s, 0.5f);
    p = fmaf(p, s, 1.0f);
    p = fmaf(p, s, 1.0f);
    return p;
}

// MODE: 0 = +bias, 1 = +bias->GELU, 2 = +bias+aux1, 3 = +bias->sigmoid gate(a1,a2),
//       4 = +aux1 (no bias), 5 = raw store (no bias, no aux)
template<int MODE>
__device__ __forceinline__ float epilogue(float acc, float bias, float a1, float a2) {
    float v = (MODE == 4 || MODE == 5) ? acc : (acc + bias);
    if (MODE == 1) {
        v = 0.5f * v * (1.0f + erff(v * 0.7071067811865476f));
    } else if (MODE == 2 || MODE == 4) {
        v = v + a1;
    } else if (MODE == 3) {
        float s = 1.0f / (1.0f + expf(-v));
        v = a1 * s + a2 * (1.0f - s);
    }
    return v;
}

// ---------------- TF32 tensor-core GEMM via wmma (m16n16k8) ----------------
// A row-major [M,K], B row-major [K,N]. K-tile = 32, double-buffered smem.
// KFIX > 0: compile-time K (full unroll). MODE 5: direct gmem store.
template<int BM, int BN, int WARPS_M, int WARPS_N, int WM, int WN, int MODE, bool DUALA, int KFIX>
__global__ void __launch_bounds__(WARPS_M*WARPS_N*32)
wgemm(const float* __restrict__ A, const float* __restrict__ B,
      const float* __restrict__ bias, float* __restrict__ C,
      int K, int lda, int ldb, int ldc,
      long sA, long sB, long sC, long sBias,
      const float* __restrict__ aux1, const float* __restrict__ aux2,
      const float* __restrict__ A2) {
    constexpr int NT  = WARPS_M * WARPS_N * 32;
    constexpr int SAS = 36;
    constexpr int SBS = BN + 4;
    constexpr int AI  = (BM * 8) / NT;
    constexpr int BI  = (BN * 8) / NT;
    constexpr int WORDS = BM * SAS + 32 * SBS;
    constexpr int STAGES = (WORDS * 8 <= 48 * 1024) ? 2 : 1;
    __shared__ float As[STAGES][BM * SAS];
    __shared__ float Bs[STAGES][32 * SBS];
    const int tid  = threadIdx.x;
    const int wid  = tid >> 5;
    const int lane = tid & 31;
    const int bm = blockIdx.y * BM;
    const int bn = blockIdx.x * BN;
    A += (size_t)blockIdx.z * sA;
    B += (size_t)blockIdx.z * sB;
    C += (size_t)blockIdx.z * sC;
    if (MODE != 4 && MODE != 5) bias += (size_t)blockIdx.z * sBias;
    const int warp_m = (wid / WARPS_N) * (WM * 16);
    const int warp_n = (wid % WARPS_N) * (WN * 16);
    const int KK = KFIX ? KFIX : K;

    wmma::fragment<wmma::accumulator, 16, 16, 8, float> cf[WM][WN];
    #pragma unroll
    for (int i = 0; i < WM; i++)
        #pragma unroll
        for (int j = 0; j < WN; j++) wmma::fill_fragment(cf[i][j], 0.0f);

    float4 av[AI], bv[BI];
    auto load_tiles = [&](int k0) {
        #pragma unroll
        for (int i = 0; i < AI; i++) {
            int idx = tid + i * NT;
            int kk = k0 + (idx & 7) * 4;
            const float* src;
            if (DUALA && kk >= 128) src = &A2[(size_t)(bm + (idx >> 3)) * 128 + (kk - 128)];
            else                    src = &A[(size_t)(bm + (idx >> 3)) * lda + kk];
            av[i] = *(const float4*)src;
        }
        #pragma unroll
        for (int i = 0; i < BI; i++) {
            int idx = tid + i * NT;
            bv[i] = *(const float4*)&B[(size_t)(k0 + idx / (BN / 4)) * ldb + bn + (idx % (BN / 4)) * 4];
        }
    };
    auto store_smem = [&](int st) {
        #pragma unroll
        for (int i = 0; i < AI; i++) {
            int idx = tid + i * NT;
            *(float4*)&As[st][(idx >> 3) * SAS + (idx & 7) * 4] = av[i];
        }
        #pragma unroll
        for (int i = 0; i < BI; i++) {
            int idx = tid + i * NT;
            *(float4*)&Bs[st][(idx / (BN / 4)) * SBS + (idx % (BN / 4)) * 4] = bv[i];
        }
    };

    int cur = 0;
    load_tiles(0);
    store_smem(0);
    __syncthreads();
    for (int k0 = 0; k0 < KK; k0 += 32) {
        bool more = (k0 + 32 < KK);
        if (more) load_tiles(k0 + 32);
        #pragma unroll
        for (int kk = 0; kk < 4; kk++) {
            wmma::fragment<wmma::matrix_a, 16, 16, 8, wmma::precision::tf32, wmma::row_major> af[WM];
            wmma::fragment<wmma::matrix_b, 16, 16, 8, wmma::precision::tf32, wmma::row_major> bf[WN];
            #pragma unroll
            for (int i = 0; i < WM; i++)
                wmma::load_matrix_sync(af[i], &As[cur][(warp_m + i * 16) * SAS + kk * 8], SAS);
            #pragma unroll
            for (int j = 0; j < WN; j++)
                wmma::load_matrix_sync(bf[j], &Bs[cur][kk * 8 * SBS + warp_n + j * 16], SBS);
            #pragma unroll
            for (int i = 0; i < WM; i++)
                #pragma unroll
                for (int j = 0; j < WN; j++)
                    wmma::mma_sync(cf[i][j], af[i], bf[j], cf[i][j]);
        }
        if (more) {
            if (STAGES == 2) {
                store_smem(1 - cur);
                __syncthreads();
                cur ^= 1;
            } else {
                __syncthreads();
                store_smem(0);
                __syncthreads();
            }
        }
    }

    if (MODE == 5) {   // direct gmem store
        #pragma unroll
        for (int i = 0; i < WM; i++)
            #pragma unroll
            for (int j = 0; j < WN; j++) {
                int row0 = bm + warp_m + i * 16;
                int col0 = bn + warp_n + j * 16;
                wmma::store_matrix_sync(&C[(size_t)row0 * ldc + col0], cf[i][j], ldc,
                                        wmma::mem_row_major);
            }
        return;
    }

    __syncthreads();
    float* scratch = &As[0][wid * 256];
    #pragma unroll
    for (int i = 0; i < WM; i++) {
        #pragma unroll
        for (int j = 0; j < WN; j++) {
            wmma::store_matrix_sync(scratch, cf[i][j], 16, wmma::mem_row_major);
            __syncwarp();
            int row0 = bm + warp_m + i * 16;
            int col0 = bn + warp_n + j * 16;
            #pragma unroll
            for (int e = 0; e < 8; e++) {
                int idx = lane + e * 32;
                int r = row0 + (idx >> 4);
                int c = col0 + (idx & 15);
                float acc = scratch[idx];
                float bvv = (MODE == 4) ? 0.0f : bias[c];
                size_t o = (size_t)r * ldc + c;
                float u = 0.f, w = 0.f;
                if (MODE == 2 || MODE == 3 || MODE == 4) u = aux1[o];
                if (MODE == 3) w = aux2[o];
                C[o] = epilogue<MODE>(acc, bvv, u, w);
            }
            __syncwarp();
        }
    }
}

// ---------------- LayerNorm ----------------
__global__ void ln_kernel(const float* __restrict__ x, const float* __restrict__ g,
                          const float* __restrict__ b, float* __restrict__ out) {
    int row = blockIdx.x, t = threadIdx.x;
    float v = x[row * DIMC + t];
    __shared__ float red[4];
    float s = warp_sum(v);
    if ((t & 31) == 0) red[t >> 5] = s;
    __syncthreads();
    float mean = (red[0] + red[1] + red[2] + red[3]) * (1.0f / 128.0f);
    float d = v - mean;
    float s2 = warp_sum(d * d);
    __syncthreads();
    if ((t & 31) == 0) red[t >> 5] = s2;
    __syncthreads();
    float var = (red[0] + red[1] + red[2] + red[3]) * (1.0f / 128.0f);
    out[row * DIMC + t] = d * rsqrtf(var + 1e-5f) * g[t] + b[t];
}

// ---------------- dense MHA via TF32 wmma (flash-style, no-max softmax) ----------------
#define ABK 64
#define APS 68
__global__ void __launch_bounds__(256)
attn_wmma_kernel(const float* __restrict__ qkv, float* __restrict__ attn) {
    __shared__ float Ks[ABK * 16];
    __shared__ float Vs[ABK * 16];
    __shared__ float Ps[8 * 16 * APS];
    __shared__ float dens[128];
    const int tid  = threadIdx.x;
    const int wid  = tid >> 5;
    const int lane = tid & 31;
    const int h  = blockIdx.y;
    const int q0 = blockIdx.x * 128;
    float* Pw = &Ps[wid * 16 * APS];

    #pragma unroll
    for (int i = 0; i < 2; i++) {
        int idx = tid + i * 256;
        int r = idx >> 2, d4 = (idx & 3) * 4;
        float4 q4 = *(const float4*)&qkv[(size_t)(q0 + r) * 384 + h * 16 + d4];
        Ps[r * 16 + d4 + 0] = q4.x * 0.25f;
        Ps[r * 16 + d4 + 1] = q4.y * 0.25f;
        Ps[r * 16 + d4 + 2] = q4.z * 0.25f;
        Ps[r * 16 + d4 + 3] = q4.w * 0.25f;
    }
    __syncthreads();
    wmma::fragment<wmma::matrix_a, 16, 16, 8, wmma::precision::tf32, wmma::row_major> af[2];
    #pragma unroll
    for (int k0 = 0; k0 < 2; k0++)
        wmma::load_matrix_sync(af[k0], &Ps[(wid * 16) * 16 + k0 * 8], 16);
    __syncthreads();

    wmma::fragment<wmma::accumulator, 16, 16, 8, float> oacc, dacc;
    wmma::fill_fragment(oacc, 0.0f);
    wmma::fill_fragment(dacc, 0.0f);
    wmma::fragment<wmma::matrix_b, 16, 16, 8, wmma::precision::tf32, wmma::row_major> bones;
    wmma::fill_fragment(bones, 1.0f);

    const int key = tid >> 2, d4 = (tid & 3) * 4;
    float4 k4 = *(const float4*)&qkv[(size_t)key * 384 + 128 + h * 16 + d4];
    float4 v4 = *(const float4*)&qkv[(size_t)key * 384 + 256 + h * 16 + d4];

    for (int kt = 0; kt < NN; kt += ABK) {
        __syncthreads();
        *(float4*)&Ks[key * 16 + d4] = k4;
        *(float4*)&Vs[key * 16 + d4] = v4;
        __syncthreads();
        if (kt + ABK < NN) {
            const float* kp = &qkv[(size_t)(kt + ABK + key) * 384 + 128 + h * 16 + d4];
            k4 = *(const float4*)kp;
            v4 = *(const float4*)(kp + 128);
        }

        wmma::fragment<wmma::accumulator, 16, 16, 8, float> sacc[4];
        #pragma unroll
        for (int nt = 0; nt < 4; nt++) wmma::fill_fragment(sacc[nt], 0.0f);
        #pragma unroll
        for (int k0 = 0; k0 < 2; k0++) {
            #pragma unroll
            for (int nt = 0; nt < 4; nt++) {
                wmma::fragment<wmma::matrix_b, 16, 16, 8, wmma::precision::tf32, wmma::col_major> bf;
                wmma::load_matrix_sync(bf, &Ks[(nt * 16) * 16 + k0 * 8], 16);
                wmma::mma_sync(sacc[nt], af[k0], bf, sacc[nt]);
            }
        }
        #pragma unroll
        for (int nt = 0; nt < 4; nt++) {
            #pragma unroll
            for (int t = 0; t < sacc[nt].num_elements; t++)
                sacc[nt].x[t] = exp_poly(sacc[nt].x[t]);
            wmma::store_matrix_sync(&Pw[nt * 16], sacc[nt], APS, wmma::mem_row_major);
        }
        __syncwarp();
        #pragma unroll
        for (int k0 = 0; k0 < 8; k0++) {
            wmma::fragment<wmma::matrix_a, 16, 16, 8, wmma::precision::tf32, wmma::row_major> pa;
            wmma::fragment<wmma::matrix_b, 16, 16, 8, wmma::precision::tf32, wmma::row_major> vb;
            wmma::load_matrix_sync(pa, &Pw[k0 * 8], APS);
            wmma::load_matrix_sync(vb, &Vs[(k0 * 8) * 16], 16);
            wmma::mma_sync(oacc, pa, vb, oacc);
            wmma::mma_sync(dacc, pa, bones, dacc);
        }
        __syncwarp();
    }

    wmma::store_matrix_sync(Pw, dacc, APS, wmma::mem_row_major);
    __syncwarp();
    if (lane < 16) dens[wid * 16 + lane] = Pw[lane * APS];
    __syncwarp();
    wmma::store_matrix_sync(Pw, oacc, APS, wmma::mem_row_major);
    __syncwarp();
    #pragma unroll
    for (int e = 0; e < 8; e++) {
        int idx = lane + e * 32;
        int r = idx >> 4, c = idx & 15;
        float v = Pw[r * APS + c] / dens[wid * 16 + r];
        attn[(size_t)(q0 + wid * 16 + r) * DIMC + h * 16 + c] = v;
    }
}

// ---------------- packT via tiled transpose ----------------
__global__ void packT_kernel(const float* __restrict__ w_edge) {
    __shared__ float tile[32][33];
    int h  = blockIdx.z;
    int k0 = blockIdx.x * 32;
    int j0 = blockIdx.y * 32;
    int tx = threadIdx.x, ty0 = threadIdx.y;
    #pragma unroll
    for (int i = 0; i < 4; i++) {
        int j = j0 + ty0 + i * 8;
        tile[ty0 + i * 8][tx] = w_edge[(size_t)j * HGC + h * 128 + k0 + tx];
    }
    __syncthreads();
    #pragma unroll
    for (int i = 0; i < 4; i++) {
        int k = k0 + ty0 + i * 8;
        g_packT[h * 16384 + k * 128 + j0 + tx] = tile[tx][ty0 + i * 8];
    }
}

// ---------------- pack [wq|wk|wv|wskip] + biases + packC; zero g_deg ----------------
__global__ void packw_kernel(const float* __restrict__ wq, const float* __restrict__ wk,
                             const float* __restrict__ wv, const float* __restrict__ wsk,
                             const float* __restrict__ bq, const float* __restrict__ bk,
                             const float* __restrict__ bv, const float* __restrict__ bsk,
                             const float* __restrict__ w_edge) {
    for (int idx = blockIdx.x * blockDim.x + threadIdx.x; idx < DIMC * NPROJ;
         idx += gridDim.x * blockDim.x) {
        int k = idx / NPROJ, j = idx % NPROJ;
        float v;
        if (j < 1024)      v = wq[k * 1024 + j];
        else if (j < 2048) v = wk[k * 1024 + j - 1024];
        else if (j < 3072) v = wv[k * 1024 + j - 2048];
        else               v = wsk[k * 128 + j - 3072];
        g_packW[idx] = v;
        if (idx < HEADSC * 128 * 128) {
            // packC[(h*128+k)*128 + j] = w_edge[k*HGC + h*128 + j]
            int jj = idx & 127;
            int kk = (idx >> 7) & 127;
            int hh = idx >> 14;
            g_packC[idx] = w_edge[(size_t)kk * HGC + hh * 128 + jj];
        }
        if (idx < NPROJ) {
            float bvv;
            if (idx < 1024)      bvv = bq[idx];
            else if (idx < 2048) bvv = bk[idx - 1024];
            else if (idx < 3072) bvv = bv[idx - 2048];
            else                 bvv = bsk[idx - 3072];
            g_packB[idx] = bvv;
        }
        if (idx < NN) g_deg[idx] = 0;
    }
}

// ---------------- CSR build ----------------
__global__ void hist_kernel(const int* __restrict__ ei) {
    const int* dst = ei + EC;
    for (int e = blockIdx.x * blockDim.x + threadIdx.x; e < EC; e += gridDim.x * blockDim.x)
        atomicAdd(&g_deg[dst[e]], 1);
}
__global__ void scan_kernel() {   // warp-scan; also initializes g_cur
    int t = threadIdx.x;
    int lane = t & 31, w = t >> 5;
    int base = t * 4;
    int d0 = g_deg[base], d1 = g_deg[base+1], d2 = g_deg[base+2], d3 = g_deg[base+3];
    int tot = d0 + d1 + d2 + d3;
    int v = tot;
    #pragma unroll
    for (int o = 1; o < 32; o <<= 1) {
        int u = __shfl_up_sync(0xffffffffu, v, o);
        if (lane >= o) v += u;
    }
    __shared__ int wsum[32];
    if (lane == 31) wsum[w] = v;
    __syncthreads();
    if (t < 32) {
        int wv = wsum[t];
        #pragma unroll
        for (int o = 1; o < 32; o <<= 1) {
            int u = __shfl_up_sync(0xffffffffu, wv, o);
            if (t >= o) wv += u;
        }
        wsum[t] = wv;
    }
    __syncthreads();
    int incl = v + (w ? wsum[w - 1] : 0);
    int run = incl - tot;
    g_off[base] = run;   g_cur[base] = run;     run += d0;
    g_off[base+1] = run; g_cur[base+1] = run;   run += d1;
    g_off[base+2] = run; g_cur[base+2] = run;   run += d2;
    g_off[base+3] = run; g_cur[base+3] = run;   run += d3;
    if (t == 1023) g_off[NN] = incl;
}
__global__ void scatter_kernel(const int* __restrict__ ei) {
    const int* dst = ei + EC;
    for (int e = blockIdx.x * blockDim.x + threadIdx.x; e < EC; e += gridDim.x * blockDim.x) {
        int p = atomicAdd(&g_cur[dst[e]], 1);
        g_eid[p] = e;
    }
}

// ---------------- graph aggregation: smem edge staging + inline s0 ----------------
// qkvg rows: [qg(1024) | kg(1024) | vg(1024) | xr(128)], stride NPROJ.
__global__ void graph_agg3_kernel(const int* __restrict__ ei,
                                  const float* __restrict__ edge_attr,
                                  const float* __restrict__ b_edge,
                                  const float* __restrict__ qkvg) {
    int n = blockIdx.x;
    int tid = threadIdx.x;
    int h = tid >> 5;
    int lane = tid & 31;
    const int* src = ei;
    const float invsq = 0.08838834764831845f;  // 1/sqrt(128)
    const int hoff = h * 128 + lane * 4;
    float4 qh = *(const float4*)&qkvg[(size_t)n * NPROJ + hoff];
    qh.x *= invsq; qh.y *= invsq; qh.z *= invsq; qh.w *= invsq;
    float4 th = *(const float4*)&g_t[n * HGC + hoff];
    th.x *= invsq; th.y *= invsq; th.z *= invsq; th.w *= invsq;
    float4 be4 = *(const float4*)&b_edge[hoff];
    float s0s = warp_sum(qh.x*be4.x + qh.y*be4.y + qh.z*be4.z + qh.w*be4.w);

    __shared__ float ea_s[8][132];
    __shared__ int src_s[8];
    float4 cacc = {0.f, 0.f, 0.f, 0.f};
    float4 vacc = {0.f, 0.f, 0.f, 0.f};
    float den = 0.0f;
    int beg = g_off[n], end = g_off[n + 1];

    for (int i0 = beg; i0 < end; i0 += 8) {
        int cnt = min(8, end - i0);
        __syncthreads();
        if (h < cnt) {
            int e = g_eid[i0 + h];
            if (lane == 0) src_s[h] = src[e];
            *(float4*)&ea_s[h][lane * 4] = *(const float4*)&edge_attr[(size_t)e * DIMC + lane * 4];
        }
        __syncthreads();
        int j = 0;
        for (; j + 3 < cnt; j += 4) {
            int sa = src_s[j], sb = src_s[j+1], sc = src_s[j+2], sd = src_s[j+3];
            float4 ea0 = *(const float4*)&ea_s[j  ][lane * 4];
            float4 ea1 = *(const float4*)&ea_s[j+1][lane * 4];
            float4 ea2 = *(const float4*)&ea_s[j+2][lane * 4];
            float4 ea3 = *(const float4*)&ea_s[j+3][lane * 4];
            float4 ka = *(const float4*)&qkvg[(size_t)sa * NPROJ + 1024 + hoff];
            float4 kb = *(const float4*)&qkvg[(size_t)sb * NPROJ + 1024 + hoff];
            float4 kc = *(const float4*)&qkvg[(size_t)sc * NPROJ + 1024 + hoff];
            float4 kd = *(const float4*)&qkvg[(size_t)sd * NPROJ + 1024 + hoff];
            float4 va = *(const float4*)&qkvg[(size_t)sa * NPROJ + 2048 + hoff];
            float4 vb = *(const float4*)&qkvg[(size_t)sb * NPROJ + 2048 + hoff];
            float4 vc = *(const float4*)&qkvg[(size_t)sc * NPROJ + 2048 + hoff];
            float4 vd = *(const float4*)&qkvg[(size_t)sd * NPROJ + 2048 + hoff];
            float t0 = qh.x*ka.x + qh.y*ka.y + qh.z*ka.z + qh.w*ka.w;
            t0 = fmaf(th.x, ea0.x, t0); t0 = fmaf(th.y, ea0.y, t0);
            t0 = fmaf(th.z, ea0.z, t0); t0 = fmaf(th.w, ea0.w, t0);
            float t1 = qh.x*kb.x + qh.y*kb.y + qh.z*kb.z + qh.w*kb.w;
            t1 = fmaf(th.x, ea1.x, t1); t1 = fmaf(th.y, ea1.y, t1);
            t1 = fmaf(th.z, ea1.z, t1); t1 = fmaf(th.w, ea1.w, t1);
            float t2 = qh.x*kc.x + qh.y*kc.y + qh.z*kc.z + qh.w*kc.w;
            t2 = fmaf(th.x, ea2.x, t2); t2 = fmaf(th.y, ea2.y, t2);
            t2 = fmaf(th.z, ea2.z, t2); t2 = fmaf(th.w, ea2.w, t2);
            float t3 = qh.x*kd.x + qh.y*kd.y + qh.z*kd.z + qh.w*kd.w;
            t3 = fmaf(th.x, ea3.x, t3); t3 = fmaf(th.y, ea3.y, t3);
            t3 = fmaf(th.z, ea3.z, t3); t3 = fmaf(th.w, ea3.w, t3);
            warp_sum4(t0, t1, t2, t3);
            float p0 = expf(t0 + s0s), p1 = expf(t1 + s0s);
            float p2 = expf(t2 + s0s), p3 = expf(t3 + s0s);
            den += (p0 + p1) + (p2 + p3);
            cacc.x = fmaf(p0, ea0.x, fmaf(p1, ea1.x, fmaf(p2, ea2.x, fmaf(p3, ea3.x, cacc.x))));
            cacc.y = fmaf(p0, ea0.y, fmaf(p1, ea1.y, fmaf(p2, ea2.y, fmaf(p3, ea3.y, cacc.y))));
            cacc.z = fmaf(p0, ea0.z, fmaf(p1, ea1.z, fmaf(p2, ea2.z, fmaf(p3, ea3.z, cacc.z))));
            cacc.w = fmaf(p0, ea0.w, fmaf(p1, ea1.w, fmaf(p2, ea2.w, fmaf(p3, ea3.w, cacc.w))));
            vacc.x = fmaf(p0, va.x, fmaf(p1, vb.x, fmaf(p2, vc.x, fmaf(p3, vd.x, vacc.x))));
            vacc.y = fmaf(p0, va.y, fmaf(p1, vb.y, fmaf(p2, vc.y, fmaf(p3, vd.y, vacc.y))));
            vacc.z = fmaf(p0, va.z, fmaf(p1, vb.z, fmaf(p2, vc.z, fmaf(p3, vd.z, vacc.z))));
            vacc.w = fmaf(p0, va.w, fmaf(p1, vb.w, fmaf(p2, vc.w, fmaf(p3, vd.w, vacc.w))));
        }
        for (; j < cnt; j++) {
            int s = src_s[j];
            float4 ea = *(const float4*)&ea_s[j][lane * 4];
            float4 k4 = *(const float4*)&qkvg[(size_t)s * NPROJ + 1024 + hoff];
            float4 v4 = *(const float4*)&qkvg[(size_t)s * NPROJ + 2048 + hoff];
            float t = qh.x*k4.x + qh.y*k4.y + qh.z*k4.z + qh.w*k4.w;
            t = fmaf(th.x, ea.x, t); t = fmaf(th.y, ea.y, t);
            t = fmaf(th.z, ea.z, t); t = fmaf(th.w, ea.w, t);
            t = warp_sum(t) + s0s;
            float p = expf(t);
            den += p;
            cacc.x = fmaf(p, ea.x, cacc.x); cacc.y = fmaf(p, ea.y, cacc.y);
            cacc.z = fmaf(p, ea.z, cacc.z); cacc.w = fmaf(p, ea.w, cacc.w);
            vacc.x = fmaf(p, v4.x, vacc.x); vacc.y = fmaf(p, v4.y, vacc.y);
            vacc.z = fmaf(p, v4.z, vacc.z); vacc.w = fmaf(p, v4.w, vacc.w);
        }
    }
    bool nonempty = (end > beg);
    float invden = nonempty ? 1.0f / den : 0.0f;
    float4 c4 = {cacc.x*invden, cacc.y*invden, cacc.z*invden, cacc.w*invden};
    *(float4*)&g_cnorm[n * HGC + hoff] = c4;

    __shared__ float sh[8][128];
    float gate = nonempty ? 1.0f : 0.0f;
    __syncthreads();
    sh[h][lane*4+0] = fmaf(vacc.x, invden, be4.x * gate);
    sh[h][lane*4+1] = fmaf(vacc.y, invden, be4.y * gate);
    sh[h][lane*4+2] = fmaf(vacc.z, invden, be4.z * gate);
    sh[h][lane*4+3] = fmaf(vacc.w, invden, be4.w * gate);
    __syncthreads();
    if (tid < 128) {
        int d = tid;
        float sum = 0.0f;
        #pragma unroll
        for (int hh = 0; hh < 8; hh++) sum += sh[hh][d];
        g_vsum[n * DIMC + d] = sum;
    }
}

// ---------------- fused beta gate + combine + LN3 ----------------
__global__ void beta_ln_kernel(const float* __restrict__ wb,
                               const float* __restrict__ g3, const float* __restrict__ b3,
                               const float* __restrict__ qkvg) {
    int n = blockIdx.x, t = threadIdx.x;
    float o = g_aggout[n * DIMC + t] * 0.125f;   // head mean
    float xr = qkvg[(size_t)n * NPROJ + 3072 + t];
    float part = o * (wb[t] + wb[256 + t]) + xr * (wb[128 + t] - wb[256 + t]);
    __shared__ float red[4];
    float s = warp_sum(part);
    if ((t & 31) == 0) red[t >> 5] = s;
    __syncthreads();
    float z = red[0] + red[1] + red[2] + red[3];
    float beta = 1.0f / (1.0f + expf(-z));
    float x2 = g_x1[n * DIMC + t] + beta * xr + (1.0f - beta) * o;
    g_x2[n * DIMC + t] = x2;
    __syncthreads();
    float sm = warp_sum(x2);
    if ((t & 31) == 0) red[t >> 5] = sm;
    __syncthreads();
    float mean = (red[0] + red[1] + red[2] + red[3]) * (1.0f / 128.0f);
    float d = x2 - mean;
    float s2 = warp_sum(d * d);
    __syncthreads();
    if ((t & 31) == 0) red[t >> 5] = s2;
    __syncthreads();
    float var = (red[0] + red[1] + red[2] + red[3]) * (1.0f / 128.0f);
    g_xn3[n * DIMC + t] = d * rsqrtf(var + 1e-5f) * g3[t] + b3[t];
}

// tile configs
#define WG_SMALL(MODE, KF)        wgemm<64,64,2,2,2,2,MODE,false,KF>
#define WG_NARROW(MODE, KF)       wgemm<64,32,2,2,2,1,MODE,false,KF>
#define WG_NARROW_DUAL(MODE, KF)  wgemm<64,32,2,2,2,1,MODE,true,KF>

// ---------------- launch ----------------
extern "C" void kernel_launch(void* const* d_in, const int* in_sizes, int n_in,
                              void* d_out, int out_size) {
    const float* x      = (const float*)d_in[0];
    const int*   ei     = (const int*)d_in[1];
    const float* eattr  = (const float*)d_in[2];
    const float* n1g = (const float*)d_in[3];  const float* n1b = (const float*)d_in[4];
    const float* n2g = (const float*)d_in[5];  const float* n2b = (const float*)d_in[6];
    const float* n3g = (const float*)d_in[7];  const float* n3b = (const float*)d_in[8];
    const float* w_qkv = (const float*)d_in[9];  const float* b_qkv = (const float*)d_in[10];
    const float* w_o   = (const float*)d_in[11]; const float* b_o   = (const float*)d_in[12];
    const float* w_query = (const float*)d_in[13]; const float* b_query = (const float*)d_in[14];
    const float* w_key   = (const float*)d_in[15]; const float* b_key   = (const float*)d_in[16];
    const float* w_value = (const float*)d_in[17]; const float* b_value = (const float*)d_in[18];
    const float* w_edge  = (const float*)d_in[19]; const float* b_edge  = (const float*)d_in[20];
    const float* w_skip  = (const float*)d_in[21]; const float* b_skip  = (const float*)d_in[22];
    const float* w_beta  = (const float*)d_in[23];
    const float* w_f1 = (const float*)d_in[24]; const float* b_f1 = (const float*)d_in[25];
    const float* w_f2 = (const float*)d_in[26]; const float* b_f2 = (const float*)d_in[27];
    const float* w_dyn = (const float*)d_in[28]; const float* b_dyn = (const float*)d_in[29];
    float* out = (float*)d_out;

    float *xn, *qkvb, *attnb, *x1, *xn2, *qkvg, *tb, *packT, *packC, *packW, *packB;
    float *cnorm, *vsum, *aggo, *xn3, *ffnb, *x3, *x2p;
    cudaGetSymbolAddress((void**)&xn,    g_xn);
    cudaGetSymbolAddress((void**)&qkvb,  g_qkv);
    cudaGetSymbolAddress((void**)&attnb, g_attn);
    cudaGetSymbolAddress((void**)&x1,    g_x1);
    cudaGetSymbolAddress((void**)&xn2,   g_xn2);
    cudaGetSymbolAddress((void**)&qkvg,  g_qkvg);
    cudaGetSymbolAddress((void**)&tb,    g_t);
    cudaGetSymbolAddress((void**)&packT, g_packT);
    cudaGetSymbolAddress((void**)&packC, g_packC);
    cudaGetSymbolAddress((void**)&packW, g_packW);
    cudaGetSymbolAddress((void**)&packB, g_packB);
    cudaGetSymbolAddress((void**)&cnorm, g_cnorm);
    cudaGetSymbolAddress((void**)&vsum,  g_vsum);
    cudaGetSymbolAddress((void**)&aggo,  g_aggout);
    cudaGetSymbolAddress((void**)&xn3,   g_xn3);
    cudaGetSymbolAddress((void**)&ffnb,  g_ffn);
    cudaGetSymbolAddress((void**)&x3,    g_x3);
    cudaGetSymbolAddress((void**)&x2p,   g_x2);
    float* qg = qkvg;   // stride NPROJ; kg/vg/xr at +1024/+2048/+3072

    // weight packing + deg zeroing
    packT_kernel<<<dim3(4, 4, 8), dim3(32, 8)>>>(w_edge);
    packw_kernel<<<512, 256>>>(w_query, w_key, w_value, w_skip,
                               b_query, b_key, b_value, b_skip, w_edge);

    // 1. LN1
    ln_kernel<<<NN, 128>>>(x, n1g, n1b, xn);
    // 2. QKV projection (4096 x 384, K=128) — 768 blocks
    WG_NARROW(0, 128)<<<dim3(12, 64, 1), 128>>>(xn, w_qkv, b_qkv, qkvb, 128, 128, 384, 384,
                                                0, 0, 0, 0, nullptr, nullptr, nullptr);
    // 3. dense MHA (TF32 wmma flash-style)
    attn_wmma_kernel<<<dim3(NN/128, HEADSC), 256>>>(qkvb, attnb);
    // 4. out proj + residual (4096x128, K=128)
    WG_NARROW(2, 128)<<<dim3(4, 64, 1), 128>>>(attnb, w_o, b_o, x1, 128, 128, 128, 128,
                                               0, 0, 0, 0, x, nullptr, nullptr);
    // 5. LN2
    ln_kernel<<<NN, 128>>>(x1, n2g, n2b, xn2);
    // 6. merged projections q|k|v|skip (4096 x 3200, K=128) — 3200 blocks
    WG_SMALL(0, 128)<<<dim3(NPROJ/64, 64, 1), 128>>>(xn2, packW, packB, qkvg,
                                                     128, 128, NPROJ, NPROJ,
                                                     0, 0, 0, 0, nullptr, nullptr, nullptr);
    // 7. batched t-GEMM (8x [4096x128, K=128], direct store)
    WG_NARROW(5, 128)<<<dim3(4, 64, 8), 128>>>(qg, packT, nullptr, tb, 128, NPROJ, 128, HGC,
                                               128, 128*128, 128, 0, nullptr, nullptr, nullptr);
    // 8. CSR by dst
    hist_kernel<<<256, 256>>>(ei);
    scan_kernel<<<1, 1024>>>();
    scatter_kernel<<<256, 256>>>(ei);
    // 9. eg-free segment-softmax aggregation
    graph_agg3_kernel<<<NN, 256>>>(ei, eattr, b_edge, qkvg);
    // 10. c-GEMM: aggout = cnorm @ packC + vsum  (4096x128, K=1024)
    WG_NARROW(4, 0)<<<dim3(4, 64, 1), 128>>>(cnorm, packC, nullptr, aggo, HGC, HGC, 128, 128,
                                             0, 0, 0, 0, vsum, nullptr, nullptr);
    // 11. fused beta gate + combine + LN3
    beta_ln_kernel<<<NN, 128>>>(w_beta, n3g, n3b, qkvg);
    // 12. FFN up + GELU (4096x2048, K=128) — 2048 blocks
    WG_SMALL(1, 128)<<<dim3(32, 64, 1), 128>>>(xn3, w_f1, b_f1, ffnb, 128, 128, FFNC, FFNC,
                                               0, 0, 0, 0, nullptr, nullptr, nullptr);
    // 13. FFN down + residual (4096x128, K=2048)
    WG_NARROW(2, 0)<<<dim3(4, 64, 1), 128>>>(ffnb, w_f2, b_f2, x3, FFNC, FFNC, 128, 128,
                                             0, 0, 0, 0, x2p, nullptr, nullptr);
    // 14. dyn gate (4096x128, K=256, dual-A = [x3 | x])
    WG_NARROW_DUAL(3, 256)<<<dim3(4, 64, 1), 128>>>(x3, w_dyn, b_dyn, out, 256, 128, 128, 128,
                                                    0, 0, 0, 0, x3, x, x);
}

// round 12
// speedup vs baseline: 1.0231x; 1.0231x over previous
#include <cuda_runtime.h>
#include <mma.h>
#include <math.h>

using namespace nvcuda;

#define NN   4096
#define DIMC 128
#define HEADSC 8
#define HGC  1024      // HEADS * GC
#define EC   65536
#define FFNC 2048
#define NPROJ 3200     // 3*1024 + 128 (q|k|v|skip)

// ---------------- scratch (device globals; no allocation allowed) ----------------
__device__ float g_xn[NN*DIMC];
__device__ float g_qkv[NN*3*DIMC];
__device__ float g_attn[NN*DIMC];
__device__ float g_x1[NN*DIMC];
__device__ float g_xn2[NN*DIMC];
__device__ float g_qkvg[(size_t)NN*NPROJ];   // per row: qg|kg|vg|xr
__device__ float g_t[NN*HGC];                // per-head W_h @ qg
__device__ float g_packT[HEADSC*128*128];
__device__ float g_packC[HEADSC*128*128];
__device__ float g_packW[DIMC*NPROJ];        // [wq|wk|wv|wskip] col-concat
__device__ float g_packB[NPROJ];
__device__ float g_cnorm[NN*HGC];
__device__ float g_vsum[NN*DIMC];
__device__ int   g_deg[NN];
__device__ int   g_off[NN+1];
__device__ int   g_cur[NN];
__device__ int   g_eid[EC];
__device__ float g_aggout[NN*DIMC];
__device__ float g_x2[NN*DIMC];
__device__ float g_xn3[NN*DIMC];
__device__ float g_ffn[NN*FFNC];
__device__ float g_x3[NN*DIMC];

// ---------------- helpers ----------------
__device__ __forceinline__ float warp_sum(float v) {
    #pragma unroll
    for (int o = 16; o > 0; o >>= 1) v += __shfl_xor_sync(0xffffffffu, v, o);
    return v;
}

__device__ __forceinline__ void warp_sum4(float& a, float& b, float& c, float& d) {
    #pragma unroll
    for (int o = 16; o > 0; o >>= 1) {
        a += __shfl_xor_sync(0xffffffffu, a, o);
        b += __shfl_xor_sync(0xffffffffu, b, o);
        c += __shfl_xor_sync(0xffffffffu, c, o);
        d += __shfl_xor_sync(0xffffffffu, d, o);
    }
}

// MODE: 0 = +bias, 1 = +bias->GELU, 2 = +bias+aux1, 3 = +bias->sigmoid gate(a1,a2),
//       4 = +aux1 (no bias), 5 = raw store (no bias, no aux)
template<int MODE>
__device__ __forceinline__ float epilogue(float acc, float bias, float a1, float a2) {
    float v = (MODE == 4 || MODE == 5) ? acc : (acc + bias);
    if (MODE == 1) {
        v = 0.5f * v * (1.0f + erff(v * 0.7071067811865476f));
    } else if (MODE == 2 || MODE == 4) {
        v = v + a1;
    } else if (MODE == 3) {
        float s = 1.0f / (1.0f + expf(-v));
        v = a1 * s + a2 * (1.0f - s);
    }
    return v;
}

// ---------------- TF32 tensor-core GEMM via wmma (m16n16k8) ----------------
template<int BM, int BN, int WARPS_M, int WARPS_N, int WM, int WN, int MODE, bool DUALA, int KFIX>
__global__ void __launch_bounds__(WARPS_M*WARPS_N*32)
wgemm(const float* __restrict__ A, const float* __restrict__ B,
      const float* __restrict__ bias, float* __restrict__ C,
      int K, int lda, int ldb, int ldc,
      long sA, long sB, long sC, long sBias,
      const float* __restrict__ aux1, const float* __restrict__ aux2,
      const float* __restrict__ A2) {
    constexpr int NT  = WARPS_M * WARPS_N * 32;
    constexpr int SAS = 36;
    constexpr int SBS = BN + 4;
    constexpr int AI  = (BM * 8) / NT;
    constexpr int BI  = (BN * 8) / NT;
    constexpr int WORDS = BM * SAS + 32 * SBS;
    constexpr int STAGES = (WORDS * 8 <= 48 * 1024) ? 2 : 1;
    __shared__ float As[STAGES][BM * SAS];
    __shared__ float Bs[STAGES][32 * SBS];
    const int tid  = threadIdx.x;
    const int wid  = tid >> 5;
    const int lane = tid & 31;
    const int bm = blockIdx.y * BM;
    const int bn = blockIdx.x * BN;
    A += (size_t)blockIdx.z * sA;
    B += (size_t)blockIdx.z * sB;
    C += (size_t)blockIdx.z * sC;
    if (MODE != 4 && MODE != 5) bias += (size_t)blockIdx.z * sBias;
    const int warp_m = (wid / WARPS_N) * (WM * 16);
    const int warp_n = (wid % WARPS_N) * (WN * 16);
    const int KK = KFIX ? KFIX : K;

    wmma::fragment<wmma::accumulator, 16, 16, 8, float> cf[WM][WN];
    #pragma unroll
    for (int i = 0; i < WM; i++)
        #pragma unroll
        for (int j = 0; j < WN; j++) wmma::fill_fragment(cf[i][j], 0.0f);

    float4 av[AI], bv[BI];
    auto load_tiles = [&](int k0) {
        #pragma unroll
        for (int i = 0; i < AI; i++) {
            int idx = tid + i * NT;
            int kk = k0 + (idx & 7) * 4;
            const float* src;
            if (DUALA && kk >= 128) src = &A2[(size_t)(bm + (idx >> 3)) * 128 + (kk - 128)];
            else                    src = &A[(size_t)(bm + (idx >> 3)) * lda + kk];
            av[i] = *(const float4*)src;
        }
        #pragma unroll
        for (int i = 0; i < BI; i++) {
            int idx = tid + i * NT;
            bv[i] = *(const float4*)&B[(size_t)(k0 + idx / (BN / 4)) * ldb + bn + (idx % (BN / 4)) * 4];
        }
    };
    auto store_smem = [&](int st) {
        #pragma unroll
        for (int i = 0; i < AI; i++) {
            int idx = tid + i * NT;
            *(float4*)&As[st][(idx >> 3) * SAS + (idx & 7) * 4] = av[i];
        }
        #pragma unroll
        for (int i = 0; i < BI; i++) {
            int idx = tid + i * NT;
            *(float4*)&Bs[st][(idx / (BN / 4)) * SBS + (idx % (BN / 4)) * 4] = bv[i];
        }
    };

    int cur = 0;
    load_tiles(0);
    store_smem(0);
    __syncthreads();
    for (int k0 = 0; k0 < KK; k0 += 32) {
        bool more = (k0 + 32 < KK);
        if (more) load_tiles(k0 + 32);
        #pragma unroll
        for (int kk = 0; kk < 4; kk++) {
            wmma::fragment<wmma::matrix_a, 16, 16, 8, wmma::precision::tf32, wmma::row_major> af[WM];
            wmma::fragment<wmma::matrix_b, 16, 16, 8, wmma::precision::tf32, wmma::row_major> bf[WN];
            #pragma unroll
            for (int i = 0; i < WM; i++)
                wmma::load_matrix_sync(af[i], &As[cur][(warp_m + i * 16) * SAS + kk * 8], SAS);
            #pragma unroll
            for (int j = 0; j < WN; j++)
                wmma::load_matrix_sync(bf[j], &Bs[cur][kk * 8 * SBS + warp_n + j * 16], SBS);
            #pragma unroll
            for (int i = 0; i < WM; i++)
                #pragma unroll
                for (int j = 0; j < WN; j++)
                    wmma::mma_sync(cf[i][j], af[i], bf[j], cf[i][j]);
        }
        if (more) {
            if (STAGES == 2) {
                store_smem(1 - cur);
                __syncthreads();
                cur ^= 1;
            } else {
                __syncthreads();
                store_smem(0);
                __syncthreads();
            }
        }
    }

    if (MODE == 5) {   // direct gmem store
        #pragma unroll
        for (int i = 0; i < WM; i++)
            #pragma unroll
            for (int j = 0; j < WN; j++) {
                int row0 = bm + warp_m + i * 16;
                int col0 = bn + warp_n + j * 16;
                wmma::store_matrix_sync(&C[(size_t)row0 * ldc + col0], cf[i][j], ldc,
                                        wmma::mem_row_major);
            }
        return;
    }

    __syncthreads();
    float* scratch = &As[0][wid * 256];
    #pragma unroll
    for (int i = 0; i < WM; i++) {
        #pragma unroll
        for (int j = 0; j < WN; j++) {
            wmma::store_matrix_sync(scratch, cf[i][j], 16, wmma::mem_row_major);
            __syncwarp();
            int row0 = bm + warp_m + i * 16;
            int col0 = bn + warp_n + j * 16;
            #pragma unroll
            for (int e = 0; e < 8; e++) {
                int idx = lane + e * 32;
                int r = row0 + (idx >> 4);
                int c = col0 + (idx & 15);
                float acc = scratch[idx];
                float bvv = (MODE == 4) ? 0.0f : bias[c];
                size_t o = (size_t)r * ldc + c;
                float u = 0.f, w = 0.f;
                if (MODE == 2 || MODE == 3 || MODE == 4) u = aux1[o];
                if (MODE == 3) w = aux2[o];
                C[o] = epilogue<MODE>(acc, bvv, u, w);
            }
            __syncwarp();
        }
    }
}

// ---------------- LayerNorm ----------------
__global__ void ln_kernel(const float* __restrict__ x, const float* __restrict__ g,
                          const float* __restrict__ b, float* __restrict__ out) {
    int row = blockIdx.x, t = threadIdx.x;
    float v = x[row * DIMC + t];
    __shared__ float red[4];
    float s = warp_sum(v);
    if ((t & 31) == 0) red[t >> 5] = s;
    __syncthreads();
    float mean = (red[0] + red[1] + red[2] + red[3]) * (1.0f / 128.0f);
    float d = v - mean;
    float s2 = warp_sum(d * d);
    __syncthreads();
    if ((t & 31) == 0) red[t >> 5] = s2;
    __syncthreads();
    float var = (red[0] + red[1] + red[2] + red[3]) * (1.0f / 128.0f);
    out[row * DIMC + t] = d * rsqrtf(var + 1e-5f) * g[t] + b[t];
}

// ---------------- dense MHA via TF32 wmma (flash-style, no-max softmax) ----------------
#define ABK 64
#define APS 68
__global__ void __launch_bounds__(256)
attn_wmma_kernel(const float* __restrict__ qkv, float* __restrict__ attn) {
    __shared__ float Ks[ABK * 16];
    __shared__ float Vs[ABK * 16];
    __shared__ float Ps[8 * 16 * APS];
    __shared__ float dens[128];
    const int tid  = threadIdx.x;
    const int wid  = tid >> 5;
    const int lane = tid & 31;
    const int h  = blockIdx.y;
    const int q0 = blockIdx.x * 128;
    float* Pw = &Ps[wid * 16 * APS];

    #pragma unroll
    for (int i = 0; i < 2; i++) {
        int idx = tid + i * 256;
        int r = idx >> 2, d4 = (idx & 3) * 4;
        float4 q4 = *(const float4*)&qkv[(size_t)(q0 + r) * 384 + h * 16 + d4];
        Ps[r * 16 + d4 + 0] = q4.x * 0.25f;
        Ps[r * 16 + d4 + 1] = q4.y * 0.25f;
        Ps[r * 16 + d4 + 2] = q4.z * 0.25f;
        Ps[r * 16 + d4 + 3] = q4.w * 0.25f;
    }
    __syncthreads();
    wmma::fragment<wmma::matrix_a, 16, 16, 8, wmma::precision::tf32, wmma::row_major> af[2];
    #pragma unroll
    for (int k0 = 0; k0 < 2; k0++)
        wmma::load_matrix_sync(af[k0], &Ps[(wid * 16) * 16 + k0 * 8], 16);
    __syncthreads();

    wmma::fragment<wmma::accumulator, 16, 16, 8, float> oacc, dacc;
    wmma::fill_fragment(oacc, 0.0f);
    wmma::fill_fragment(dacc, 0.0f);
    wmma::fragment<wmma::matrix_b, 16, 16, 8, wmma::precision::tf32, wmma::row_major> bones;
    wmma::fill_fragment(bones, 1.0f);

    const int key = tid >> 2, d4 = (tid & 3) * 4;
    float4 k4 = *(const float4*)&qkv[(size_t)key * 384 + 128 + h * 16 + d4];
    float4 v4 = *(const float4*)&qkv[(size_t)key * 384 + 256 + h * 16 + d4];

    for (int kt = 0; kt < NN; kt += ABK) {
        __syncthreads();
        *(float4*)&Ks[key * 16 + d4] = k4;
        *(float4*)&Vs[key * 16 + d4] = v4;
        __syncthreads();
        if (kt + ABK < NN) {
            const float* kp = &qkv[(size_t)(kt + ABK + key) * 384 + 128 + h * 16 + d4];
            k4 = *(const float4*)kp;
            v4 = *(const float4*)(kp + 128);
        }

        wmma::fragment<wmma::accumulator, 16, 16, 8, float> sacc[4];
        #pragma unroll
        for (int nt = 0; nt < 4; nt++) wmma::fill_fragment(sacc[nt], 0.0f);
        #pragma unroll
        for (int k0 = 0; k0 < 2; k0++) {
            #pragma unroll
            for (int nt = 0; nt < 4; nt++) {
                wmma::fragment<wmma::matrix_b, 16, 16, 8, wmma::precision::tf32, wmma::col_major> bf;
                wmma::load_matrix_sync(bf, &Ks[(nt * 16) * 16 + k0 * 8], 16);
                wmma::mma_sync(sacc[nt], af[k0], bf, sacc[nt]);
            }
        }
        // exp on the idle MUFU pipe (more accurate than poly, frees FMA pipe)
        #pragma unroll
        for (int nt = 0; nt < 4; nt++) {
            #pragma unroll
            for (int t = 0; t < sacc[nt].num_elements; t++)
                sacc[nt].x[t] = __expf(sacc[nt].x[t]);
            wmma::store_matrix_sync(&Pw[nt * 16], sacc[nt], APS, wmma::mem_row_major);
        }
        __syncwarp();
        #pragma unroll
        for (int k0 = 0; k0 < 8; k0++) {
            wmma::fragment<wmma::matrix_a, 16, 16, 8, wmma::precision::tf32, wmma::row_major> pa;
            wmma::fragment<wmma::matrix_b, 16, 16, 8, wmma::precision::tf32, wmma::row_major> vb;
            wmma::load_matrix_sync(pa, &Pw[k0 * 8], APS);
            wmma::load_matrix_sync(vb, &Vs[(k0 * 8) * 16], 16);
            wmma::mma_sync(oacc, pa, vb, oacc);
            wmma::mma_sync(dacc, pa, bones, dacc);
        }
        __syncwarp();
    }

    wmma::store_matrix_sync(Pw, dacc, APS, wmma::mem_row_major);
    __syncwarp();
    if (lane < 16) dens[wid * 16 + lane] = Pw[lane * APS];
    __syncwarp();
    wmma::store_matrix_sync(Pw, oacc, APS, wmma::mem_row_major);
    __syncwarp();
    #pragma unroll
    for (int e = 0; e < 8; e++) {
        int idx = lane + e * 32;
        int r = idx >> 4, c = idx & 15;
        float v = Pw[r * APS + c] / dens[wid * 16 + r];
        attn[(size_t)(q0 + wid * 16 + r) * DIMC + h * 16 + c] = v;
    }
}

// ---------------- packT via tiled transpose ----------------
__global__ void packT_kernel(const float* __restrict__ w_edge) {
    __shared__ float tile[32][33];
    int h  = blockIdx.z;
    int k0 = blockIdx.x * 32;
    int j0 = blockIdx.y * 32;
    int tx = threadIdx.x, ty0 = threadIdx.y;
    #pragma unroll
    for (int i = 0; i < 4; i++) {
        int j = j0 + ty0 + i * 8;
        tile[ty0 + i * 8][tx] = w_edge[(size_t)j * HGC + h * 128 + k0 + tx];
    }
    __syncthreads();
    #pragma unroll
    for (int i = 0; i < 4; i++) {
        int k = k0 + ty0 + i * 8;
        g_packT[h * 16384 + k * 128 + j0 + tx] = tile[tx][ty0 + i * 8];
    }
}

// ---------------- pack [wq|wk|wv|wskip] + biases + packC; zero g_deg ----------------
__global__ void packw_kernel(const float* __restrict__ wq, const float* __restrict__ wk,
                             const float* __restrict__ wv, const float* __restrict__ wsk,
                             const float* __restrict__ bq, const float* __restrict__ bk,
                             const float* __restrict__ bv, const float* __restrict__ bsk,
                             const float* __restrict__ w_edge) {
    for (int idx = blockIdx.x * blockDim.x + threadIdx.x; idx < DIMC * NPROJ;
         idx += gridDim.x * blockDim.x) {
        int k = idx / NPROJ, j = idx % NPROJ;
        float v;
        if (j < 1024)      v = wq[k * 1024 + j];
        else if (j < 2048) v = wk[k * 1024 + j - 1024];
        else if (j < 3072) v = wv[k * 1024 + j - 2048];
        else               v = wsk[k * 128 + j - 3072];
        g_packW[idx] = v;
        if (idx < HEADSC * 128 * 128) {
            int jj = idx & 127;
            int kk = (idx >> 7) & 127;
            int hh = idx >> 14;
            g_packC[idx] = w_edge[(size_t)kk * HGC + hh * 128 + jj];
        }
        if (idx < NPROJ) {
            float bvv;
            if (idx < 1024)      bvv = bq[idx];
            else if (idx < 2048) bvv = bk[idx - 1024];
            else if (idx < 3072) bvv = bv[idx - 2048];
            else                 bvv = bsk[idx - 3072];
            g_packB[idx] = bvv;
        }
        if (idx < NN) g_deg[idx] = 0;
    }
}

// ---------------- CSR build ----------------
__global__ void hist_kernel(const int* __restrict__ ei) {
    const int* dst = ei + EC;
    for (int e = blockIdx.x * blockDim.x + threadIdx.x; e < EC; e += gridDim.x * blockDim.x)
        atomicAdd(&g_deg[dst[e]], 1);
}
__global__ void scan_kernel() {   // warp-scan; also initializes g_cur
    int t = threadIdx.x;
    int lane = t & 31, w = t >> 5;
    int base = t * 4;
    int d0 = g_deg[base], d1 = g_deg[base+1], d2 = g_deg[base+2], d3 = g_deg[base+3];
    int tot = d0 + d1 + d2 + d3;
    int v = tot;
    #pragma unroll
    for (int o = 1; o < 32; o <<= 1) {
        int u = __shfl_up_sync(0xffffffffu, v, o);
        if (lane >= o) v += u;
    }
    __shared__ int wsum[32];
    if (lane == 31) wsum[w] = v;
    __syncthreads();
    if (t < 32) {
        int wv = wsum[t];
        #pragma unroll
        for (int o = 1; o < 32; o <<= 1) {
            int u = __shfl_up_sync(0xffffffffu, wv, o);
            if (t >= o) wv += u;
        }
        wsum[t] = wv;
    }
    __syncthreads();
    int incl = v + (w ? wsum[w - 1] : 0);
    int run = incl - tot;
    g_off[base] = run;   g_cur[base] = run;     run += d0;
    g_off[base+1] = run; g_cur[base+1] = run;   run += d1;
    g_off[base+2] = run; g_cur[base+2] = run;   run += d2;
    g_off[base+3] = run; g_cur[base+3] = run;   run += d3;
    if (t == 1023) g_off[NN] = incl;
}
__global__ void scatter_kernel(const int* __restrict__ ei) {
    const int* dst = ei + EC;
    for (int e = blockIdx.x * blockDim.x + threadIdx.x; e < EC; e += gridDim.x * blockDim.x) {
        int p = atomicAdd(&g_cur[dst[e]], 1);
        g_eid[p] = e;
    }
}

// ---------------- graph aggregation: smem edge staging + inline s0 ----------------
__global__ void graph_agg3_kernel(const int* __restrict__ ei,
                                  const float* __restrict__ edge_attr,
                                  const float* __restrict__ b_edge,
                                  const float* __restrict__ qkvg) {
    int n = blockIdx.x;
    int tid = threadIdx.x;
    int h = tid >> 5;
    int lane = tid & 31;
    const int* src = ei;
    const float invsq = 0.08838834764831845f;  // 1/sqrt(128)
    const int hoff = h * 128 + lane * 4;
    float4 qh = *(const float4*)&qkvg[(size_t)n * NPROJ + hoff];
    qh.x *= invsq; qh.y *= invsq; qh.z *= invsq; qh.w *= invsq;
    float4 th = *(const float4*)&g_t[n * HGC + hoff];
    th.x *= invsq; th.y *= invsq; th.z *= invsq; th.w *= invsq;
    float4 be4 = *(const float4*)&b_edge[hoff];
    float s0s = warp_sum(qh.x*be4.x + qh.y*be4.y + qh.z*be4.z + qh.w*be4.w);

    __shared__ float ea_s[8][132];
    __shared__ int src_s[8];
    float4 cacc = {0.f, 0.f, 0.f, 0.f};
    float4 vacc = {0.f, 0.f, 0.f, 0.f};
    float den = 0.0f;
    int beg = g_off[n], end = g_off[n + 1];

    for (int i0 = beg; i0 < end; i0 += 8) {
        int cnt = min(8, end - i0);
        __syncthreads();
        if (h < cnt) {
            int e = g_eid[i0 + h];
            if (lane == 0) src_s[h] = src[e];
            *(float4*)&ea_s[h][lane * 4] = *(const float4*)&edge_attr[(size_t)e * DIMC + lane * 4];
        }
        __syncthreads();
        int j = 0;
        for (; j + 3 < cnt; j += 4) {
            int sa = src_s[j], sb = src_s[j+1], sc = src_s[j+2], sd = src_s[j+3];
            float4 ea0 = *(const float4*)&ea_s[j  ][lane * 4];
            float4 ea1 = *(const float4*)&ea_s[j+1][lane * 4];
            float4 ea2 = *(const float4*)&ea_s[j+2][lane * 4];
            float4 ea3 = *(const float4*)&ea_s[j+3][lane * 4];
            float4 ka = *(const float4*)&qkvg[(size_t)sa * NPROJ + 1024 + hoff];
            float4 kb = *(const float4*)&qkvg[(size_t)sb * NPROJ + 1024 + hoff];
            float4 kc = *(const float4*)&qkvg[(size_t)sc * NPROJ + 1024 + hoff];
            float4 kd = *(const float4*)&qkvg[(size_t)sd * NPROJ + 1024 + hoff];
            float4 va = *(const float4*)&qkvg[(size_t)sa * NPROJ + 2048 + hoff];
            float4 vb = *(const float4*)&qkvg[(size_t)sb * NPROJ + 2048 + hoff];
            float4 vc = *(const float4*)&qkvg[(size_t)sc * NPROJ + 2048 + hoff];
            float4 vd = *(const float4*)&qkvg[(size_t)sd * NPROJ + 2048 + hoff];
            float t0 = qh.x*ka.x + qh.y*ka.y + qh.z*ka.z + qh.w*ka.w;
            t0 = fmaf(th.x, ea0.x, t0); t0 = fmaf(th.y, ea0.y, t0);
            t0 = fmaf(th.z, ea0.z, t0); t0 = fmaf(th.w, ea0.w, t0);
            float t1 = qh.x*kb.x + qh.y*kb.y + qh.z*kb.z + qh.w*kb.w;
            t1 = fmaf(th.x, ea1.x, t1); t1 = fmaf(th.y, ea1.y, t1);
            t1 = fmaf(th.z, ea1.z, t1); t1 = fmaf(th.w, ea1.w, t1);
            float t2 = qh.x*kc.x + qh.y*kc.y + qh.z*kc.z + qh.w*kc.w;
            t2 = fmaf(th.x, ea2.x, t2); t2 = fmaf(th.y, ea2.y, t2);
            t2 = fmaf(th.z, ea2.z, t2); t2 = fmaf(th.w, ea2.w, t2);
            float t3 = qh.x*kd.x + qh.y*kd.y + qh.z*kd.z + qh.w*kd.w;
            t3 = fmaf(th.x, ea3.x, t3); t3 = fmaf(th.y, ea3.y, t3);
            t3 = fmaf(th.z, ea3.z, t3); t3 = fmaf(th.w, ea3.w, t3);
            warp_sum4(t0, t1, t2, t3);
            float p0 = expf(t0 + s0s), p1 = expf(t1 + s0s);
            float p2 = expf(t2 + s0s), p3 = expf(t3 + s0s);
            den += (p0 + p1) + (p2 + p3);
            cacc.x = fmaf(p0, ea0.x, fmaf(p1, ea1.x, fmaf(p2, ea2.x, fmaf(p3, ea3.x, cacc.x))));
            cacc.y = fmaf(p0, ea0.y, fmaf(p1, ea1.y, fmaf(p2, ea2.y, fmaf(p3, ea3.y, cacc.y))));
            cacc.z = fmaf(p0, ea0.z, fmaf(p1, ea1.z, fmaf(p2, ea2.z, fmaf(p3, ea3.z, cacc.z))));
            cacc.w = fmaf(p0, ea0.w, fmaf(p1, ea1.w, fmaf(p2, ea2.w, fmaf(p3, ea3.w, cacc.w))));
            vacc.x = fmaf(p0, va.x, fmaf(p1, vb.x, fmaf(p2, vc.x, fmaf(p3, vd.x, vacc.x))));
            vacc.y = fmaf(p0, va.y, fmaf(p1, vb.y, fmaf(p2, vc.y, fmaf(p3, vd.y, vacc.y))));
            vacc.z = fmaf(p0, va.z, fmaf(p1, vb.z, fmaf(p2, vc.z, fmaf(p3, vd.z, vacc.z))));
            vacc.w = fmaf(p0, va.w, fmaf(p1, vb.w, fmaf(p2, vc.w, fmaf(p3, vd.w, vacc.w))));
        }
        for (; j < cnt; j++) {
            int s = src_s[j];
            float4 ea = *(const float4*)&ea_s[j][lane * 4];
            float4 k4 = *(const float4*)&qkvg[(size_t)s * NPROJ + 1024 + hoff];
            float4 v4 = *(const float4*)&qkvg[(size_t)s * NPROJ + 2048 + hoff];
            float t = qh.x*k4.x + qh.y*k4.y + qh.z*k4.z + qh.w*k4.w;
            t = fmaf(th.x, ea.x, t); t = fmaf(th.y, ea.y, t);
            t = fmaf(th.z, ea.z, t); t = fmaf(th.w, ea.w, t);
            t = warp_sum(t) + s0s;
            float p = expf(t);
            den += p;
            cacc.x = fmaf(p, ea.x, cacc.x); cacc.y = fmaf(p, ea.y, cacc.y);
            cacc.z = fmaf(p, ea.z, cacc.z); cacc.w = fmaf(p, ea.w, cacc.w);
            vacc.x = fmaf(p, v4.x, vacc.x); vacc.y = fmaf(p, v4.y, vacc.y);
            vacc.z = fmaf(p, v4.z, vacc.z); vacc.w = fmaf(p, v4.w, vacc.w);
        }
    }
    bool nonempty = (end > beg);
    float invden = nonempty ? 1.0f / den : 0.0f;
    float4 c4 = {cacc.x*invden, cacc.y*invden, cacc.z*invden, cacc.w*invden};
    *(float4*)&g_cnorm[n * HGC + hoff] = c4;

    __shared__ float sh[8][128];
    float gate = nonempty ? 1.0f : 0.0f;
    __syncthreads();
    sh[h][lane*4+0] = fmaf(vacc.x, invden, be4.x * gate);
    sh[h][lane*4+1] = fmaf(vacc.y, invden, be4.y * gate);
    sh[h][lane*4+2] = fmaf(vacc.z, invden, be4.z * gate);
    sh[h][lane*4+3] = fmaf(vacc.w, invden, be4.w * gate);
    __syncthreads();
    if (tid < 128) {
        int d = tid;
        float sum = 0.0f;
        #pragma unroll
        for (int hh = 0; hh < 8; hh++) sum += sh[hh][d];
        g_vsum[n * DIMC + d] = sum;
    }
}

// ---------------- fused beta gate + combine + LN3 ----------------
__global__ void beta_ln_kernel(const float* __restrict__ wb,
                               const float* __restrict__ g3, const float* __restrict__ b3,
                               const float* __restrict__ qkvg) {
    int n = blockIdx.x, t = threadIdx.x;
    float o = g_aggout[n * DIMC + t] * 0.125f;
    float xr = qkvg[(size_t)n * NPROJ + 3072 + t];
    float part = o * (wb[t] + wb[256 + t]) + xr * (wb[128 + t] - wb[256 + t]);
    __shared__ float red[4];
    float s = warp_sum(part);
    if ((t & 31) == 0) red[t >> 5] = s;
    __syncthreads();
    float z = red[0] + red[1] + red[2] + red[3];
    float beta = 1.0f / (1.0f + expf(-z));
    float x2 = g_x1[n * DIMC + t] + beta * xr + (1.0f - beta) * o;
    g_x2[n * DIMC + t] = x2;
    __syncthreads();
    float sm = warp_sum(x2);
    if ((t & 31) == 0) red[t >> 5] = sm;
    __syncthreads();
    float mean = (red[0] + red[1] + red[2] + red[3]) * (1.0f / 128.0f);
    float d = x2 - mean;
    float s2 = warp_sum(d * d);
    __syncthreads();
    if ((t & 31) == 0) red[t >> 5] = s2;
    __syncthreads();
    float var = (red[0] + red[1] + red[2] + red[3]) * (1.0f / 128.0f);
    g_xn3[n * DIMC + t] = d * rsqrtf(var + 1e-5f) * g3[t] + b3[t];
}

// tile configs
#define WG_SMALL(MODE, KF)        wgemm<64,64,2,2,2,2,MODE,false,KF>
#define WG_NARROW(MODE, KF)       wgemm<64,32,2,2,2,1,MODE,false,KF>
#define WG_NARROW_DUAL(MODE, KF)  wgemm<64,32,2,2,2,1,MODE,true,KF>

// ---------------- launch ----------------
extern "C" void kernel_launch(void* const* d_in, const int* in_sizes, int n_in,
                              void* d_out, int out_size) {
    const float* x      = (const float*)d_in[0];
    const int*   ei     = (const int*)d_in[1];
    const float* eattr  = (const float*)d_in[2];
    const float* n1g = (const float*)d_in[3];  const float* n1b = (const float*)d_in[4];
    const float* n2g = (const float*)d_in[5];  const float* n2b = (const float*)d_in[6];
    const float* n3g = (const float*)d_in[7];  const float* n3b = (const float*)d_in[8];
    const float* w_qkv = (const float*)d_in[9];  const float* b_qkv = (const float*)d_in[10];
    const float* w_o   = (const float*)d_in[11]; const float* b_o   = (const float*)d_in[12];
    const float* w_query = (const float*)d_in[13]; const float* b_query = (const float*)d_in[14];
    const float* w_key   = (const float*)d_in[15]; const float* b_key   = (const float*)d_in[16];
    const float* w_value = (const float*)d_in[17]; const float* b_value = (const float*)d_in[18];
    const float* w_edge  = (const float*)d_in[19]; const float* b_edge  = (const float*)d_in[20];
    const float* w_skip  = (const float*)d_in[21]; const float* b_skip  = (const float*)d_in[22];
    const float* w_beta  = (const float*)d_in[23];
    const float* w_f1 = (const float*)d_in[24]; const float* b_f1 = (const float*)d_in[25];
    const float* w_f2 = (const float*)d_in[26]; const float* b_f2 = (const float*)d_in[27];
    const float* w_dyn = (const float*)d_in[28]; const float* b_dyn = (const float*)d_in[29];
    float* out = (float*)d_out;

    float *xn, *qkvb, *attnb, *x1, *xn2, *qkvg, *tb, *packT, *packC, *packW, *packB;
    float *cnorm, *vsum, *aggo, *xn3, *ffnb, *x3, *x2p;
    cudaGetSymbolAddress((void**)&xn,    g_xn);
    cudaGetSymbolAddress((void**)&qkvb,  g_qkv);
    cudaGetSymbolAddress((void**)&attnb, g_attn);
    cudaGetSymbolAddress((void**)&x1,    g_x1);
    cudaGetSymbolAddress((void**)&xn2,   g_xn2);
    cudaGetSymbolAddress((void**)&qkvg,  g_qkvg);
    cudaGetSymbolAddress((void**)&tb,    g_t);
    cudaGetSymbolAddress((void**)&packT, g_packT);
    cudaGetSymbolAddress((void**)&packC, g_packC);
    cudaGetSymbolAddress((void**)&packW, g_packW);
    cudaGetSymbolAddress((void**)&packB, g_packB);
    cudaGetSymbolAddress((void**)&cnorm, g_cnorm);
    cudaGetSymbolAddress((void**)&vsum,  g_vsum);
    cudaGetSymbolAddress((void**)&aggo,  g_aggout);
    cudaGetSymbolAddress((void**)&xn3,   g_xn3);
    cudaGetSymbolAddress((void**)&ffnb,  g_ffn);
    cudaGetSymbolAddress((void**)&x3,    g_x3);
    cudaGetSymbolAddress((void**)&x2p,   g_x2);
    float* qg = qkvg;

    // side stream for weight packing + CSR build (independent of x until merged proj)
    static cudaStream_t s2 = nullptr;
    static cudaEvent_t evF = nullptr, evJ = nullptr;
    if (!s2) {
        cudaStreamCreateWithFlags(&s2, cudaStreamNonBlocking);
        cudaEventCreateWithFlags(&evF, cudaEventDisableTiming);
        cudaEventCreateWithFlags(&evJ, cudaEventDisableTiming);
    }
    cudaEventRecord(evF, 0);
    cudaStreamWaitEvent(s2, evF, 0);

    // ---- stream s2: packT, packw(+deg zero), hist, scan, scatter ----
    packT_kernel<<<dim3(4, 4, 8), dim3(32, 8), 0, s2>>>(w_edge);
    packw_kernel<<<512, 256, 0, s2>>>(w_query, w_key, w_value, w_skip,
                                      b_query, b_key, b_value, b_skip, w_edge);
    hist_kernel<<<256, 256, 0, s2>>>(ei);
    scan_kernel<<<1, 1024, 0, s2>>>();
    scatter_kernel<<<256, 256, 0, s2>>>(ei);
    cudaEventRecord(evJ, s2);

    // ---- main stream: LN1 -> QKV -> attention -> out-proj -> LN2 ----
    ln_kernel<<<NN, 128>>>(x, n1g, n1b, xn);
    WG_SMALL(0, 128)<<<dim3(6, 64, 1), 128>>>(xn, w_qkv, b_qkv, qkvb, 128, 128, 384, 384,
                                              0, 0, 0, 0, nullptr, nullptr, nullptr);
    attn_wmma_kernel<<<dim3(NN/128, HEADSC), 256>>>(qkvb, attnb);
    WG_NARROW(2, 128)<<<dim3(4, 64, 1), 128>>>(attnb, w_o, b_o, x1, 128, 128, 128, 128,
                                               0, 0, 0, 0, x, nullptr, nullptr);
    ln_kernel<<<NN, 128>>>(x1, n2g, n2b, xn2);

    // join: merged proj needs packW/packB; later kernels need packT/packC/CSR
    cudaStreamWaitEvent(0, evJ, 0);

    // merged projections q|k|v|skip (4096 x 3200, K=128)
    WG_SMALL(0, 128)<<<dim3(NPROJ/64, 64, 1), 128>>>(xn2, packW, packB, qkvg,
                                                     128, 128, NPROJ, NPROJ,
                                                     0, 0, 0, 0, nullptr, nullptr, nullptr);
    // batched t-GEMM (8x [4096x128, K=128], direct store)
    WG_NARROW(5, 128)<<<dim3(4, 64, 8), 128>>>(qg, packT, nullptr, tb, 128, NPROJ, 128, HGC,
                                               128, 128*128, 128, 0, nullptr, nullptr, nullptr);
    // eg-free segment-softmax aggregation
    graph_agg3_kernel<<<NN, 256>>>(ei, eattr, b_edge, qkvg);
    // c-GEMM: aggout = cnorm @ packC + vsum
    WG_NARROW(4, 0)<<<dim3(4, 64, 1), 128>>>(cnorm, packC, nullptr, aggo, HGC, HGC, 128, 128,
                                             0, 0, 0, 0, vsum, nullptr, nullptr);
    // fused beta gate + combine + LN3
    beta_ln_kernel<<<NN, 128>>>(w_beta, n3g, n3b, qkvg);
    // FFN up + GELU
    WG_SMALL(1, 128)<<<dim3(32, 64, 1), 128>>>(xn3, w_f1, b_f1, ffnb, 128, 128, FFNC, FFNC,
                                               0, 0, 0, 0, nullptr, nullptr, nullptr);
    // FFN down + residual
    WG_NARROW(2, 0)<<<dim3(4, 64, 1), 128>>>(ffnb, w_f2, b_f2, x3, FFNC, FFNC, 128, 128,
                                             0, 0, 0, 0, x2p, nullptr, nullptr);
    // dyn gate (dual-A = [x3 | x])
    WG_NARROW_DUAL(3, 256)<<<dim3(4, 64, 1), 128>>>(x3, w_dyn, b_dyn, out, 256, 128, 128, 128,
                                                    0, 0, 0, 0, x3, x, x);
}

// round 13
// speedup vs baseline: 1.0936x; 1.0689x over previous
#include <cuda_runtime.h>
#include <cuda_bf16.h>
#include <mma.h>
#include <math.h>

using namespace nvcuda;

#define NN   4096
#define DIMC 128
#define HEADSC 8
#define HGC  1024      // HEADS * GC
#define EC   65536
#define FFNC 2048
#define NPROJ 3200     // 3*1024 + 128 (q|k|v|skip)

// ---------------- scratch (device globals; no allocation allowed) ----------------
__device__ float g_xn[NN*DIMC];
__device__ float g_qkv[NN*3*DIMC];
__device__ float g_attn[NN*DIMC];
__device__ float g_x1[NN*DIMC];
__device__ float g_xn2[NN*DIMC];
__device__ float g_qkvg[(size_t)NN*NPROJ];   // per row: qg|kg|vg|xr
__device__ float g_t[NN*HGC];                // per-head W_h @ qg
__device__ __nv_bfloat16 g_kvh[(size_t)NN*2048];  // bf16 copy: kg|vg per row
__device__ float g_packT[HEADSC*128*128];
__device__ float g_packC[HEADSC*128*128];
__device__ float g_packW[DIMC*NPROJ];        // [wq|wk|wv|wskip] col-concat
__device__ float g_packB[NPROJ];
__device__ float g_cnorm[NN*HGC];
__device__ float g_vsum[NN*DIMC];
__device__ int   g_deg[NN];
__device__ int   g_off[NN+1];
__device__ int   g_cur[NN];
__device__ int   g_eid[EC];
__device__ float g_aggout[NN*DIMC];
__device__ float g_x2[NN*DIMC];
__device__ float g_xn3[NN*DIMC];
__device__ float g_ffn[NN*FFNC];
__device__ float g_x3[NN*DIMC];

// ---------------- helpers ----------------
__device__ __forceinline__ float warp_sum(float v) {
    #pragma unroll
    for (int o = 16; o > 0; o >>= 1) v += __shfl_xor_sync(0xffffffffu, v, o);
    return v;
}

__device__ __forceinline__ void warp_sum4(float& a, float& b, float& c, float& d) {
    #pragma unroll
    for (int o = 16; o > 0; o >>= 1) {
        a += __shfl_xor_sync(0xffffffffu, a, o);
        b += __shfl_xor_sync(0xffffffffu, b, o);
        c += __shfl_xor_sync(0xffffffffu, c, o);
        d += __shfl_xor_sync(0xffffffffu, d, o);
    }
}

__device__ __forceinline__ float4 ldkv(const __nv_bfloat16* p) {
    uint2 raw = *(const uint2*)p;
    __nv_bfloat162 a = *reinterpret_cast<__nv_bfloat162*>(&raw.x);
    __nv_bfloat162 b = *reinterpret_cast<__nv_bfloat162*>(&raw.y);
    float2 fa = __bfloat1622float2(a), fb = __bfloat1622float2(b);
    return make_float4(fa.x, fa.y, fb.x, fb.y);
}

// MODE: 0 = +bias, 1 = +bias->GELU, 2 = +bias+aux1, 3 = +bias->sigmoid gate(a1,a2),
//       4 = +aux1 (no bias), 5 = raw store (no bias, no aux)
template<int MODE>
__device__ __forceinline__ float epilogue(float acc, float bias, float a1, float a2) {
    float v = (MODE == 4 || MODE == 5) ? acc : (acc + bias);
    if (MODE == 1) {
        v = 0.5f * v * (1.0f + erff(v * 0.7071067811865476f));
    } else if (MODE == 2 || MODE == 4) {
        v = v + a1;
    } else if (MODE == 3) {
        float s = 1.0f / (1.0f + expf(-v));
        v = a1 * s + a2 * (1.0f - s);
    }
    return v;
}

// ---------------- TF32 tensor-core GEMM via wmma (m16n16k8) ----------------
template<int BM, int BN, int WARPS_M, int WARPS_N, int WM, int WN, int MODE, bool DUALA, int KFIX>
__global__ void __launch_bounds__(WARPS_M*WARPS_N*32)
wgemm(const float* __restrict__ A, const float* __restrict__ B,
      const float* __restrict__ bias, float* __restrict__ C,
      int K, int lda, int ldb, int ldc,
      long sA, long sB, long sC, long sBias,
      const float* __restrict__ aux1, const float* __restrict__ aux2,
      const float* __restrict__ A2) {
    constexpr int NT  = WARPS_M * WARPS_N * 32;
    constexpr int SAS = 36;
    constexpr int SBS = BN + 4;
    constexpr int AI  = (BM * 8) / NT;
    constexpr int BI  = (BN * 8) / NT;
    constexpr int WORDS = BM * SAS + 32 * SBS;
    constexpr int STAGES = (WORDS * 8 <= 48 * 1024) ? 2 : 1;
    __shared__ float As[STAGES][BM * SAS];
    __shared__ float Bs[STAGES][32 * SBS];
    const int tid  = threadIdx.x;
    const int wid  = tid >> 5;
    const int lane = tid & 31;
    const int bm = blockIdx.y * BM;
    const int bn = blockIdx.x * BN;
    A += (size_t)blockIdx.z * sA;
    B += (size_t)blockIdx.z * sB;
    C += (size_t)blockIdx.z * sC;
    if (MODE != 4 && MODE != 5) bias += (size_t)blockIdx.z * sBias;
    const int warp_m = (wid / WARPS_N) * (WM * 16);
    const int warp_n = (wid % WARPS_N) * (WN * 16);
    const int KK = KFIX ? KFIX : K;

    wmma::fragment<wmma::accumulator, 16, 16, 8, float> cf[WM][WN];
    #pragma unroll
    for (int i = 0; i < WM; i++)
        #pragma unroll
        for (int j = 0; j < WN; j++) wmma::fill_fragment(cf[i][j], 0.0f);

    float4 av[AI], bv[BI];
    auto load_tiles = [&](int k0) {
        #pragma unroll
        for (int i = 0; i < AI; i++) {
            int idx = tid + i * NT;
            int kk = k0 + (idx & 7) * 4;
            const float* src;
            if (DUALA && kk >= 128) src = &A2[(size_t)(bm + (idx >> 3)) * 128 + (kk - 128)];
            else                    src = &A[(size_t)(bm + (idx >> 3)) * lda + kk];
            av[i] = *(const float4*)src;
        }
        #pragma unroll
        for (int i = 0; i < BI; i++) {
            int idx = tid + i * NT;
            bv[i] = *(const float4*)&B[(size_t)(k0 + idx / (BN / 4)) * ldb + bn + (idx % (BN / 4)) * 4];
        }
    };
    auto store_smem = [&](int st) {
        #pragma unroll
        for (int i = 0; i < AI; i++) {
            int idx = tid + i * NT;
            *(float4*)&As[st][(idx >> 3) * SAS + (idx & 7) * 4] = av[i];
        }
        #pragma unroll
        for (int i = 0; i < BI; i++) {
            int idx = tid + i * NT;
            *(float4*)&Bs[st][(idx / (BN / 4)) * SBS + (idx % (BN / 4)) * 4] = bv[i];
        }
    };

    int cur = 0;
    load_tiles(0);
    store_smem(0);
    __syncthreads();
    for (int k0 = 0; k0 < KK; k0 += 32) {
        bool more = (k0 + 32 < KK);
        if (more) load_tiles(k0 + 32);
        #pragma unroll
        for (int kk = 0; kk < 4; kk++) {
            wmma::fragment<wmma::matrix_a, 16, 16, 8, wmma::precision::tf32, wmma::row_major> af[WM];
            wmma::fragment<wmma::matrix_b, 16, 16, 8, wmma::precision::tf32, wmma::row_major> bf[WN];
            #pragma unroll
            for (int i = 0; i < WM; i++)
                wmma::load_matrix_sync(af[i], &As[cur][(warp_m + i * 16) * SAS + kk * 8], SAS);
            #pragma unroll
            for (int j = 0; j < WN; j++)
                wmma::load_matrix_sync(bf[j], &Bs[cur][kk * 8 * SBS + warp_n + j * 16], SBS);
            #pragma unroll
            for (int i = 0; i < WM; i++)
                #pragma unroll
                for (int j = 0; j < WN; j++)
                    wmma::mma_sync(cf[i][j], af[i], bf[j], cf[i][j]);
        }
        if (more) {
            if (STAGES == 2) {
                store_smem(1 - cur);
                __syncthreads();
                cur ^= 1;
            } else {
                __syncthreads();
                store_smem(0);
                __syncthreads();
            }
        }
    }

    if (MODE == 5) {
        #pragma unroll
        for (int i = 0; i < WM; i++)
            #pragma unroll
            for (int j = 0; j < WN; j++) {
                int row0 = bm + warp_m + i * 16;
                int col0 = bn + warp_n + j * 16;
                wmma::store_matrix_sync(&C[(size_t)row0 * ldc + col0], cf[i][j], ldc,
                                        wmma::mem_row_major);
            }
        return;
    }

    __syncthreads();
    float* scratch = &As[0][wid * 256];
    #pragma unroll
    for (int i = 0; i < WM; i++) {
        #pragma unroll
        for (int j = 0; j < WN; j++) {
            wmma::store_matrix_sync(scratch, cf[i][j], 16, wmma::mem_row_major);
            __syncwarp();
            int row0 = bm + warp_m + i * 16;
            int col0 = bn + warp_n + j * 16;
            #pragma unroll
            for (int e = 0; e < 8; e++) {
                int idx = lane + e * 32;
                int r = row0 + (idx >> 4);
                int c = col0 + (idx & 15);
                float acc = scratch[idx];
                float bvv = (MODE == 4) ? 0.0f : bias[c];
                size_t o = (size_t)r * ldc + c;
                float u = 0.f, w = 0.f;
                if (MODE == 2 || MODE == 3 || MODE == 4) u = aux1[o];
                if (MODE == 3) w = aux2[o];
                C[o] = epilogue<MODE>(acc, bvv, u, w);
            }
            __syncwarp();
        }
    }
}

// ---------------- LayerNorm ----------------
__global__ void ln_kernel(const float* __restrict__ x, const float* __restrict__ g,
                          const float* __restrict__ b, float* __restrict__ out) {
    int row = blockIdx.x, t = threadIdx.x;
    float v = x[row * DIMC + t];
    __shared__ float red[4];
    float s = warp_sum(v);
    if ((t & 31) == 0) red[t >> 5] = s;
    __syncthreads();
    float mean = (red[0] + red[1] + red[2] + red[3]) * (1.0f / 128.0f);
    float d = v - mean;
    float s2 = warp_sum(d * d);
    __syncthreads();
    if ((t & 31) == 0) red[t >> 5] = s2;
    __syncthreads();
    float var = (red[0] + red[1] + red[2] + red[3]) * (1.0f / 128.0f);
    out[row * DIMC + t] = d * rsqrtf(var + 1e-5f) * g[t] + b[t];
}

// ---------------- dense MHA via TF32 wmma (flash-style, no-max softmax) ----------------
// Denominator computed from S-accumulator fragments (sm80 f32 acc layout:
// x0,x1,x4,x5 -> row g; x2,x3,x6,x7 -> row g+8), no ones-mma needed.
#define ABK 64
#define APS 68
__global__ void __launch_bounds__(256)
attn_wmma_kernel(const float* __restrict__ qkv, float* __restrict__ attn) {
    __shared__ float Ks[ABK * 16];
    __shared__ float Vs[ABK * 16];
    __shared__ float Ps[8 * 16 * APS];
    __shared__ float dens[128];
    const int tid  = threadIdx.x;
    const int wid  = tid >> 5;
    const int lane = tid & 31;
    const int h  = blockIdx.y;
    const int q0 = blockIdx.x * 128;
    float* Pw = &Ps[wid * 16 * APS];

    #pragma unroll
    for (int i = 0; i < 2; i++) {
        int idx = tid + i * 256;
        int r = idx >> 2, d4 = (idx & 3) * 4;
        float4 q4 = *(const float4*)&qkv[(size_t)(q0 + r) * 384 + h * 16 + d4];
        Ps[r * 16 + d4 + 0] = q4.x * 0.25f;
        Ps[r * 16 + d4 + 1] = q4.y * 0.25f;
        Ps[r * 16 + d4 + 2] = q4.z * 0.25f;
        Ps[r * 16 + d4 + 3] = q4.w * 0.25f;
    }
    __syncthreads();
    wmma::fragment<wmma::matrix_a, 16, 16, 8, wmma::precision::tf32, wmma::row_major> af[2];
    #pragma unroll
    for (int k0 = 0; k0 < 2; k0++)
        wmma::load_matrix_sync(af[k0], &Ps[(wid * 16) * 16 + k0 * 8], 16);
    __syncthreads();

    wmma::fragment<wmma::accumulator, 16, 16, 8, float> oacc;
    wmma::fill_fragment(oacc, 0.0f);
    float dh0 = 0.0f, dh1 = 0.0f;   // row g / row g+8 denominator partials

    const int key = tid >> 2, d4 = (tid & 3) * 4;
    float4 k4 = *(const float4*)&qkv[(size_t)key * 384 + 128 + h * 16 + d4];
    float4 v4 = *(const float4*)&qkv[(size_t)key * 384 + 256 + h * 16 + d4];

    for (int kt = 0; kt < NN; kt += ABK) {
        __syncthreads();
        *(float4*)&Ks[key * 16 + d4] = k4;
        *(float4*)&Vs[key * 16 + d4] = v4;
        __syncthreads();
        if (kt + ABK < NN) {
            const float* kp = &qkv[(size_t)(kt + ABK + key) * 384 + 128 + h * 16 + d4];
            k4 = *(const float4*)kp;
            v4 = *(const float4*)(kp + 128);
        }

        wmma::fragment<wmma::accumulator, 16, 16, 8, float> sacc[4];
        #pragma unroll
        for (int nt = 0; nt < 4; nt++) wmma::fill_fragment(sacc[nt], 0.0f);
        #pragma unroll
        for (int k0 = 0; k0 < 2; k0++) {
            #pragma unroll
            for (int nt = 0; nt < 4; nt++) {
                wmma::fragment<wmma::matrix_b, 16, 16, 8, wmma::precision::tf32, wmma::col_major> bf;
                wmma::load_matrix_sync(bf, &Ks[(nt * 16) * 16 + k0 * 8], 16);
                wmma::mma_sync(sacc[nt], af[k0], bf, sacc[nt]);
            }
        }
        #pragma unroll
        for (int nt = 0; nt < 4; nt++) {
            #pragma unroll
            for (int t = 0; t < sacc[nt].num_elements; t++)
                sacc[nt].x[t] = __expf(sacc[nt].x[t]);
            dh0 += (sacc[nt].x[0] + sacc[nt].x[1]) + (sacc[nt].x[4] + sacc[nt].x[5]);
            dh1 += (sacc[nt].x[2] + sacc[nt].x[3]) + (sacc[nt].x[6] + sacc[nt].x[7]);
            wmma::store_matrix_sync(&Pw[nt * 16], sacc[nt], APS, wmma::mem_row_major);
        }
        __syncwarp();
        #pragma unroll
        for (int k0 = 0; k0 < 8; k0++) {
            wmma::fragment<wmma::matrix_a, 16, 16, 8, wmma::precision::tf32, wmma::row_major> pa;
            wmma::fragment<wmma::matrix_b, 16, 16, 8, wmma::precision::tf32, wmma::row_major> vb;
            wmma::load_matrix_sync(pa, &Pw[k0 * 8], APS);
            wmma::load_matrix_sync(vb, &Vs[(k0 * 8) * 16], 16);
            wmma::mma_sync(oacc, pa, vb, oacc);
        }
        __syncwarp();
    }

    // combine denominator across the 4-lane tg group
    dh0 += __shfl_xor_sync(0xffffffffu, dh0, 1);
    dh0 += __shfl_xor_sync(0xffffffffu, dh0, 2);
    dh1 += __shfl_xor_sync(0xffffffffu, dh1, 1);
    dh1 += __shfl_xor_sync(0xffffffffu, dh1, 2);
    if ((lane & 3) == 0) {
        dens[wid * 16 + (lane >> 2)]     = dh0;
        dens[wid * 16 + 8 + (lane >> 2)] = dh1;
    }
    __syncwarp();
    wmma::store_matrix_sync(Pw, oacc, APS, wmma::mem_row_major);
    __syncwarp();
    #pragma unroll
    for (int e = 0; e < 8; e++) {
        int idx = lane + e * 32;
        int r = idx >> 4, c = idx & 15;
        float v = Pw[r * APS + c] / dens[wid * 16 + r];
        attn[(size_t)(q0 + wid * 16 + r) * DIMC + h * 16 + c] = v;
    }
}

// ---------------- kg|vg -> bf16 copy ----------------
__global__ void kv2bf_kernel(const float* __restrict__ qkvg) {
    for (size_t i = (size_t)blockIdx.x * blockDim.x + threadIdx.x;
         i < (size_t)NN * 512; i += (size_t)gridDim.x * blockDim.x) {
        int n = (int)(i >> 9);            // 512 float4 per row (2048 floats)
        int c4 = (int)(i & 511);
        float4 v = *(const float4*)&qkvg[(size_t)n * NPROJ + 1024 + c4 * 4];
        __nv_bfloat162 lo = __floats2bfloat162_rn(v.x, v.y);
        __nv_bfloat162 hi = __floats2bfloat162_rn(v.z, v.w);
        uint2 raw;
        raw.x = *reinterpret_cast<unsigned*>(&lo);
        raw.y = *reinterpret_cast<unsigned*>(&hi);
        *(uint2*)&g_kvh[(size_t)n * 2048 + c4 * 4] = raw;
    }
}

// ---------------- packT via tiled transpose ----------------
__global__ void packT_kernel(const float* __restrict__ w_edge) {
    __shared__ float tile[32][33];
    int h  = blockIdx.z;
    int k0 = blockIdx.x * 32;
    int j0 = blockIdx.y * 32;
    int tx = threadIdx.x, ty0 = threadIdx.y;
    #pragma unroll
    for (int i = 0; i < 4; i++) {
        int j = j0 + ty0 + i * 8;
        tile[ty0 + i * 8][tx] = w_edge[(size_t)j * HGC + h * 128 + k0 + tx];
    }
    __syncthreads();
    #pragma unroll
    for (int i = 0; i < 4; i++) {
        int k = k0 + ty0 + i * 8;
        g_packT[h * 16384 + k * 128 + j0 + tx] = tile[tx][ty0 + i * 8];
    }
}

// ---------------- pack [wq|wk|wv|wskip] + biases + packC; zero g_deg ----------------
__global__ void packw_kernel(const float* __restrict__ wq, const float* __restrict__ wk,
                             const float* __restrict__ wv, const float* __restrict__ wsk,
                             const float* __restrict__ bq, const float* __restrict__ bk,
                             const float* __restrict__ bv, const float* __restrict__ bsk,
                             const float* __restrict__ w_edge) {
    for (int idx = blockIdx.x * blockDim.x + threadIdx.x; idx < DIMC * NPROJ;
         idx += gridDim.x * blockDim.x) {
        int k = idx / NPROJ, j = idx % NPROJ;
        float v;
        if (j < 1024)      v = wq[k * 1024 + j];
        else if (j < 2048) v = wk[k * 1024 + j - 1024];
        else if (j < 3072) v = wv[k * 1024 + j - 2048];
        else               v = wsk[k * 128 + j - 3072];
        g_packW[idx] = v;
        if (idx < HEADSC * 128 * 128) {
            int jj = idx & 127;
            int kk = (idx >> 7) & 127;
            int hh = idx >> 14;
            g_packC[idx] = w_edge[(size_t)kk * HGC + hh * 128 + jj];
        }
        if (idx < NPROJ) {
            float bvv;
            if (idx < 1024)      bvv = bq[idx];
            else if (idx < 2048) bvv = bk[idx - 1024];
            else if (idx < 3072) bvv = bv[idx - 2048];
            else                 bvv = bsk[idx - 3072];
            g_packB[idx] = bvv;
        }
        if (idx < NN) g_deg[idx] = 0;
    }
}

// ---------------- CSR build ----------------
__global__ void hist_kernel(const int* __restrict__ ei) {
    const int* dst = ei + EC;
    for (int e = blockIdx.x * blockDim.x + threadIdx.x; e < EC; e += gridDim.x * blockDim.x)
        atomicAdd(&g_deg[dst[e]], 1);
}
__global__ void scan_kernel() {   // warp-scan; also initializes g_cur
    int t = threadIdx.x;
    int lane = t & 31, w = t >> 5;
    int base = t * 4;
    int d0 = g_deg[base], d1 = g_deg[base+1], d2 = g_deg[base+2], d3 = g_deg[base+3];
    int tot = d0 + d1 + d2 + d3;
    int v = tot;
    #pragma unroll
    for (int o = 1; o < 32; o <<= 1) {
        int u = __shfl_up_sync(0xffffffffu, v, o);
        if (lane >= o) v += u;
    }
    __shared__ int wsum[32];
    if (lane == 31) wsum[w] = v;
    __syncthreads();
    if (t < 32) {
        int wv = wsum[t];
        #pragma unroll
        for (int o = 1; o < 32; o <<= 1) {
            int u = __shfl_up_sync(0xffffffffu, wv, o);
            if (t >= o) wv += u;
        }
        wsum[t] = wv;
    }
    __syncthreads();
    int incl = v + (w ? wsum[w - 1] : 0);
    int run = incl - tot;
    g_off[base] = run;   g_cur[base] = run;     run += d0;
    g_off[base+1] = run; g_cur[base+1] = run;   run += d1;
    g_off[base+2] = run; g_cur[base+2] = run;   run += d2;
    g_off[base+3] = run; g_cur[base+3] = run;   run += d3;
    if (t == 1023) g_off[NN] = incl;
}
__global__ void scatter_kernel(const int* __restrict__ ei) {
    const int* dst = ei + EC;
    for (int e = blockIdx.x * blockDim.x + threadIdx.x; e < EC; e += gridDim.x * blockDim.x) {
        int p = atomicAdd(&g_cur[dst[e]], 1);
        g_eid[p] = e;
    }
}

// ---------------- graph aggregation: smem edge staging, bf16 kg/vg gathers ----------------
__global__ void graph_agg3_kernel(const int* __restrict__ ei,
                                  const float* __restrict__ edge_attr,
                                  const float* __restrict__ b_edge,
                                  const float* __restrict__ qkvg) {
    int n = blockIdx.x;
    int tid = threadIdx.x;
    int h = tid >> 5;
    int lane = tid & 31;
    const int* src = ei;
    const float invsq = 0.08838834764831845f;  // 1/sqrt(128)
    const int hoff = h * 128 + lane * 4;
    float4 qh = *(const float4*)&qkvg[(size_t)n * NPROJ + hoff];
    qh.x *= invsq; qh.y *= invsq; qh.z *= invsq; qh.w *= invsq;
    float4 th = *(const float4*)&g_t[n * HGC + hoff];
    th.x *= invsq; th.y *= invsq; th.z *= invsq; th.w *= invsq;
    float4 be4 = *(const float4*)&b_edge[hoff];
    float s0s = warp_sum(qh.x*be4.x + qh.y*be4.y + qh.z*be4.z + qh.w*be4.w);

    __shared__ float ea_s[8][132];
    __shared__ int src_s[8];
    float4 cacc = {0.f, 0.f, 0.f, 0.f};
    float4 vacc = {0.f, 0.f, 0.f, 0.f};
    float den = 0.0f;
    int beg = g_off[n], end = g_off[n + 1];

    for (int i0 = beg; i0 < end; i0 += 8) {
        int cnt = min(8, end - i0);
        __syncthreads();
        if (h < cnt) {
            int e = g_eid[i0 + h];
            if (lane == 0) src_s[h] = src[e];
            *(float4*)&ea_s[h][lane * 4] = *(const float4*)&edge_attr[(size_t)e * DIMC + lane * 4];
        }
        __syncthreads();
        int j = 0;
        for (; j + 3 < cnt; j += 4) {
            int sa = src_s[j], sb = src_s[j+1], sc = src_s[j+2], sd = src_s[j+3];
            float4 ea0 = *(const float4*)&ea_s[j  ][lane * 4];
            float4 ea1 = *(const float4*)&ea_s[j+1][lane * 4];
            float4 ea2 = *(const float4*)&ea_s[j+2][lane * 4];
            float4 ea3 = *(const float4*)&ea_s[j+3][lane * 4];
            float4 ka = ldkv(&g_kvh[(size_t)sa * 2048 + hoff]);
            float4 kb = ldkv(&g_kvh[(size_t)sb * 2048 + hoff]);
            float4 kc = ldkv(&g_kvh[(size_t)sc * 2048 + hoff]);
            float4 kd = ldkv(&g_kvh[(size_t)sd * 2048 + hoff]);
            float4 va = ldkv(&g_kvh[(size_t)sa * 2048 + 1024 + hoff]);
            float4 vb = ldkv(&g_kvh[(size_t)sb * 2048 + 1024 + hoff]);
            float4 vc = ldkv(&g_kvh[(size_t)sc * 2048 + 1024 + hoff]);
            float4 vd = ldkv(&g_kvh[(size_t)sd * 2048 + 1024 + hoff]);
            float t0 = qh.x*ka.x + qh.y*ka.y + qh.z*ka.z + qh.w*ka.w;
            t0 = fmaf(th.x, ea0.x, t0); t0 = fmaf(th.y, ea0.y, t0);
            t0 = fmaf(th.z, ea0.z, t0); t0 = fmaf(th.w, ea0.w, t0);
            float t1 = qh.x*kb.x + qh.y*kb.y + qh.z*kb.z + qh.w*kb.w;
            t1 = fmaf(th.x, ea1.x, t1); t1 = fmaf(th.y, ea1.y, t1);
            t1 = fmaf(th.z, ea1.z, t1); t1 = fmaf(th.w, ea1.w, t1);
            float t2 = qh.x*kc.x + qh.y*kc.y + qh.z*kc.z + qh.w*kc.w;
            t2 = fmaf(th.x, ea2.x, t2); t2 = fmaf(th.y, ea2.y, t2);
            t2 = fmaf(th.z, ea2.z, t2); t2 = fmaf(th.w, ea2.w, t2);
            float t3 = qh.x*kd.x + qh.y*kd.y + qh.z*kd.z + qh.w*kd.w;
            t3 = fmaf(th.x, ea3.x, t3); t3 = fmaf(th.y, ea3.y, t3);
            t3 = fmaf(th.z, ea3.z, t3); t3 = fmaf(th.w, ea3.w, t3);
            warp_sum4(t0, t1, t2, t3);
            float p0 = expf(t0 + s0s), p1 = expf(t1 + s0s);
            float p2 = expf(t2 + s0s), p3 = expf(t3 + s0s);
            den += (p0 + p1) + (p2 + p3);
            cacc.x = fmaf(p0, ea0.x, fmaf(p1, ea1.x, fmaf(p2, ea2.x, fmaf(p3, ea3.x, cacc.x))));
            cacc.y = fmaf(p0, ea0.y, fmaf(p1, ea1.y, fmaf(p2, ea2.y, fmaf(p3, ea3.y, cacc.y))));
            cacc.z = fmaf(p0, ea0.z, fmaf(p1, ea1.z, fmaf(p2, ea2.z, fmaf(p3, ea3.z, cacc.z))));
            cacc.w = fmaf(p0, ea0.w, fmaf(p1, ea1.w, fmaf(p2, ea2.w, fmaf(p3, ea3.w, cacc.w))));
            vacc.x = fmaf(p0, va.x, fmaf(p1, vb.x, fmaf(p2, vc.x, fmaf(p3, vd.x, vacc.x))));
            vacc.y = fmaf(p0, va.y, fmaf(p1, vb.y, fmaf(p2, vc.y, fmaf(p3, vd.y, vacc.y))));
            vacc.z = fmaf(p0, va.z, fmaf(p1, vb.z, fmaf(p2, vc.z, fmaf(p3, vd.z, vacc.z))));
            vacc.w = fmaf(p0, va.w, fmaf(p1, vb.w, fmaf(p2, vc.w, fmaf(p3, vd.w, vacc.w))));
        }
        for (; j < cnt; j++) {
            int s = src_s[j];
            float4 ea = *(const float4*)&ea_s[j][lane * 4];
            float4 k4 = ldkv(&g_kvh[(size_t)s * 2048 + hoff]);
            float4 v4 = ldkv(&g_kvh[(size_t)s * 2048 + 1024 + hoff]);
            float t = qh.x*k4.x + qh.y*k4.y + qh.z*k4.z + qh.w*k4.w;
            t = fmaf(th.x, ea.x, t); t = fmaf(th.y, ea.y, t);
            t = fmaf(th.z, ea.z, t); t = fmaf(th.w, ea.w, t);
            t = warp_sum(t) + s0s;
            float p = expf(t);
            den += p;
            cacc.x = fmaf(p, ea.x, cacc.x); cacc.y = fmaf(p, ea.y, cacc.y);
            cacc.z = fmaf(p, ea.z, cacc.z); cacc.w = fmaf(p, ea.w, cacc.w);
            vacc.x = fmaf(p, v4.x, vacc.x); vacc.y = fmaf(p, v4.y, vacc.y);
            vacc.z = fmaf(p, v4.z, vacc.z); vacc.w = fmaf(p, v4.w, vacc.w);
        }
    }
    bool nonempty = (end > beg);
    float invden = nonempty ? 1.0f / den : 0.0f;
    float4 c4 = {cacc.x*invden, cacc.y*invden, cacc.z*invden, cacc.w*invden};
    *(float4*)&g_cnorm[n * HGC + hoff] = c4;

    __shared__ float sh[8][128];
    float gate = nonempty ? 1.0f : 0.0f;
    __syncthreads();
    sh[h][lane*4+0] = fmaf(vacc.x, invden, be4.x * gate);
    sh[h][lane*4+1] = fmaf(vacc.y, invden, be4.y * gate);
    sh[h][lane*4+2] = fmaf(vacc.z, invden, be4.z * gate);
    sh[h][lane*4+3] = fmaf(vacc.w, invden, be4.w * gate);
    __syncthreads();
    if (tid < 128) {
        int d = tid;
        float sum = 0.0f;
        #pragma unroll
        for (int hh = 0; hh < 8; hh++) sum += sh[hh][d];
        g_vsum[n * DIMC + d] = sum;
    }
}

// ---------------- fused beta gate + combine + LN3 ----------------
__global__ void beta_ln_kernel(const float* __restrict__ wb,
                               const float* __restrict__ g3, const float* __restrict__ b3,
                               const float* __restrict__ qkvg) {
    int n = blockIdx.x, t = threadIdx.x;
    float o = g_aggout[n * DIMC + t] * 0.125f;
    float xr = qkvg[(size_t)n * NPROJ + 3072 + t];
    float part = o * (wb[t] + wb[256 + t]) + xr * (wb[128 + t] - wb[256 + t]);
    __shared__ float red[4];
    float s = warp_sum(part);
    if ((t & 31) == 0) red[t >> 5] = s;
    __syncthreads();
    float z = red[0] + red[1] + red[2] + red[3];
    float beta = 1.0f / (1.0f + expf(-z));
    float x2 = g_x1[n * DIMC + t] + beta * xr + (1.0f - beta) * o;
    g_x2[n * DIMC + t] = x2;
    __syncthreads();
    float sm = warp_sum(x2);
    if ((t & 31) == 0) red[t >> 5] = sm;
    __syncthreads();
    float mean = (red[0] + red[1] + red[2] + red[3]) * (1.0f / 128.0f);
    float d = x2 - mean;
    float s2 = warp_sum(d * d);
    __syncthreads();
    if ((t & 31) == 0) red[t >> 5] = s2;
    __syncthreads();
    float var = (red[0] + red[1] + red[2] + red[3]) * (1.0f / 128.0f);
    g_xn3[n * DIMC + t] = d * rsqrtf(var + 1e-5f) * g3[t] + b3[t];
}

// tile configs
#define WG_SMALL(MODE, KF)        wgemm<64,64,2,2,2,2,MODE,false,KF>
#define WG_NARROW(MODE, KF)       wgemm<64,32,2,2,2,1,MODE,false,KF>
#define WG_NARROW_DUAL(MODE, KF)  wgemm<64,32,2,2,2,1,MODE,true,KF>

// ---------------- launch ----------------
extern "C" void kernel_launch(void* const* d_in, const int* in_sizes, int n_in,
                              void* d_out, int out_size) {
    const float* x      = (const float*)d_in[0];
    const int*   ei     = (const int*)d_in[1];
    const float* eattr  = (const float*)d_in[2];
    const float* n1g = (const float*)d_in[3];  const float* n1b = (const float*)d_in[4];
    const float* n2g = (const float*)d_in[5];  const float* n2b = (const float*)d_in[6];
    const float* n3g = (const float*)d_in[7];  const float* n3b = (const float*)d_in[8];
    const float* w_qkv = (const float*)d_in[9];  const float* b_qkv = (const float*)d_in[10];
    const float* w_o   = (const float*)d_in[11]; const float* b_o   = (const float*)d_in[12];
    const float* w_query = (const float*)d_in[13]; const float* b_query = (const float*)d_in[14];
    const float* w_key   = (const float*)d_in[15]; const float* b_key   = (const float*)d_in[16];
    const float* w_value = (const float*)d_in[17]; const float* b_value = (const float*)d_in[18];
    const float* w_edge  = (const float*)d_in[19]; const float* b_edge  = (const float*)d_in[20];
    const float* w_skip  = (const float*)d_in[21]; const float* b_skip  = (const float*)d_in[22];
    const float* w_beta  = (const float*)d_in[23];
    const float* w_f1 = (const float*)d_in[24]; const float* b_f1 = (const float*)d_in[25];
    const float* w_f2 = (const float*)d_in[26]; const float* b_f2 = (const float*)d_in[27];
    const float* w_dyn = (const float*)d_in[28]; const float* b_dyn = (const float*)d_in[29];
    float* out = (float*)d_out;

    float *xn, *qkvb, *attnb, *x1, *xn2, *qkvg, *tb, *packT, *packC, *packW, *packB;
    float *cnorm, *vsum, *aggo, *xn3, *ffnb, *x3, *x2p;
    cudaGetSymbolAddress((void**)&xn,    g_xn);
    cudaGetSymbolAddress((void**)&qkvb,  g_qkv);
    cudaGetSymbolAddress((void**)&attnb, g_attn);
    cudaGetSymbolAddress((void**)&x1,    g_x1);
    cudaGetSymbolAddress((void**)&xn2,   g_xn2);
    cudaGetSymbolAddress((void**)&qkvg,  g_qkvg);
    cudaGetSymbolAddress((void**)&tb,    g_t);
    cudaGetSymbolAddress((void**)&packT, g_packT);
    cudaGetSymbolAddress((void**)&packC, g_packC);
    cudaGetSymbolAddress((void**)&packW, g_packW);
    cudaGetSymbolAddress((void**)&packB, g_packB);
    cudaGetSymbolAddress((void**)&cnorm, g_cnorm);
    cudaGetSymbolAddress((void**)&vsum,  g_vsum);
    cudaGetSymbolAddress((void**)&aggo,  g_aggout);
    cudaGetSymbolAddress((void**)&xn3,   g_xn3);
    cudaGetSymbolAddress((void**)&ffnb,  g_ffn);
    cudaGetSymbolAddress((void**)&x3,    g_x3);
    cudaGetSymbolAddress((void**)&x2p,   g_x2);
    float* qg = qkvg;

    // side stream for weight packing + CSR build
    static cudaStream_t s2 = nullptr;
    static cudaEvent_t evF = nullptr, evJ = nullptr;
    if (!s2) {
        cudaStreamCreateWithFlags(&s2, cudaStreamNonBlocking);
        cudaEventCreateWithFlags(&evF, cudaEventDisableTiming);
        cudaEventCreateWithFlags(&evJ, cudaEventDisableTiming);
    }
    cudaEventRecord(evF, 0);
    cudaStreamWaitEvent(s2, evF, 0);

    // ---- stream s2: packT, packw(+deg zero), hist, scan, scatter ----
    packT_kernel<<<dim3(4, 4, 8), dim3(32, 8), 0, s2>>>(w_edge);
    packw_kernel<<<512, 256, 0, s2>>>(w_query, w_key, w_value, w_skip,
                                      b_query, b_key, b_value, b_skip, w_edge);
    hist_kernel<<<256, 256, 0, s2>>>(ei);
    scan_kernel<<<1, 1024, 0, s2>>>();
    scatter_kernel<<<256, 256, 0, s2>>>(ei);
    cudaEventRecord(evJ, s2);

    // ---- main stream: LN1 -> QKV -> attention -> out-proj -> LN2 ----
    ln_kernel<<<NN, 128>>>(x, n1g, n1b, xn);
    WG_SMALL(0, 128)<<<dim3(6, 64, 1), 128>>>(xn, w_qkv, b_qkv, qkvb, 128, 128, 384, 384,
                                              0, 0, 0, 0, nullptr, nullptr, nullptr);
    attn_wmma_kernel<<<dim3(NN/128, HEADSC), 256>>>(qkvb, attnb);
    WG_NARROW(2, 128)<<<dim3(4, 64, 1), 128>>>(attnb, w_o, b_o, x1, 128, 128, 128, 128,
                                               0, 0, 0, 0, x, nullptr, nullptr);
    ln_kernel<<<NN, 128>>>(x1, n2g, n2b, xn2);

    cudaStreamWaitEvent(0, evJ, 0);

    // merged projections q|k|v|skip (4096 x 3200, K=128)
    WG_SMALL(0, 128)<<<dim3(NPROJ/64, 64, 1), 128>>>(xn2, packW, packB, qkvg,
                                                     128, 128, NPROJ, NPROJ,
                                                     0, 0, 0, 0, nullptr, nullptr, nullptr);
    // bf16 copy of kg|vg
    kv2bf_kernel<<<1024, 256>>>(qkvg);
    // batched t-GEMM (8x [4096x128, K=128], direct store)
    WG_NARROW(5, 128)<<<dim3(4, 64, 8), 128>>>(qg, packT, nullptr, tb, 128, NPROJ, 128, HGC,
                                               128, 128*128, 128, 0, nullptr, nullptr, nullptr);
    // eg-free segment-softmax aggregation (bf16 gathers)
    graph_agg3_kernel<<<NN, 256>>>(ei, eattr, b_edge, qkvg);
    // c-GEMM: aggout = cnorm @ packC + vsum
    WG_NARROW(4, 0)<<<dim3(4, 64, 1), 128>>>(cnorm, packC, nullptr, aggo, HGC, HGC, 128, 128,
                                             0, 0, 0, 0, vsum, nullptr, nullptr);
    // fused beta gate + combine + LN3
    beta_ln_kernel<<<NN, 128>>>(w_beta, n3g, n3b, qkvg);
    // FFN up + GELU
    WG_SMALL(1, 128)<<<dim3(32, 64, 1), 128>>>(xn3, w_f1, b_f1, ffnb, 128, 128, FFNC, FFNC,
                                               0, 0, 0, 0, nullptr, nullptr, nullptr);
    // FFN down + residual
    WG_NARROW(2, 0)<<<dim3(4, 64, 1), 128>>>(ffnb, w_f2, b_f2, x3, FFNC, FFNC, 128, 128,
                                             0, 0, 0, 0, x2p, nullptr, nullptr);
    // dyn gate (dual-A = [x3 | x])
    WG_NARROW_DUAL(3, 256)<<<dim3(4, 64, 1), 128>>>(x3, w_dyn, b_dyn, out, 256, 128, 128, 128,
                                                    0, 0, 0, 0, x3, x, x);
}

// round 15
// speedup vs baseline: 1.1888x; 1.0871x over previous
#include <cuda_runtime.h>
#include <cuda_bf16.h>
#include <mma.h>
#include <math.h>

using namespace nvcuda;

#define NN   4096
#define DIMC 128
#define HEADSC 8
#define HGC  1024      // HEADS * GC
#define EC   65536
#define FFNC 2048
#define NPROJ 3200     // 3*1024 + 128 (q|k|v|skip)

// ---------------- scratch (device globals; no allocation allowed) ----------------
__device__ float g_xn[NN*DIMC];
__device__ float g_qkv[NN*3*DIMC];
__device__ float g_attn[NN*DIMC];
__device__ float g_x1[NN*DIMC];
__device__ float g_xn2[NN*DIMC];
__device__ float g_qkvg[(size_t)NN*NPROJ];   // per row: qg|kg|vg|xr
__device__ float g_t[NN*HGC];                // per-head W_h @ qg
__device__ __nv_bfloat16 g_kvh[(size_t)NN*2048];  // bf16 copy: kg|vg per row
__device__ __nv_bfloat16 g_packTh[HEADSC*128*128];
__device__ __nv_bfloat16 g_packCh[HEADSC*128*128];
__device__ __nv_bfloat16 g_packWh[DIMC*NPROJ];    // [wq|wk|wv|wskip] bf16
__device__ float g_packB[NPROJ];
__device__ float g_cnorm[NN*HGC];
__device__ float g_vsum[NN*DIMC];
__device__ int   g_deg[NN];
__device__ int   g_off[NN+1];
__device__ int   g_cur[NN];
__device__ int   g_eid[EC];
__device__ float g_aggout[NN*DIMC];
__device__ float g_x2[NN*DIMC];
__device__ float g_xn3[NN*DIMC];
__device__ float g_ffn[NN*FFNC];
__device__ float g_x3[NN*DIMC];

// ---------------- helpers ----------------
__device__ __forceinline__ float warp_sum(float v) {
    #pragma unroll
    for (int o = 16; o > 0; o >>= 1) v += __shfl_xor_sync(0xffffffffu, v, o);
    return v;
}

__device__ __forceinline__ void warp_sum4(float& a, float& b, float& c, float& d) {
    #pragma unroll
    for (int o = 16; o > 0; o >>= 1) {
        a += __shfl_xor_sync(0xffffffffu, a, o);
        b += __shfl_xor_sync(0xffffffffu, b, o);
        c += __shfl_xor_sync(0xffffffffu, c, o);
        d += __shfl_xor_sync(0xffffffffu, d, o);
    }
}

__device__ __forceinline__ float4 ldkv(const __nv_bfloat16* p) {
    uint2 raw = *(const uint2*)p;
    __nv_bfloat162 a = *reinterpret_cast<__nv_bfloat162*>(&raw.x);
    __nv_bfloat162 b = *reinterpret_cast<__nv_bfloat162*>(&raw.y);
    float2 fa = __bfloat1622float2(a), fb = __bfloat1622float2(b);
    return make_float4(fa.x, fa.y, fb.x, fb.y);
}

// MODE: 0 = +bias, 1 = +bias->GELU, 2 = +bias+aux1, 3 = +bias->sigmoid gate(a1,a2),
//       4 = +aux1 (no bias), 5 = raw store, 6 = +bias & bf16 side-store (kg|vg)
template<int MODE>
__device__ __forceinline__ float epilogue(float acc, float bias, float a1, float a2) {
    float v = (MODE == 4 || MODE == 5) ? acc : (acc + bias);
    if (MODE == 1) {
        v = 0.5f * v * (1.0f + erff(v * 0.7071067811865476f));
    } else if (MODE == 2 || MODE == 4) {
        v = v + a1;
    } else if (MODE == 3) {
        float s = 1.0f / (1.0f + expf(-v));
        v = a1 * s + a2 * (1.0f - s);
    }
    return v;
}

// ---------------- TF32 tensor-core GEMM via wmma (m16n16k8) ----------------
template<int BM, int BN, int WARPS_M, int WARPS_N, int WM, int WN, int MODE, bool DUALA, int KFIX>
__global__ void __launch_bounds__(WARPS_M*WARPS_N*32)
wgemm(const float* __restrict__ A, const float* __restrict__ B,
      const float* __restrict__ bias, float* __restrict__ C,
      int K, int lda, int ldb, int ldc,
      long sA, long sB, long sC, long sBias,
      const float* __restrict__ aux1, const float* __restrict__ aux2,
      const float* __restrict__ A2) {
    constexpr int NT  = WARPS_M * WARPS_N * 32;
    constexpr int SAS = 36;
    constexpr int SBS = BN + 4;
    constexpr int AI  = (BM * 8) / NT;
    constexpr int BI  = (BN * 8) / NT;
    constexpr int WORDS = BM * SAS + 32 * SBS;
    constexpr int STAGES = (WORDS * 8 <= 48 * 1024) ? 2 : 1;
    __shared__ float As[STAGES][BM * SAS];
    __shared__ float Bs[STAGES][32 * SBS];
    const int tid  = threadIdx.x;
    const int wid  = tid >> 5;
    const int lane = tid & 31;
    const int bm = blockIdx.y * BM;
    const int bn = blockIdx.x * BN;
    A += (size_t)blockIdx.z * sA;
    B += (size_t)blockIdx.z * sB;
    C += (size_t)blockIdx.z * sC;
    if (MODE != 4 && MODE != 5) bias += (size_t)blockIdx.z * sBias;
    const int warp_m = (wid / WARPS_N) * (WM * 16);
    const int warp_n = (wid % WARPS_N) * (WN * 16);
    const int KK = KFIX ? KFIX : K;

    wmma::fragment<wmma::accumulator, 16, 16, 8, float> cf[WM][WN];
    #pragma unroll
    for (int i = 0; i < WM; i++)
        #pragma unroll
        for (int j = 0; j < WN; j++) wmma::fill_fragment(cf[i][j], 0.0f);

    float4 av[AI], bv[BI];
    auto load_tiles = [&](int k0) {
        #pragma unroll
        for (int i = 0; i < AI; i++) {
            int idx = tid + i * NT;
            int kk = k0 + (idx & 7) * 4;
            const float* src;
            if (DUALA && kk >= 128) src = &A2[(size_t)(bm + (idx >> 3)) * 128 + (kk - 128)];
            else                    src = &A[(size_t)(bm + (idx >> 3)) * lda + kk];
            av[i] = *(const float4*)src;
        }
        #pragma unroll
        for (int i = 0; i < BI; i++) {
            int idx = tid + i * NT;
            bv[i] = *(const float4*)&B[(size_t)(k0 + idx / (BN / 4)) * ldb + bn + (idx % (BN / 4)) * 4];
        }
    };
    auto store_smem = [&](int st) {
        #pragma unroll
        for (int i = 0; i < AI; i++) {
            int idx = tid + i * NT;
            *(float4*)&As[st][(idx >> 3) * SAS + (idx & 7) * 4] = av[i];
        }
        #pragma unroll
        for (int i = 0; i < BI; i++) {
            int idx = tid + i * NT;
            *(float4*)&Bs[st][(idx / (BN / 4)) * SBS + (idx % (BN / 4)) * 4] = bv[i];
        }
    };

    int cur = 0;
    load_tiles(0);
    store_smem(0);
    __syncthreads();
    for (int k0 = 0; k0 < KK; k0 += 32) {
        bool more = (k0 + 32 < KK);
        if (more) load_tiles(k0 + 32);
        #pragma unroll
        for (int kk = 0; kk < 4; kk++) {
            wmma::fragment<wmma::matrix_a, 16, 16, 8, wmma::precision::tf32, wmma::row_major> af[WM];
            wmma::fragment<wmma::matrix_b, 16, 16, 8, wmma::precision::tf32, wmma::row_major> bf[WN];
            #pragma unroll
            for (int i = 0; i < WM; i++)
                wmma::load_matrix_sync(af[i], &As[cur][(warp_m + i * 16) * SAS + kk * 8], SAS);
            #pragma unroll
            for (int j = 0; j < WN; j++)
                wmma::load_matrix_sync(bf[j], &Bs[cur][kk * 8 * SBS + warp_n + j * 16], SBS);
            #pragma unroll
            for (int i = 0; i < WM; i++)
                #pragma unroll
                for (int j = 0; j < WN; j++)
                    wmma::mma_sync(cf[i][j], af[i], bf[j], cf[i][j]);
        }
        if (more) {
            if (STAGES == 2) {
                store_smem(1 - cur);
                __syncthreads();
                cur ^= 1;
            } else {
                __syncthreads();
                store_smem(0);
                __syncthreads();
            }
        }
    }

    if (MODE == 5) {
        #pragma unroll
        for (int i = 0; i < WM; i++)
            #pragma unroll
            for (int j = 0; j < WN; j++) {
                int row0 = bm + warp_m + i * 16;
                int col0 = bn + warp_n + j * 16;
                wmma::store_matrix_sync(&C[(size_t)row0 * ldc + col0], cf[i][j], ldc,
                                        wmma::mem_row_major);
            }
        return;
    }

    __syncthreads();
    float* scratch = &As[0][wid * 256];
    #pragma unroll
    for (int i = 0; i < WM; i++) {
        #pragma unroll
        for (int j = 0; j < WN; j++) {
            wmma::store_matrix_sync(scratch, cf[i][j], 16, wmma::mem_row_major);
            __syncwarp();
            int row0 = bm + warp_m + i * 16;
            int col0 = bn + warp_n + j * 16;
            #pragma unroll
            for (int e = 0; e < 8; e++) {
                int idx = lane + e * 32;
                int r = row0 + (idx >> 4);
                int c = col0 + (idx & 15);
                float acc = scratch[idx];
                float bvv = (MODE == 4) ? 0.0f : bias[c];
                size_t o = (size_t)r * ldc + c;
                float u = 0.f, w = 0.f;
                if (MODE == 2 || MODE == 3 || MODE == 4) u = aux1[o];
                if (MODE == 3) w = aux2[o];
                C[o] = epilogue<MODE>(acc, bvv, u, w);
            }
            __syncwarp();
        }
    }
}

// ---------------- bf16 tensor-core GEMM (m16n16k16), 64x64 tile, 4 warps ----------------
// A fp32 row-major (converted to bf16 at smem store); B pre-packed bf16 row-major.
// MODE 6: +bias, and cols [1024,3072) also side-stored to g_kvh as bf16.
template<int MODE, int KFIX>
__global__ void __launch_bounds__(128)
hgemm(const float* __restrict__ A, const __nv_bfloat16* __restrict__ B,
      const float* __restrict__ bias, float* __restrict__ C,
      int K, int lda, int ldb, int ldc,
      long sA, long sB, long sC,
      const float* __restrict__ aux1) {
    constexpr int BM = 64, BN = 64;
    constexpr int SAS = 40;       // bf16 elements (pad to 8-elem multiple)
    constexpr int SBS = BN + 8;   // 72
    constexpr int AI  = (BM * 8) / 128;        // 4 float4 loads of A
    constexpr int BI  = (32 * BN / 8) / 128;   // 2 uint4 loads of B (8 bf16 each)
    __shared__ __nv_bfloat16 As[2][BM * SAS];
    __shared__ __nv_bfloat16 Bs[2][32 * SBS];
    __shared__ float scr[4][256];
    const int tid  = threadIdx.x;
    const int wid  = tid >> 5;
    const int lane = tid & 31;
    const int bm = blockIdx.y * BM;
    const int bn = blockIdx.x * BN;
    A += (size_t)blockIdx.z * sA;
    B += (size_t)blockIdx.z * sB;
    C += (size_t)blockIdx.z * sC;
    const int warp_m = (wid >> 1) * 32;   // 2x2 warps, warp tile 32x32
    const int warp_n = (wid & 1) * 32;
    const int KK = KFIX ? KFIX : K;

    wmma::fragment<wmma::accumulator, 16, 16, 16, float> cf[2][2];
    #pragma unroll
    for (int i = 0; i < 2; i++)
        #pragma unroll
        for (int j = 0; j < 2; j++) wmma::fill_fragment(cf[i][j], 0.0f);

    float4 av[AI];
    uint4 bv[BI];
    auto load_tiles = [&](int k0) {
        #pragma unroll
        for (int i = 0; i < AI; i++) {
            int idx = tid + i * 128;
            av[i] = *(const float4*)&A[(size_t)(bm + (idx >> 3)) * lda + k0 + (idx & 7) * 4];
        }
        #pragma unroll
        for (int i = 0; i < BI; i++) {
            int idx = tid + i * 128;          // [0, 256): row = idx/8, c8 = idx%8
            bv[i] = *(const uint4*)&B[(size_t)(k0 + (idx >> 3)) * ldb + bn + (idx & 7) * 8];
        }
    };
    auto store_smem = [&](int st) {
        #pragma unroll
        for (int i = 0; i < AI; i++) {
            int idx = tid + i * 128;
            __nv_bfloat162 lo = __floats2bfloat162_rn(av[i].x, av[i].y);
            __nv_bfloat162 hi = __floats2bfloat162_rn(av[i].z, av[i].w);
            uint2 raw;
            raw.x = *reinterpret_cast<unsigned*>(&lo);
            raw.y = *reinterpret_cast<unsigned*>(&hi);
            *(uint2*)&As[st][(idx >> 3) * SAS + (idx & 7) * 4] = raw;
        }
        #pragma unroll
        for (int i = 0; i < BI; i++) {
            int idx = tid + i * 128;
            *(uint4*)&Bs[st][(idx >> 3) * SBS + (idx & 7) * 8] = bv[i];
        }
    };

    int cur = 0;
    load_tiles(0);
    store_smem(0);
    __syncthreads();
    for (int k0 = 0; k0 < KK; k0 += 32) {
        bool more = (k0 + 32 < KK);
        if (more) load_tiles(k0 + 32);
        #pragma unroll
        for (int kk = 0; kk < 2; kk++) {
            wmma::fragment<wmma::matrix_a, 16, 16, 16, __nv_bfloat16, wmma::row_major> af[2];
            wmma::fragment<wmma::matrix_b, 16, 16, 16, __nv_bfloat16, wmma::row_major> bf[2];
            #pragma unroll
            for (int i = 0; i < 2; i++)
                wmma::load_matrix_sync(af[i], &As[cur][(warp_m + i * 16) * SAS + kk * 16], SAS);
            #pragma unroll
            for (int j = 0; j < 2; j++)
                wmma::load_matrix_sync(bf[j], &Bs[cur][(kk * 16) * SBS + warp_n + j * 16], SBS);
            #pragma unroll
            for (int i = 0; i < 2; i++)
                #pragma unroll
                for (int j = 0; j < 2; j++)
                    wmma::mma_sync(cf[i][j], af[i], bf[j], cf[i][j]);
        }
        if (more) {
            store_smem(1 - cur);
            __syncthreads();
            cur ^= 1;
        }
    }

    if (MODE == 5) {
        #pragma unroll
        for (int i = 0; i < 2; i++)
            #pragma unroll
            for (int j = 0; j < 2; j++) {
                int row0 = bm + warp_m + i * 16;
                int col0 = bn + warp_n + j * 16;
                wmma::store_matrix_sync(&C[(size_t)row0 * ldc + col0], cf[i][j], ldc,
                                        wmma::mem_row_major);
            }
        return;
    }

    __syncthreads();
    #pragma unroll
    for (int i = 0; i < 2; i++) {
        #pragma unroll
        for (int j = 0; j < 2; j++) {
            wmma::store_matrix_sync(scr[wid], cf[i][j], 16, wmma::mem_row_major);
            __syncwarp();
            int row0 = bm + warp_m + i * 16;
            int col0 = bn + warp_n + j * 16;
            #pragma unroll
            for (int e = 0; e < 8; e++) {
                int idx = lane + e * 32;
                int r = row0 + (idx >> 4);
                int c = col0 + (idx & 15);
                float acc = scr[wid][idx];
                float bvv = (MODE == 4) ? 0.0f : bias[c];
                size_t o = (size_t)r * ldc + c;
                float u = 0.f;
                if (MODE == 4) u = aux1[o];
                float v = epilogue<(MODE == 6 ? 0 : MODE)>(acc, bvv, u, 0.f);
                C[o] = v;
                if (MODE == 6 && c >= 1024 && c < 3072)
                    g_kvh[(size_t)r * 2048 + (c - 1024)] = __float2bfloat16_rn(v);
            }
            __syncwarp();
        }
    }
}

// ---------------- LayerNorm ----------------
__global__ void ln_kernel(const float* __restrict__ x, const float* __restrict__ g,
                          const float* __restrict__ b, float* __restrict__ out) {
    int row = blockIdx.x, t = threadIdx.x;
    float v = x[row * DIMC + t];
    __shared__ float red[4];
    float s = warp_sum(v);
    if ((t & 31) == 0) red[t >> 5] = s;
    __syncthreads();
    float mean = (red[0] + red[1] + red[2] + red[3]) * (1.0f / 128.0f);
    float d = v - mean;
    float s2 = warp_sum(d * d);
    __syncthreads();
    if ((t & 31) == 0) red[t >> 5] = s2;
    __syncthreads();
    float var = (red[0] + red[1] + red[2] + red[3]) * (1.0f / 128.0f);
    out[row * DIMC + t] = d * rsqrtf(var + 1e-5f) * g[t] + b[t];
}

// ---------------- dense MHA via TF32 wmma (flash-style, no-max softmax) ----------------
#define ABK 64
#define APS 68
__global__ void __launch_bounds__(256)
attn_wmma_kernel(const float* __restrict__ qkv, float* __restrict__ attn) {
    __shared__ float Ks[ABK * 16];
    __shared__ float Vs[ABK * 16];
    __shared__ float Ps[8 * 16 * APS];
    __shared__ float dens[128];
    const int tid  = threadIdx.x;
    const int wid  = tid >> 5;
    const int lane = tid & 31;
    const int h  = blockIdx.y;
    const int q0 = blockIdx.x * 128;
    float* Pw = &Ps[wid * 16 * APS];

    #pragma unroll
    for (int i = 0; i < 2; i++) {
        int idx = tid + i * 256;
        int r = idx >> 2, d4 = (idx & 3) * 4;
        float4 q4 = *(const float4*)&qkv[(size_t)(q0 + r) * 384 + h * 16 + d4];
        Ps[r * 16 + d4 + 0] = q4.x * 0.25f;
        Ps[r * 16 + d4 + 1] = q4.y * 0.25f;
        Ps[r * 16 + d4 + 2] = q4.z * 0.25f;
        Ps[r * 16 + d4 + 3] = q4.w * 0.25f;
    }
    __syncthreads();
    wmma::fragment<wmma::matrix_a, 16, 16, 8, wmma::precision::tf32, wmma::row_major> af[2];
    #pragma unroll
    for (int k0 = 0; k0 < 2; k0++)
        wmma::load_matrix_sync(af[k0], &Ps[(wid * 16) * 16 + k0 * 8], 16);
    __syncthreads();

    wmma::fragment<wmma::accumulator, 16, 16, 8, float> oacc;
    wmma::fill_fragment(oacc, 0.0f);
    float dh0 = 0.0f, dh1 = 0.0f;

    const int key = tid >> 2, d4 = (tid & 3) * 4;
    float4 k4 = *(const float4*)&qkv[(size_t)key * 384 + 128 + h * 16 + d4];
    float4 v4 = *(const float4*)&qkv[(size_t)key * 384 + 256 + h * 16 + d4];

    for (int kt = 0; kt < NN; kt += ABK) {
        __syncthreads();
        *(float4*)&Ks[key * 16 + d4] = k4;
        *(float4*)&Vs[key * 16 + d4] = v4;
        __syncthreads();
        if (kt + ABK < NN) {
            const float* kp = &qkv[(size_t)(kt + ABK + key) * 384 + 128 + h * 16 + d4];
            k4 = *(const float4*)kp;
            v4 = *(const float4*)(kp + 128);
        }

        wmma::fragment<wmma::accumulator, 16, 16, 8, float> sacc[4];
        #pragma unroll
        for (int nt = 0; nt < 4; nt++) wmma::fill_fragment(sacc[nt], 0.0f);
        #pragma unroll
        for (int k0 = 0; k0 < 2; k0++) {
            #pragma unroll
            for (int nt = 0; nt < 4; nt++) {
                wmma::fragment<wmma::matrix_b, 16, 16, 8, wmma::precision::tf32, wmma::col_major> bf;
                wmma::load_matrix_sync(bf, &Ks[(nt * 16) * 16 + k0 * 8], 16);
                wmma::mma_sync(sacc[nt], af[k0], bf, sacc[nt]);
            }
        }
        #pragma unroll
        for (int nt = 0; nt < 4; nt++) {
            #pragma unroll
            for (int t = 0; t < sacc[nt].num_elements; t++)
                sacc[nt].x[t] = __expf(sacc[nt].x[t]);
            dh0 += (sacc[nt].x[0] + sacc[nt].x[1]) + (sacc[nt].x[4] + sacc[nt].x[5]);
            dh1 += (sacc[nt].x[2] + sacc[nt].x[3]) + (sacc[nt].x[6] + sacc[nt].x[7]);
            wmma::store_matrix_sync(&Pw[nt * 16], sacc[nt], APS, wmma::mem_row_major);
        }
        __syncwarp();
        #pragma unroll
        for (int k0 = 0; k0 < 8; k0++) {
            wmma::fragment<wmma::matrix_a, 16, 16, 8, wmma::precision::tf32, wmma::row_major> pa;
            wmma::fragment<wmma::matrix_b, 16, 16, 8, wmma::precision::tf32, wmma::row_major> vb;
            wmma::load_matrix_sync(pa, &Pw[k0 * 8], APS);
            wmma::load_matrix_sync(vb, &Vs[(k0 * 8) * 16], 16);
            wmma::mma_sync(oacc, pa, vb, oacc);
        }
        __syncwarp();
    }

    dh0 += __shfl_xor_sync(0xffffffffu, dh0, 1);
    dh0 += __shfl_xor_sync(0xffffffffu, dh0, 2);
    dh1 += __shfl_xor_sync(0xffffffffu, dh1, 1);
    dh1 += __shfl_xor_sync(0xffffffffu, dh1, 2);
    if ((lane & 3) == 0) {
        dens[wid * 16 + (lane >> 2)]     = dh0;
        dens[wid * 16 + 8 + (lane >> 2)] = dh1;
    }
    __syncwarp();
    wmma::store_matrix_sync(Pw, oacc, APS, wmma::mem_row_major);
    __syncwarp();
    #pragma unroll
    for (int e = 0; e < 8; e++) {
        int idx = lane + e * 32;
        int r = idx >> 4, c = idx & 15;
        float v = Pw[r * APS + c] / dens[wid * 16 + r];
        attn[(size_t)(q0 + wid * 16 + r) * DIMC + h * 16 + c] = v;
    }
}

// ---------------- packT (bf16) via tiled transpose ----------------
__global__ void packT_kernel(const float* __restrict__ w_edge) {
    __shared__ float tile[32][33];
    int h  = blockIdx.z;
    int k0 = blockIdx.x * 32;
    int j0 = blockIdx.y * 32;
    int tx = threadIdx.x, ty0 = threadIdx.y;
    #pragma unroll
    for (int i = 0; i < 4; i++) {
        int j = j0 + ty0 + i * 8;
        tile[ty0 + i * 8][tx] = w_edge[(size_t)j * HGC + h * 128 + k0 + tx];
    }
    __syncthreads();
    #pragma unroll
    for (int i = 0; i < 4; i++) {
        int k = k0 + ty0 + i * 8;
        g_packTh[h * 16384 + k * 128 + j0 + tx] = __float2bfloat16_rn(tile[tx][ty0 + i * 8]);
    }
}

// ---------------- pack [wq|wk|wv|wskip] bf16 + biases + packC bf16; zero g_deg ----------------
__global__ void packw_kernel(const float* __restrict__ wq, const float* __restrict__ wk,
                             const float* __restrict__ wv, const float* __restrict__ wsk,
                             const float* __restrict__ bq, const float* __restrict__ bk,
                             const float* __restrict__ bv, const float* __restrict__ bsk,
                             const float* __restrict__ w_edge) {
    for (int idx = blockIdx.x * blockDim.x + threadIdx.x; idx < DIMC * NPROJ;
         idx += gridDim.x * blockDim.x) {
        int k = idx / NPROJ, j = idx % NPROJ;
        float v;
        if (j < 1024)      v = wq[k * 1024 + j];
        else if (j < 2048) v = wk[k * 1024 + j - 1024];
        else if (j < 3072) v = wv[k * 1024 + j - 2048];
        else               v = wsk[k * 128 + j - 3072];
        g_packWh[idx] = __float2bfloat16_rn(v);
        if (idx < HEADSC * 128 * 128) {
            int jj = idx & 127;
            int kk = (idx >> 7) & 127;
            int hh = idx >> 14;
            g_packCh[idx] = __float2bfloat16_rn(w_edge[(size_t)kk * HGC + hh * 128 + jj]);
        }
        if (idx < NPROJ) {
            float bvv;
            if (idx < 1024)      bvv = bq[idx];
            else if (idx < 2048) bvv = bk[idx - 1024];
            else if (idx < 3072) bvv = bv[idx - 2048];
            else                 bvv = bsk[idx - 3072];
            g_packB[idx] = bvv;
        }
        if (idx < NN) g_deg[idx] = 0;
    }
}

// ---------------- CSR build ----------------
__global__ void hist_kernel(const int* __restrict__ ei) {
    const int* dst = ei + EC;
    for (int e = blockIdx.x * blockDim.x + threadIdx.x; e < EC; e += gridDim.x * blockDim.x)
        atomicAdd(&g_deg[dst[e]], 1);
}
__global__ void scan_kernel() {
    int t = threadIdx.x;
    int lane = t & 31, w = t >> 5;
    int base = t * 4;
    int d0 = g_deg[base], d1 = g_deg[base+1], d2 = g_deg[base+2], d3 = g_deg[base+3];
    int tot = d0 + d1 + d2 + d3;
    int v = tot;
    #pragma unroll
    for (int o = 1; o < 32; o <<= 1) {
        int u = __shfl_up_sync(0xffffffffu, v, o);
        if (lane >= o) v += u;
    }
    __shared__ int wsum[32];
    if (lane == 31) wsum[w] = v;
    __syncthreads();
    if (t < 32) {
        int wv = wsum[t];
        #pragma unroll
        for (int o = 1; o < 32; o <<= 1) {
            int u = __shfl_up_sync(0xffffffffu, wv, o);
            if (t >= o) wv += u;
        }
        wsum[t] = wv;
    }
    __syncthreads();
    int incl = v + (w ? wsum[w - 1] : 0);
    int run = incl - tot;
    g_off[base] = run;   g_cur[base] = run;     run += d0;
    g_off[base+1] = run; g_cur[base+1] = run;   run += d1;
    g_off[base+2] = run; g_cur[base+2] = run;   run += d2;
    g_off[base+3] = run; g_cur[base+3] = run;   run += d3;
    if (t == 1023) g_off[NN] = incl;
}
__global__ void scatter_kernel(const int* __restrict__ ei) {
    const int* dst = ei + EC;
    for (int e = blockIdx.x * blockDim.x + threadIdx.x; e < EC; e += gridDim.x * blockDim.x) {
        int p = atomicAdd(&g_cur[dst[e]], 1);
        g_eid[p] = e;
    }
}

// ---------------- graph aggregation: smem edge staging, bf16 kg/vg gathers ----------------
__global__ void graph_agg3_kernel(const int* __restrict__ ei,
                                  const float* __restrict__ edge_attr,
                                  const float* __restrict__ b_edge,
                                  const float* __restrict__ qkvg) {
    int n = blockIdx.x;
    int tid = threadIdx.x;
    int h = tid >> 5;
    int lane = tid & 31;
    const int* src = ei;
    const float invsq = 0.08838834764831845f;  // 1/sqrt(128)
    const int hoff = h * 128 + lane * 4;
    float4 qh = *(const float4*)&qkvg[(size_t)n * NPROJ + hoff];
    qh.x *= invsq; qh.y *= invsq; qh.z *= invsq; qh.w *= invsq;
    float4 th = *(const float4*)&g_t[n * HGC + hoff];
    th.x *= invsq; th.y *= invsq; th.z *= invsq; th.w *= invsq;
    float4 be4 = *(const float4*)&b_edge[hoff];
    float s0s = warp_sum(qh.x*be4.x + qh.y*be4.y + qh.z*be4.z + qh.w*be4.w);

    __shared__ float ea_s[8][132];
    __shared__ int src_s[8];
    float4 cacc = {0.f, 0.f, 0.f, 0.f};
    float4 vacc = {0.f, 0.f, 0.f, 0.f};
    float den = 0.0f;
    int beg = g_off[n], end = g_off[n + 1];

    for (int i0 = beg; i0 < end; i0 += 8) {
        int cnt = min(8, end - i0);
        __syncthreads();
        if (h < cnt) {
            int e = g_eid[i0 + h];
            if (lane == 0) src_s[h] = src[e];
            *(float4*)&ea_s[h][lane * 4] = *(const float4*)&edge_attr[(size_t)e * DIMC + lane * 4];
        }
        __syncthreads();
        int j = 0;
        for (; j + 3 < cnt; j += 4) {
            int sa = src_s[j], sb = src_s[j+1], sc = src_s[j+2], sd = src_s[j+3];
            float4 ea0 = *(const float4*)&ea_s[j  ][lane * 4];
            float4 ea1 = *(const float4*)&ea_s[j+1][lane * 4];
            float4 ea2 = *(const float4*)&ea_s[j+2][lane * 4];
            float4 ea3 = *(const float4*)&ea_s[j+3][lane * 4];
            float4 ka = ldkv(&g_kvh[(size_t)sa * 2048 + hoff]);
            float4 kb = ldkv(&g_kvh[(size_t)sb * 2048 + hoff]);
            float4 kc = ldkv(&g_kvh[(size_t)sc * 2048 + hoff]);
            float4 kd = ldkv(&g_kvh[(size_t)sd * 2048 + hoff]);
            float4 va = ldkv(&g_kvh[(size_t)sa * 2048 + 1024 + hoff]);
            float4 vb = ldkv(&g_kvh[(size_t)sb * 2048 + 1024 + hoff]);
            float4 vc = ldkv(&g_kvh[(size_t)sc * 2048 + 1024 + hoff]);
            float4 vd = ldkv(&g_kvh[(size_t)sd * 2048 + 1024 + hoff]);
            float t0 = qh.x*ka.x + qh.y*ka.y + qh.z*ka.z + qh.w*ka.w;
            t0 = fmaf(th.x, ea0.x, t0); t0 = fmaf(th.y, ea0.y, t0);
            t0 = fmaf(th.z, ea0.z, t0); t0 = fmaf(th.w, ea0.w, t0);
            float t1 = qh.x*kb.x + qh.y*kb.y + qh.z*kb.z + qh.w*kb.w;
            t1 = fmaf(th.x, ea1.x, t1); t1 = fmaf(th.y, ea1.y, t1);
            t1 = fmaf(th.z, ea1.z, t1); t1 = fmaf(th.w, ea1.w, t1);
            float t2 = qh.x*kc.x + qh.y*kc.y + qh.z*kc.z + qh.w*kc.w;
            t2 = fmaf(th.x, ea2.x, t2); t2 = fmaf(th.y, ea2.y, t2);
            t2 = fmaf(th.z, ea2.z, t2); t2 = fmaf(th.w, ea2.w, t2);
            float t3 = qh.x*kd.x + qh.y*kd.y + qh.z*kd.z + qh.w*kd.w;
            t3 = fmaf(th.x, ea3.x, t3); t3 = fmaf(th.y, ea3.y, t3);
            t3 = fmaf(th.z, ea3.z, t3); t3 = fmaf(th.w, ea3.w, t3);
            warp_sum4(t0, t1, t2, t3);
            float p0 = expf(t0 + s0s), p1 = expf(t1 + s0s);
            float p2 = expf(t2 + s0s), p3 = expf(t3 + s0s);
            den += (p0 + p1) + (p2 + p3);
            cacc.x = fmaf(p0, ea0.x, fmaf(p1, ea1.x, fmaf(p2, ea2.x, fmaf(p3, ea3.x, cacc.x))));
            cacc.y = fmaf(p0, ea0.y, fmaf(p1, ea1.y, fmaf(p2, ea2.y, fmaf(p3, ea3.y, cacc.y))));
            cacc.z = fmaf(p0, ea0.z, fmaf(p1, ea1.z, fmaf(p2, ea2.z, fmaf(p3, ea3.z, cacc.z))));
            cacc.w = fmaf(p0, ea0.w, fmaf(p1, ea1.w, fmaf(p2, ea2.w, fmaf(p3, ea3.w, cacc.w))));
            vacc.x = fmaf(p0, va.x, fmaf(p1, vb.x, fmaf(p2, vc.x, fmaf(p3, vd.x, vacc.x))));
            vacc.y = fmaf(p0, va.y, fmaf(p1, vb.y, fmaf(p2, vc.y, fmaf(p3, vd.y, vacc.y))));
            vacc.z = fmaf(p0, va.z, fmaf(p1, vb.z, fmaf(p2, vc.z, fmaf(p3, vd.z, vacc.z))));
            vacc.w = fmaf(p0, va.w, fmaf(p1, vb.w, fmaf(p2, vc.w, fmaf(p3, vd.w, vacc.w))));
        }
        for (; j < cnt; j++) {
            int s = src_s[j];
            float4 ea = *(const float4*)&ea_s[j][lane * 4];
            float4 k4 = ldkv(&g_kvh[(size_t)s * 2048 + hoff]);
            float4 v4 = ldkv(&g_kvh[(size_t)s * 2048 + 1024 + hoff]);
            float t = qh.x*k4.x + qh.y*k4.y + qh.z*k4.z + qh.w*k4.w;
            t = fmaf(th.x, ea.x, t); t = fmaf(th.y, ea.y, t);
            t = fmaf(th.z, ea.z, t); t = fmaf(th.w, ea.w, t);
            t = warp_sum(t) + s0s;
            float p = expf(t);
            den += p;
            cacc.x = fmaf(p, ea.x, cacc.x); cacc.y = fmaf(p, ea.y, cacc.y);
            cacc.z = fmaf(p, ea.z, cacc.z); cacc.w = fmaf(p, ea.w, cacc.w);
            vacc.x = fmaf(p, v4.x, vacc.x); vacc.y = fmaf(p, v4.y, vacc.y);
            vacc.z = fmaf(p, v4.z, vacc.z); vacc.w = fmaf(p, v4.w, vacc.w);
        }
    }
    bool nonempty = (end > beg);
    float invden = nonempty ? 1.0f / den : 0.0f;
    float4 c4 = {cacc.x*invden, cacc.y*invden, cacc.z*invden, cacc.w*invden};
    *(float4*)&g_cnorm[n * HGC + hoff] = c4;

    __shared__ float sh[8][128];
    float gate = nonempty ? 1.0f : 0.0f;
    __syncthreads();
    sh[h][lane*4+0] = fmaf(vacc.x, invden, be4.x * gate);
    sh[h][lane*4+1] = fmaf(vacc.y, invden, be4.y * gate);
    sh[h][lane*4+2] = fmaf(vacc.z, invden, be4.z * gate);
    sh[h][lane*4+3] = fmaf(vacc.w, invden, be4.w * gate);
    __syncthreads();
    if (tid < 128) {
        int d = tid;
        float sum = 0.0f;
        #pragma unroll
        for (int hh = 0; hh < 8; hh++) sum += sh[hh][d];
        g_vsum[n * DIMC + d] = sum;
    }
}

// ---------------- fused beta gate + combine + LN3 ----------------
__global__ void beta_ln_kernel(const float* __restrict__ wb,
                               const float* __restrict__ g3, const float* __restrict__ b3,
                               const float* __restrict__ qkvg) {
    int n = blockIdx.x, t = threadIdx.x;
    float o = g_aggout[n * DIMC + t] * 0.125f;
    float xr = qkvg[(size_t)n * NPROJ + 3072 + t];
    float part = o * (wb[t] + wb[256 + t]) + xr * (wb[128 + t] - wb[256 + t]);
    __shared__ float red[4];
    float s = warp_sum(part);
    if ((t & 31) == 0) red[t >> 5] = s;
    __syncthreads();
    float z = red[0] + red[1] + red[2] + red[3];
    float beta = 1.0f / (1.0f + expf(-z));
    float x2 = g_x1[n * DIMC + t] + beta * xr + (1.0f - beta) * o;
    g_x2[n * DIMC + t] = x2;
    __syncthreads();
    float sm = warp_sum(x2);
    if ((t & 31) == 0) red[t >> 5] = sm;
    __syncthreads();
    float mean = (red[0] + red[1] + red[2] + red[3]) * (1.0f / 128.0f);
    float d = x2 - mean;
    float s2 = warp_sum(d * d);
    __syncthreads();
    if ((t & 31) == 0) red[t >> 5] = s2;
    __syncthreads();
    float var = (red[0] + red[1] + red[2] + red[3]) * (1.0f / 128.0f);
    g_xn3[n * DIMC + t] = d * rsqrtf(var + 1e-5f) * g3[t] + b3[t];
}

// tile configs
#define WG_SMALL(MODE, KF)        wgemm<64,64,2,2,2,2,MODE,false,KF>
#define WG_NARROW(MODE, KF)       wgemm<64,32,2,2,2,1,MODE,false,KF>
#define WG_NARROW_DUAL(MODE, KF)  wgemm<64,32,2,2,2,1,MODE,true,KF>

// ---------------- launch ----------------
extern "C" void kernel_launch(void* const* d_in, const int* in_sizes, int n_in,
                              void* d_out, int out_size) {
    const float* x      = (const float*)d_in[0];
    const int*   ei     = (const int*)d_in[1];
    const float* eattr  = (const float*)d_in[2];
    const float* n1g = (const float*)d_in[3];  const float* n1b = (const float*)d_in[4];
    const float* n2g = (const float*)d_in[5];  const float* n2b = (const float*)d_in[6];
    const float* n3g = (const float*)d_in[7];  const float* n3b = (const float*)d_in[8];
    const float* w_qkv = (const float*)d_in[9];  const float* b_qkv = (const float*)d_in[10];
    const float* w_o   = (const float*)d_in[11]; const float* b_o   = (const float*)d_in[12];
    const float* w_query = (const float*)d_in[13]; const float* b_query = (const float*)d_in[14];
    const float* w_key   = (const float*)d_in[15]; const float* b_key   = (const float*)d_in[16];
    const float* w_value = (const float*)d_in[17]; const float* b_value = (const float*)d_in[18];
    const float* w_edge  = (const float*)d_in[19]; const float* b_edge  = (const float*)d_in[20];
    const float* w_skip  = (const float*)d_in[21]; const float* b_skip  = (const float*)d_in[22];
    const float* w_beta  = (const float*)d_in[23];
    const float* w_f1 = (const float*)d_in[24]; const float* b_f1 = (const float*)d_in[25];
    const float* w_f2 = (const float*)d_in[26]; const float* b_f2 = (const float*)d_in[27];
    const float* w_dyn = (const float*)d_in[28]; const float* b_dyn = (const float*)d_in[29];
    float* out = (float*)d_out;

    float *xn, *qkvb, *attnb, *x1, *xn2, *qkvg, *tb, *packB;
    float *cnorm, *vsum, *aggo, *xn3, *ffnb, *x3, *x2p;
    __nv_bfloat16 *packTh, *packCh, *packWh;
    cudaGetSymbolAddress((void**)&xn,     g_xn);
    cudaGetSymbolAddress((void**)&qkvb,   g_qkv);
    cudaGetSymbolAddress((void**)&attnb,  g_attn);
    cudaGetSymbolAddress((void**)&x1,     g_x1);
    cudaGetSymbolAddress((void**)&xn2,    g_xn2);
    cudaGetSymbolAddress((void**)&qkvg,   g_qkvg);
    cudaGetSymbolAddress((void**)&tb,     g_t);
    cudaGetSymbolAddress((void**)&packTh, g_packTh);
    cudaGetSymbolAddress((void**)&packCh, g_packCh);
    cudaGetSymbolAddress((void**)&packWh, g_packWh);
    cudaGetSymbolAddress((void**)&packB,  g_packB);
    cudaGetSymbolAddress((void**)&cnorm,  g_cnorm);
    cudaGetSymbolAddress((void**)&vsum,   g_vsum);
    cudaGetSymbolAddress((void**)&aggo,   g_aggout);
    cudaGetSymbolAddress((void**)&xn3,    g_xn3);
    cudaGetSymbolAddress((void**)&ffnb,   g_ffn);
    cudaGetSymbolAddress((void**)&x3,     g_x3);
    cudaGetSymbolAddress((void**)&x2p,    g_x2);
    float* qg = qkvg;

    // side stream for weight packing + CSR build
    static cudaStream_t s2 = nullptr;
    static cudaEvent_t evF = nullptr, evJ = nullptr;
    if (!s2) {
        cudaStreamCreateWithFlags(&s2, cudaStreamNonBlocking);
        cudaEventCreateWithFlags(&evF, cudaEventDisableTiming);
        cudaEventCreateWithFlags(&evJ, cudaEventDisableTiming);
    }
    cudaEventRecord(evF, 0);
    cudaStreamWaitEvent(s2, evF, 0);

    // ---- stream s2: packT, packw(+deg zero), hist, scan, scatter ----
    packT_kernel<<<dim3(4, 4, 8), dim3(32, 8), 0, s2>>>(w_edge);
    packw_kernel<<<512, 256, 0, s2>>>(w_query, w_key, w_value, w_skip,
                                      b_query, b_key, b_value, b_skip, w_edge);
    hist_kernel<<<256, 256, 0, s2>>>(ei);
    scan_kernel<<<1, 1024, 0, s2>>>();
    scatter_kernel<<<256, 256, 0, s2>>>(ei);
    cudaEventRecord(evJ, s2);

    // ---- main stream: LN1 -> QKV -> attention -> out-proj -> LN2 ----
    ln_kernel<<<NN, 128>>>(x, n1g, n1b, xn);
    WG_SMALL(0, 128)<<<dim3(6, 64, 1), 128>>>(xn, w_qkv, b_qkv, qkvb, 128, 128, 384, 384,
                                              0, 0, 0, 0, nullptr, nullptr, nullptr);
    attn_wmma_kernel<<<dim3(NN/128, HEADSC), 256>>>(qkvb, attnb);
    WG_NARROW(2, 128)<<<dim3(4, 64, 1), 128>>>(attnb, w_o, b_o, x1, 128, 128, 128, 128,
                                               0, 0, 0, 0, x, nullptr, nullptr);
    ln_kernel<<<NN, 128>>>(x1, n2g, n2b, xn2);

    cudaStreamWaitEvent(0, evJ, 0);

    // merged projections q|k|v|skip (bf16 mma; MODE 6 also writes g_kvh for kg|vg cols)
    hgemm<6, 128><<<dim3(NPROJ/64, 64, 1), 128>>>(xn2, packWh, packB, qkvg,
                                                  128, 128, NPROJ, NPROJ, 0, 0, 0, nullptr);
    // batched t-GEMM (bf16, 8x [4096x128, K=128], direct store)
    hgemm<5, 128><<<dim3(2, 64, 8), 128>>>(qg, packTh, nullptr, tb,
                                           128, NPROJ, 128, HGC, 128, 128*128, 128, nullptr);
    // eg-free segment-softmax aggregation (bf16 gathers)
    graph_agg3_kernel<<<NN, 256>>>(ei, eattr, b_edge, qkvg);
    // c-GEMM (bf16): aggout = cnorm @ packC + vsum
    hgemm<4, 0><<<dim3(2, 64, 1), 128>>>(cnorm, packCh, nullptr, aggo,
                                         HGC, HGC, 128, 128, 0, 0, 0, vsum);
    // fused beta gate + combine + LN3
    beta_ln_kernel<<<NN, 128>>>(w_beta, n3g, n3b, qkvg);
    // FFN up + GELU (tf32)
    WG_SMALL(1, 128)<<<dim3(32, 64, 1), 128>>>(xn3, w_f1, b_f1, ffnb, 128, 128, FFNC, FFNC,
                                               0, 0, 0, 0, nullptr, nullptr, nullptr);
    // FFN down + residual (tf32)
    WG_NARROW(2, 0)<<<dim3(4, 64, 1), 128>>>(ffnb, w_f2, b_f2, x3, FFNC, FFNC, 128, 128,
                                             0, 0, 0, 0, x2p, nullptr, nullptr);
    // dyn gate (tf32, dual-A = [x3 | x])
    WG_NARROW_DUAL(3, 256)<<<dim3(4, 64, 1), 128>>>(x3, w_dyn, b_dyn, out, 256, 128, 128, 128,
                                                    0, 0, 0, 0, x3, x, x);
}

// round 17
// speedup vs baseline: 1.6183x; 1.3613x over previous
#include <cuda_runtime.h>
#include <cuda_bf16.h>
#include <mma.h>
#include <math.h>

using namespace nvcuda;

#define NN   4096
#define DIMC 128
#define HEADSC 8
#define HGC  1024      // HEADS * GC
#define EC   65536
#define FFNC 2048
#define NPROJ 3200     // 3*1024 + 128 (q|k|v|skip)

// ---------------- scratch (device globals; no allocation allowed) ----------------
__device__ float g_xn[NN*DIMC];
__device__ float g_qkv[NN*3*DIMC];
__device__ float g_attn[NN*DIMC];
__device__ float g_x1[NN*DIMC];
__device__ float g_xn2[NN*DIMC];
__device__ float g_qkvg[(size_t)NN*NPROJ];   // per row: qg|kg|vg|xr
__device__ float g_t[NN*HGC];                // per-head W_h @ qg
__device__ __nv_bfloat16 g_kvh[(size_t)NN*2048];  // bf16 copy: kg|vg per row
__device__ __nv_bfloat16 g_packTh[HEADSC*128*128];
__device__ __nv_bfloat16 g_packCh[HEADSC*128*128];
__device__ __nv_bfloat16 g_packWh[DIMC*NPROJ];    // [wq|wk|wv|wskip] bf16
__device__ __nv_bfloat16 g_packQh[DIMC*384];      // w_qkv bf16
__device__ float g_packB[NPROJ];
__device__ float g_cnorm[NN*HGC];
__device__ float g_vsum[NN*DIMC];
__device__ int   g_deg[NN];
__device__ int   g_off[NN+1];
__device__ int   g_cur[NN];
__device__ int   g_eid[EC];
__device__ float g_aggout[NN*DIMC];
__device__ float g_x2[NN*DIMC];
__device__ float g_xn3[NN*DIMC];
__device__ float g_ffn[NN*FFNC];
__device__ float g_x3[NN*DIMC];

// ---------------- helpers ----------------
__device__ __forceinline__ float warp_sum(float v) {
    #pragma unroll
    for (int o = 16; o > 0; o >>= 1) v += __shfl_xor_sync(0xffffffffu, v, o);
    return v;
}

__device__ __forceinline__ void warp_sum4(float& a, float& b, float& c, float& d) {
    #pragma unroll
    for (int o = 16; o > 0; o >>= 1) {
        a += __shfl_xor_sync(0xffffffffu, a, o);
        b += __shfl_xor_sync(0xffffffffu, b, o);
        c += __shfl_xor_sync(0xffffffffu, c, o);
        d += __shfl_xor_sync(0xffffffffu, d, o);
    }
}

__device__ __forceinline__ float4 ldkv(const __nv_bfloat16* p) {
    uint2 raw = *(const uint2*)p;
    __nv_bfloat162 a = *reinterpret_cast<__nv_bfloat162*>(&raw.x);
    __nv_bfloat162 b = *reinterpret_cast<__nv_bfloat162*>(&raw.y);
    float2 fa = __bfloat1622float2(a), fb = __bfloat1622float2(b);
    return make_float4(fa.x, fa.y, fb.x, fb.y);
}

// MODE: 0 = +bias, 1 = +bias->GELU, 2 = +bias+aux1, 3 = +bias->sigmoid gate(a1,a2),
//       4 = +aux1 (no bias), 5 = raw store, 6 = +bias & bf16 side-store (kg|vg)
template<int MODE>
__device__ __forceinline__ float epilogue(float acc, float bias, float a1, float a2) {
    float v = (MODE == 4 || MODE == 5) ? acc : (acc + bias);
    if (MODE == 1) {
        v = 0.5f * v * (1.0f + erff(v * 0.7071067811865476f));
    } else if (MODE == 2 || MODE == 4) {
        v = v + a1;
    } else if (MODE == 3) {
        float s = 1.0f / (1.0f + expf(-v));
        v = a1 * s + a2 * (1.0f - s);
    }
    return v;
}

// ---------------- TF32 tensor-core GEMM via wmma (m16n16k8) ----------------
template<int BM, int BN, int WARPS_M, int WARPS_N, int WM, int WN, int MODE, bool DUALA, int KFIX>
__global__ void __launch_bounds__(WARPS_M*WARPS_N*32)
wgemm(const float* __restrict__ A, const float* __restrict__ B,
      const float* __restrict__ bias, float* __restrict__ C,
      int K, int lda, int ldb, int ldc,
      long sA, long sB, long sC, long sBias,
      const float* __restrict__ aux1, const float* __restrict__ aux2,
      const float* __restrict__ A2) {
    constexpr int NT  = WARPS_M * WARPS_N * 32;
    constexpr int SAS = 36;
    constexpr int SBS = BN + 4;
    constexpr int AI  = (BM * 8) / NT;
    constexpr int BI  = (BN * 8) / NT;
    constexpr int WORDS = BM * SAS + 32 * SBS;
    constexpr int STAGES = (WORDS * 8 <= 48 * 1024) ? 2 : 1;
    __shared__ float As[STAGES][BM * SAS];
    __shared__ float Bs[STAGES][32 * SBS];
    const int tid  = threadIdx.x;
    const int wid  = tid >> 5;
    const int lane = tid & 31;
    const int bm = blockIdx.y * BM;
    const int bn = blockIdx.x * BN;
    A += (size_t)blockIdx.z * sA;
    B += (size_t)blockIdx.z * sB;
    C += (size_t)blockIdx.z * sC;
    if (MODE != 4 && MODE != 5) bias += (size_t)blockIdx.z * sBias;
    const int warp_m = (wid / WARPS_N) * (WM * 16);
    const int warp_n = (wid % WARPS_N) * (WN * 16);
    const int KK = KFIX ? KFIX : K;

    wmma::fragment<wmma::accumulator, 16, 16, 8, float> cf[WM][WN];
    #pragma unroll
    for (int i = 0; i < WM; i++)
        #pragma unroll
        for (int j = 0; j < WN; j++) wmma::fill_fragment(cf[i][j], 0.0f);

    float4 av[AI], bv[BI];
    auto load_tiles = [&](int k0) {
        #pragma unroll
        for (int i = 0; i < AI; i++) {
            int idx = tid + i * NT;
            int kk = k0 + (idx & 7) * 4;
            const float* src;
            if (DUALA && kk >= 128) src = &A2[(size_t)(bm + (idx >> 3)) * 128 + (kk - 128)];
            else                    src = &A[(size_t)(bm + (idx >> 3)) * lda + kk];
            av[i] = *(const float4*)src;
        }
        #pragma unroll
        for (int i = 0; i < BI; i++) {
            int idx = tid + i * NT;
            bv[i] = *(const float4*)&B[(size_t)(k0 + idx / (BN / 4)) * ldb + bn + (idx % (BN / 4)) * 4];
        }
    };
    auto store_smem = [&](int st) {
        #pragma unroll
        for (int i = 0; i < AI; i++) {
            int idx = tid + i * NT;
            *(float4*)&As[st][(idx >> 3) * SAS + (idx & 7) * 4] = av[i];
        }
        #pragma unroll
        for (int i = 0; i < BI; i++) {
            int idx = tid + i * NT;
            *(float4*)&Bs[st][(idx / (BN / 4)) * SBS + (idx % (BN / 4)) * 4] = bv[i];
        }
    };

    int cur = 0;
    load_tiles(0);
    store_smem(0);
    __syncthreads();
    for (int k0 = 0; k0 < KK; k0 += 32) {
        bool more = (k0 + 32 < KK);
        if (more) load_tiles(k0 + 32);
        #pragma unroll
        for (int kk = 0; kk < 4; kk++) {
            wmma::fragment<wmma::matrix_a, 16, 16, 8, wmma::precision::tf32, wmma::row_major> af[WM];
            wmma::fragment<wmma::matrix_b, 16, 16, 8, wmma::precision::tf32, wmma::row_major> bf[WN];
            #pragma unroll
            for (int i = 0; i < WM; i++)
                wmma::load_matrix_sync(af[i], &As[cur][(warp_m + i * 16) * SAS + kk * 8], SAS);
            #pragma unroll
            for (int j = 0; j < WN; j++)
                wmma::load_matrix_sync(bf[j], &Bs[cur][kk * 8 * SBS + warp_n + j * 16], SBS);
            #pragma unroll
            for (int i = 0; i < WM; i++)
                #pragma unroll
                for (int j = 0; j < WN; j++)
                    wmma::mma_sync(cf[i][j], af[i], bf[j], cf[i][j]);
        }
        if (more) {
            if (STAGES == 2) {
                store_smem(1 - cur);
                __syncthreads();
                cur ^= 1;
            } else {
                __syncthreads();
                store_smem(0);
                __syncthreads();
            }
        }
    }

    if (MODE == 5) {
        #pragma unroll
        for (int i = 0; i < WM; i++)
            #pragma unroll
            for (int j = 0; j < WN; j++) {
                int row0 = bm + warp_m + i * 16;
                int col0 = bn + warp_n + j * 16;
                wmma::store_matrix_sync(&C[(size_t)row0 * ldc + col0], cf[i][j], ldc,
                                        wmma::mem_row_major);
            }
        return;
    }

    __syncthreads();
    float* scratch = &As[0][wid * 256];
    #pragma unroll
    for (int i = 0; i < WM; i++) {
        #pragma unroll
        for (int j = 0; j < WN; j++) {
            wmma::store_matrix_sync(scratch, cf[i][j], 16, wmma::mem_row_major);
            __syncwarp();
            int row0 = bm + warp_m + i * 16;
            int col0 = bn + warp_n + j * 16;
            #pragma unroll
            for (int e = 0; e < 8; e++) {
                int idx = lane + e * 32;
                int r = row0 + (idx >> 4);
                int c = col0 + (idx & 15);
                float acc = scratch[idx];
                float bvv = (MODE == 4) ? 0.0f : bias[c];
                size_t o = (size_t)r * ldc + c;
                float u = 0.f, w = 0.f;
                if (MODE == 2 || MODE == 3 || MODE == 4) u = aux1[o];
                if (MODE == 3) w = aux2[o];
                C[o] = epilogue<MODE>(acc, bvv, u, w);
            }
            __syncwarp();
        }
    }
}

// ---------------- bf16 tensor-core GEMM (m16n16k16), 64x64 tile, 4 warps ----------------
template<int MODE, int KFIX>
__global__ void __launch_bounds__(128)
hgemm(const float* __restrict__ A, const __nv_bfloat16* __restrict__ B,
      const float* __restrict__ bias, float* __restrict__ C,
      int K, int lda, int ldb, int ldc,
      long sA, long sB, long sC,
      const float* __restrict__ aux1) {
    constexpr int BM = 64, BN = 64;
    constexpr int SAS = 40;
    constexpr int SBS = BN + 8;
    constexpr int AI  = (BM * 8) / 128;
    constexpr int BI  = (32 * BN / 8) / 128;
    __shared__ __nv_bfloat16 As[2][BM * SAS];
    __shared__ __nv_bfloat16 Bs[2][32 * SBS];
    __shared__ float scr[4][256];
    const int tid  = threadIdx.x;
    const int wid  = tid >> 5;
    const int lane = tid & 31;
    const int bm = blockIdx.y * BM;
    const int bn = blockIdx.x * BN;
    A += (size_t)blockIdx.z * sA;
    B += (size_t)blockIdx.z * sB;
    C += (size_t)blockIdx.z * sC;
    const int warp_m = (wid >> 1) * 32;
    const int warp_n = (wid & 1) * 32;
    const int KK = KFIX ? KFIX : K;

    wmma::fragment<wmma::accumulator, 16, 16, 16, float> cf[2][2];
    #pragma unroll
    for (int i = 0; i < 2; i++)
        #pragma unroll
        for (int j = 0; j < 2; j++) wmma::fill_fragment(cf[i][j], 0.0f);

    float4 av[AI];
    uint4 bv[BI];
    auto load_tiles = [&](int k0) {
        #pragma unroll
        for (int i = 0; i < AI; i++) {
            int idx = tid + i * 128;
            av[i] = *(const float4*)&A[(size_t)(bm + (idx >> 3)) * lda + k0 + (idx & 7) * 4];
        }
        #pragma unroll
        for (int i = 0; i < BI; i++) {
            int idx = tid + i * 128;
            bv[i] = *(const uint4*)&B[(size_t)(k0 + (idx >> 3)) * ldb + bn + (idx & 7) * 8];
        }
    };
    auto store_smem = [&](int st) {
        #pragma unroll
        for (int i = 0; i < AI; i++) {
            int idx = tid + i * 128;
            __nv_bfloat162 lo = __floats2bfloat162_rn(av[i].x, av[i].y);
            __nv_bfloat162 hi = __floats2bfloat162_rn(av[i].z, av[i].w);
            uint2 raw;
            raw.x = *reinterpret_cast<unsigned*>(&lo);
            raw.y = *reinterpret_cast<unsigned*>(&hi);
            *(uint2*)&As[st][(idx >> 3) * SAS + (idx & 7) * 4] = raw;
        }
        #pragma unroll
        for (int i = 0; i < BI; i++) {
            int idx = tid + i * 128;
            *(uint4*)&Bs[st][(idx >> 3) * SBS + (idx & 7) * 8] = bv[i];
        }
    };

    int cur = 0;
    load_tiles(0);
    store_smem(0);
    __syncthreads();
    for (int k0 = 0; k0 < KK; k0 += 32) {
        bool more = (k0 + 32 < KK);
        if (more) load_tiles(k0 + 32);
        #pragma unroll
        for (int kk = 0; kk < 2; kk++) {
            wmma::fragment<wmma::matrix_a, 16, 16, 16, __nv_bfloat16, wmma::row_major> af[2];
            wmma::fragment<wmma::matrix_b, 16, 16, 16, __nv_bfloat16, wmma::row_major> bf[2];
            #pragma unroll
            for (int i = 0; i < 2; i++)
                wmma::load_matrix_sync(af[i], &As[cur][(warp_m + i * 16) * SAS + kk * 16], SAS);
            #pragma unroll
            for (int j = 0; j < 2; j++)
                wmma::load_matrix_sync(bf[j], &Bs[cur][(kk * 16) * SBS + warp_n + j * 16], SBS);
            #pragma unroll
            for (int i = 0; i < 2; i++)
                #pragma unroll
                for (int j = 0; j < 2; j++)
                    wmma::mma_sync(cf[i][j], af[i], bf[j], cf[i][j]);
        }
        if (more) {
            store_smem(1 - cur);
            __syncthreads();
            cur ^= 1;
        }
    }

    if (MODE == 5) {
        #pragma unroll
        for (int i = 0; i < 2; i++)
            #pragma unroll
            for (int j = 0; j < 2; j++) {
                int row0 = bm + warp_m + i * 16;
                int col0 = bn + warp_n + j * 16;
                wmma::store_matrix_sync(&C[(size_t)row0 * ldc + col0], cf[i][j], ldc,
                                        wmma::mem_row_major);
            }
        return;
    }

    __syncthreads();
    #pragma unroll
    for (int i = 0; i < 2; i++) {
        #pragma unroll
        for (int j = 0; j < 2; j++) {
            wmma::store_matrix_sync(scr[wid], cf[i][j], 16, wmma::mem_row_major);
            __syncwarp();
            int row0 = bm + warp_m + i * 16;
            int col0 = bn + warp_n + j * 16;
            #pragma unroll
            for (int e = 0; e < 8; e++) {
                int idx = lane + e * 32;
                int r = row0 + (idx >> 4);
                int c = col0 + (idx & 15);
                float acc = scr[wid][idx];
                float bvv = (MODE == 4) ? 0.0f : bias[c];
                size_t o = (size_t)r * ldc + c;
                float u = 0.f;
                if (MODE == 4) u = aux1[o];
                float v = epilogue<(MODE == 6 ? 0 : MODE)>(acc, bvv, u, 0.f);
                C[o] = v;
                if (MODE == 6 && c >= 1024 && c < 3072)
                    g_kvh[(size_t)r * 2048 + (c - 1024)] = __float2bfloat16_rn(v);
            }
            __syncwarp();
        }
    }
}

// ---------------- LayerNorm ----------------
__global__ void ln_kernel(const float* __restrict__ x, const float* __restrict__ g,
                          const float* __restrict__ b, float* __restrict__ out) {
    int row = blockIdx.x, t = threadIdx.x;
    float v = x[row * DIMC + t];
    __shared__ float red[4];
    float s = warp_sum(v);
    if ((t & 31) == 0) red[t >> 5] = s;
    __syncthreads();
    float mean = (red[0] + red[1] + red[2] + red[3]) * (1.0f / 128.0f);
    float d = v - mean;
    float s2 = warp_sum(d * d);
    __syncthreads();
    if ((t & 31) == 0) red[t >> 5] = s2;
    __syncthreads();
    float var = (red[0] + red[1] + red[2] + red[3]) * (1.0f / 128.0f);
    out[row * DIMC + t] = d * rsqrtf(var + 1e-5f) * g[t] + b[t];
}

// ---------------- dense MHA via bf16 wmma (flash-style, no-max softmax) ----------------
// One m16n16k16 mma covers the full d=16 per 16-key subtile. P stored bf16 via
// the accumulator element map; output scaled in-register and stored directly.
#define ABK 64
#define QPS 72
__global__ void __launch_bounds__(256)
attn_bf16_kernel(const float* __restrict__ qkv, float* __restrict__ attn) {
    __shared__ __nv_bfloat16 Ks[ABK * 16];
    __shared__ __nv_bfloat16 Vs[ABK * 16];
    __shared__ __nv_bfloat16 Ps[8 * 16 * QPS];   // per-warp 16 x 64 P (also Q stage)
    const int tid  = threadIdx.x;
    const int wid  = tid >> 5;
    const int lane = tid & 31;
    const int g    = lane >> 2;
    const int tg   = lane & 3;
    const int h  = blockIdx.y;
    const int q0 = blockIdx.x * 128;
    __nv_bfloat16* Pw = &Ps[wid * 16 * QPS];

    // stage Q (scaled) as bf16 into Ps region: [row][16] ld=16
    #pragma unroll
    for (int i = 0; i < 2; i++) {
        int idx = tid + i * 256;
        int r = idx >> 2, d4 = (idx & 3) * 4;
        float4 q4 = *(const float4*)&qkv[(size_t)(q0 + r) * 384 + h * 16 + d4];
        __nv_bfloat162 lo = __floats2bfloat162_rn(q4.x * 0.25f, q4.y * 0.25f);
        __nv_bfloat162 hi = __floats2bfloat162_rn(q4.z * 0.25f, q4.w * 0.25f);
        uint2 raw;
        raw.x = *reinterpret_cast<unsigned*>(&lo);
        raw.y = *reinterpret_cast<unsigned*>(&hi);
        *(uint2*)&Ps[r * 16 + d4] = raw;
    }
    __syncthreads();
    wmma::fragment<wmma::matrix_a, 16, 16, 16, __nv_bfloat16, wmma::row_major> af;
    wmma::load_matrix_sync(af, &Ps[(wid * 16) * 16], 16);
    __syncthreads();   // Ps now free for P tiles

    wmma::fragment<wmma::accumulator, 16, 16, 16, float> oacc;
    wmma::fill_fragment(oacc, 0.0f);
    float dh0 = 0.0f, dh1 = 0.0f;

    const int key = tid >> 2, d4 = (tid & 3) * 4;
    float4 k4 = *(const float4*)&qkv[(size_t)key * 384 + 128 + h * 16 + d4];
    float4 v4 = *(const float4*)&qkv[(size_t)key * 384 + 256 + h * 16 + d4];

    for (int kt = 0; kt < NN; kt += ABK) {
        __syncthreads();
        {
            __nv_bfloat162 klo = __floats2bfloat162_rn(k4.x, k4.y);
            __nv_bfloat162 khi = __floats2bfloat162_rn(k4.z, k4.w);
            __nv_bfloat162 vlo = __floats2bfloat162_rn(v4.x, v4.y);
            __nv_bfloat162 vhi = __floats2bfloat162_rn(v4.z, v4.w);
            uint2 kr, vr;
            kr.x = *reinterpret_cast<unsigned*>(&klo);
            kr.y = *reinterpret_cast<unsigned*>(&khi);
            vr.x = *reinterpret_cast<unsigned*>(&vlo);
            vr.y = *reinterpret_cast<unsigned*>(&vhi);
            *(uint2*)&Ks[key * 16 + d4] = kr;
            *(uint2*)&Vs[key * 16 + d4] = vr;
        }
        __syncthreads();
        if (kt + ABK < NN) {
            const float* kp = &qkv[(size_t)(kt + ABK + key) * 384 + 128 + h * 16 + d4];
            k4 = *(const float4*)kp;
            v4 = *(const float4*)(kp + 128);
        }

        // S = Q x K^T : one k16 mma per 16-key subtile
        #pragma unroll
        for (int nt = 0; nt < 4; nt++) {
            wmma::fragment<wmma::accumulator, 16, 16, 16, float> sacc;
            wmma::fill_fragment(sacc, 0.0f);
            wmma::fragment<wmma::matrix_b, 16, 16, 16, __nv_bfloat16, wmma::col_major> bf;
            wmma::load_matrix_sync(bf, &Ks[(nt * 16) * 16], 16);
            wmma::mma_sync(sacc, af, bf, sacc);
            // exp + accumulate row denominators + write P (bf16) via element map
            float e0 = __expf(sacc.x[0]), e1 = __expf(sacc.x[1]);
            float e2 = __expf(sacc.x[2]), e3 = __expf(sacc.x[3]);
            float e4 = __expf(sacc.x[4]), e5 = __expf(sacc.x[5]);
            float e6 = __expf(sacc.x[6]), e7 = __expf(sacc.x[7]);
            dh0 += (e0 + e1) + (e4 + e5);
            dh1 += (e2 + e3) + (e6 + e7);
            int c0 = nt * 16 + 2 * tg;
            *(__nv_bfloat162*)&Pw[g * QPS + c0]           = __floats2bfloat162_rn(e0, e1);
            *(__nv_bfloat162*)&Pw[(g + 8) * QPS + c0]     = __floats2bfloat162_rn(e2, e3);
            *(__nv_bfloat162*)&Pw[g * QPS + c0 + 8]       = __floats2bfloat162_rn(e4, e5);
            *(__nv_bfloat162*)&Pw[(g + 8) * QPS + c0 + 8] = __floats2bfloat162_rn(e6, e7);
        }
        __syncwarp();
        // PV: oacc += P [16 x 64] x V [64 x 16]
        #pragma unroll
        for (int k0 = 0; k0 < 4; k0++) {
            wmma::fragment<wmma::matrix_a, 16, 16, 16, __nv_bfloat16, wmma::row_major> pa;
            wmma::fragment<wmma::matrix_b, 16, 16, 16, __nv_bfloat16, wmma::row_major> vb;
            wmma::load_matrix_sync(pa, &Pw[k0 * 16], QPS);
            wmma::load_matrix_sync(vb, &Vs[(k0 * 16) * 16], 16);
            wmma::mma_sync(oacc, pa, vb, oacc);
        }
        __syncwarp();
    }

    // combine denominators across the 4-lane tg group, scale fragments, store direct
    dh0 += __shfl_xor_sync(0xffffffffu, dh0, 1);
    dh0 += __shfl_xor_sync(0xffffffffu, dh0, 2);
    dh1 += __shfl_xor_sync(0xffffffffu, dh1, 1);
    dh1 += __shfl_xor_sync(0xffffffffu, dh1, 2);
    float i0 = 1.0f / dh0, i1 = 1.0f / dh1;
    oacc.x[0] *= i0; oacc.x[1] *= i0; oacc.x[4] *= i0; oacc.x[5] *= i0;
    oacc.x[2] *= i1; oacc.x[3] *= i1; oacc.x[6] *= i1; oacc.x[7] *= i1;
    wmma::store_matrix_sync(&attn[(size_t)(q0 + wid * 16) * DIMC + h * 16], oacc, DIMC,
                            wmma::mem_row_major);
}

// ---------------- packq: w_qkv -> bf16 ----------------
__global__ void packq_kernel(const float* __restrict__ w_qkv) {
    for (int idx = blockIdx.x * blockDim.x + threadIdx.x; idx < DIMC * 384;
         idx += gridDim.x * blockDim.x)
        g_packQh[idx] = __float2bfloat16_rn(w_qkv[idx]);
}

// ---------------- packT (bf16) via tiled transpose ----------------
__global__ void packT_kernel(const float* __restrict__ w_edge) {
    __shared__ float tile[32][33];
    int h  = blockIdx.z;
    int k0 = blockIdx.x * 32;
    int j0 = blockIdx.y * 32;
    int tx = threadIdx.x, ty0 = threadIdx.y;
    #pragma unroll
    for (int i = 0; i < 4; i++) {
        int j = j0 + ty0 + i * 8;
        tile[ty0 + i * 8][tx] = w_edge[(size_t)j * HGC + h * 128 + k0 + tx];
    }
    __syncthreads();
    #pragma unroll
    for (int i = 0; i < 4; i++) {
        int k = k0 + ty0 + i * 8;
        g_packTh[h * 16384 + k * 128 + j0 + tx] = __float2bfloat16_rn(tile[tx][ty0 + i * 8]);
    }
}

// ---------------- pack [wq|wk|wv|wskip] bf16 + biases + packC bf16; zero g_deg ----------------
__global__ void packw_kernel(const float* __restrict__ wq, const float* __restrict__ wk,
                             const float* __restrict__ wv, const float* __restrict__ wsk,
                             const float* __restrict__ bq, const float* __restrict__ bk,
                             const float* __restrict__ bv, const float* __restrict__ bsk,
                             const float* __restrict__ w_edge) {
    for (int idx = blockIdx.x * blockDim.x + threadIdx.x; idx < DIMC * NPROJ;
         idx += gridDim.x * blockDim.x) {
        int k = idx / NPROJ, j = idx % NPROJ;
        float v;
        if (j < 1024)      v = wq[k * 1024 + j];
        else if (j < 2048) v = wk[k * 1024 + j - 1024];
        else if (j < 3072) v = wv[k * 1024 + j - 2048];
        else               v = wsk[k * 128 + j - 3072];
        g_packWh[idx] = __float2bfloat16_rn(v);
        if (idx < HEADSC * 128 * 128) {
            int jj = idx & 127;
            int kk = (idx >> 7) & 127;
            int hh = idx >> 14;
            g_packCh[idx] = __float2bfloat16_rn(w_edge[(size_t)kk * HGC + hh * 128 + jj]);
        }
        if (idx < NPROJ) {
            float bvv;
            if (idx < 1024)      bvv = bq[idx];
            else if (idx < 2048) bvv = bk[idx - 1024];
            else if (idx < 3072) bvv = bv[idx - 2048];
            else                 bvv = bsk[idx - 3072];
            g_packB[idx] = bvv;
        }
        if (idx < NN) g_deg[idx] = 0;
    }
}

// ---------------- CSR build ----------------
__global__ void hist_kernel(const int* __restrict__ ei) {
    const int* dst = ei + EC;
    for (int e = blockIdx.x * blockDim.x + threadIdx.x; e < EC; e += gridDim.x * blockDim.x)
        atomicAdd(&g_deg[dst[e]], 1);
}
__global__ void scan_kernel() {
    int t = threadIdx.x;
    int lane = t & 31, w = t >> 5;
    int base = t * 4;
    int d0 = g_deg[base], d1 = g_deg[base+1], d2 = g_deg[base+2], d3 = g_deg[base+3];
    int tot = d0 + d1 + d2 + d3;
    int v = tot;
    #pragma unroll
    for (int o = 1; o < 32; o <<= 1) {
        int u = __shfl_up_sync(0xffffffffu, v, o);
        if (lane >= o) v += u;
    }
    __shared__ int wsum[32];
    if (lane == 31) wsum[w] = v;
    __syncthreads();
    if (t < 32) {
        int wv = wsum[t];
        #pragma unroll
        for (int o = 1; o < 32; o <<= 1) {
            int u = __shfl_up_sync(0xffffffffu, wv, o);
            if (t >= o) wv += u;
        }
        wsum[t] = wv;
    }
    __syncthreads();
    int incl = v + (w ? wsum[w - 1] : 0);
    int run = incl - tot;
    g_off[base] = run;   g_cur[base] = run;     run += d0;
    g_off[base+1] = run; g_cur[base+1] = run;   run += d1;
    g_off[base+2] = run; g_cur[base+2] = run;   run += d2;
    g_off[base+3] = run; g_cur[base+3] = run;   run += d3;
    if (t == 1023) g_off[NN] = incl;
}
__global__ void scatter_kernel(const int* __restrict__ ei) {
    const int* dst = ei + EC;
    for (int e = blockIdx.x * blockDim.x + threadIdx.x; e < EC; e += gridDim.x * blockDim.x) {
        int p = atomicAdd(&g_cur[dst[e]], 1);
        g_eid[p] = e;
    }
}

// ---------------- graph aggregation: smem edge staging, bf16 kg/vg gathers ----------------
__global__ void graph_agg3_kernel(const int* __restrict__ ei,
                                  const float* __restrict__ edge_attr,
                                  const float* __restrict__ b_edge,
                                  const float* __restrict__ qkvg) {
    int n = blockIdx.x;
    int tid = threadIdx.x;
    int h = tid >> 5;
    int lane = tid & 31;
    const int* src = ei;
    const float invsq = 0.08838834764831845f;  // 1/sqrt(128)
    const int hoff = h * 128 + lane * 4;
    float4 qh = *(const float4*)&qkvg[(size_t)n * NPROJ + hoff];
    qh.x *= invsq; qh.y *= invsq; qh.z *= invsq; qh.w *= invsq;
    float4 th = *(const float4*)&g_t[n * HGC + hoff];
    th.x *= invsq; th.y *= invsq; th.z *= invsq; th.w *= invsq;
    float4 be4 = *(const float4*)&b_edge[hoff];
    float s0s = warp_sum(qh.x*be4.x + qh.y*be4.y + qh.z*be4.z + qh.w*be4.w);

    __shared__ float ea_s[8][132];
    __shared__ int src_s[8];
    float4 cacc = {0.f, 0.f, 0.f, 0.f};
    float4 vacc = {0.f, 0.f, 0.f, 0.f};
    float den = 0.0f;
    int beg = g_off[n], end = g_off[n + 1];

    for (int i0 = beg; i0 < end; i0 += 8) {
        int cnt = min(8, end - i0);
        __syncthreads();
        if (h < cnt) {
            int e = g_eid[i0 + h];
            if (lane == 0) src_s[h] = src[e];
            *(float4*)&ea_s[h][lane * 4] = *(const float4*)&edge_attr[(size_t)e * DIMC + lane * 4];
        }
        __syncthreads();
        int j = 0;
        for (; j + 3 < cnt; j += 4) {
            int sa = src_s[j], sb = src_s[j+1], sc = src_s[j+2], sd = src_s[j+3];
            float4 ea0 = *(const float4*)&ea_s[j  ][lane * 4];
            float4 ea1 = *(const float4*)&ea_s[j+1][lane * 4];
            float4 ea2 = *(const float4*)&ea_s[j+2][lane * 4];
            float4 ea3 = *(const float4*)&ea_s[j+3][lane * 4];
            float4 ka = ldkv(&g_kvh[(size_t)sa * 2048 + hoff]);
            float4 kb = ldkv(&g_kvh[(size_t)sb * 2048 + hoff]);
            float4 kc = ldkv(&g_kvh[(size_t)sc * 2048 + hoff]);
            float4 kd = ldkv(&g_kvh[(size_t)sd * 2048 + hoff]);
            float4 va = ldkv(&g_kvh[(size_t)sa * 2048 + 1024 + hoff]);
            float4 vb = ldkv(&g_kvh[(size_t)sb * 2048 + 1024 + hoff]);
            float4 vc = ldkv(&g_kvh[(size_t)sc * 2048 + 1024 + hoff]);
            float4 vd = ldkv(&g_kvh[(size_t)sd * 2048 + 1024 + hoff]);
            float t0 = qh.x*ka.x + qh.y*ka.y + qh.z*ka.z + qh.w*ka.w;
            t0 = fmaf(th.x, ea0.x, t0); t0 = fmaf(th.y, ea0.y, t0);
            t0 = fmaf(th.z, ea0.z, t0); t0 = fmaf(th.w, ea0.w, t0);
            float t1 = qh.x*kb.x + qh.y*kb.y + qh.z*kb.z + qh.w*kb.w;
            t1 = fmaf(th.x, ea1.x, t1); t1 = fmaf(th.y, ea1.y, t1);
            t1 = fmaf(th.z, ea1.z, t1); t1 = fmaf(th.w, ea1.w, t1);
            float t2 = qh.x*kc.x + qh.y*kc.y + qh.z*kc.z + qh.w*kc.w;
            t2 = fmaf(th.x, ea2.x, t2); t2 = fmaf(th.y, ea2.y, t2);
            t2 = fmaf(th.z, ea2.z, t2); t2 = fmaf(th.w, ea2.w, t2);
            float t3 = qh.x*kd.x + qh.y*kd.y + qh.z*kd.z + qh.w*kd.w;
            t3 = fmaf(th.x, ea3.x, t3); t3 = fmaf(th.y, ea3.y, t3);
            t3 = fmaf(th.z, ea3.z, t3); t3 = fmaf(th.w, ea3.w, t3);
            warp_sum4(t0, t1, t2, t3);
            float p0 = expf(t0 + s0s), p1 = expf(t1 + s0s);
            float p2 = expf(t2 + s0s), p3 = expf(t3 + s0s);
            den += (p0 + p1) + (p2 + p3);
            cacc.x = fmaf(p0, ea0.x, fmaf(p1, ea1.x, fmaf(p2, ea2.x, fmaf(p3, ea3.x, cacc.x))));
            cacc.y = fmaf(p0, ea0.y, fmaf(p1, ea1.y, fmaf(p2, ea2.y, fmaf(p3, ea3.y, cacc.y))));
            cacc.z = fmaf(p0, ea0.z, fmaf(p1, ea1.z, fmaf(p2, ea2.z, fmaf(p3, ea3.z, cacc.z))));
            cacc.w = fmaf(p0, ea0.w, fmaf(p1, ea1.w, fmaf(p2, ea2.w, fmaf(p3, ea3.w, cacc.w))));
            vacc.x = fmaf(p0, va.x, fmaf(p1, vb.x, fmaf(p2, vc.x, fmaf(p3, vd.x, vacc.x))));
            vacc.y = fmaf(p0, va.y, fmaf(p1, vb.y, fmaf(p2, vc.y, fmaf(p3, vd.y, vacc.y))));
            vacc.z = fmaf(p0, va.z, fmaf(p1, vb.z, fmaf(p2, vc.z, fmaf(p3, vd.z, vacc.z))));
            vacc.w = fmaf(p0, va.w, fmaf(p1, vb.w, fmaf(p2, vc.w, fmaf(p3, vd.w, vacc.w))));
        }
        for (; j < cnt; j++) {
            int s = src_s[j];
            float4 ea = *(const float4*)&ea_s[j][lane * 4];
            float4 k4 = ldkv(&g_kvh[(size_t)s * 2048 + hoff]);
            float4 v4 = ldkv(&g_kvh[(size_t)s * 2048 + 1024 + hoff]);
            float t = qh.x*k4.x + qh.y*k4.y + qh.z*k4.z + qh.w*k4.w;
            t = fmaf(th.x, ea.x, t); t = fmaf(th.y, ea.y, t);
            t = fmaf(th.z, ea.z, t); t = fmaf(th.w, ea.w, t);
            t = warp_sum(t) + s0s;
            float p = expf(t);
            den += p;
            cacc.x = fmaf(p, ea.x, cacc.x); cacc.y = fmaf(p, ea.y, cacc.y);
            cacc.z = fmaf(p, ea.z, cacc.z); cacc.w = fmaf(p, ea.w, cacc.w);
            vacc.x = fmaf(p, v4.x, vacc.x); vacc.y = fmaf(p, v4.y, vacc.y);
            vacc.z = fmaf(p, v4.z, vacc.z); vacc.w = fmaf(p, v4.w, vacc.w);
        }
    }
    bool nonempty = (end > beg);
    float invden = nonempty ? 1.0f / den : 0.0f;
    float4 c4 = {cacc.x*invden, cacc.y*invden, cacc.z*invden, cacc.w*invden};
    *(float4*)&g_cnorm[n * HGC + hoff] = c4;

    __shared__ float sh[8][128];
    float gate = nonempty ? 1.0f : 0.0f;
    __syncthreads();
    sh[h][lane*4+0] = fmaf(vacc.x, invden, be4.x * gate);
    sh[h][lane*4+1] = fmaf(vacc.y, invden, be4.y * gate);
    sh[h][lane*4+2] = fmaf(vacc.z, invden, be4.z * gate);
    sh[h][lane*4+3] = fmaf(vacc.w, invden, be4.w * gate);
    __syncthreads();
    if (tid < 128) {
        int d = tid;
        float sum = 0.0f;
        #pragma unroll
        for (int hh = 0; hh < 8; hh++) sum += sh[hh][d];
        g_vsum[n * DIMC + d] = sum;
    }
}

// ---------------- fused beta gate + combine + LN3 ----------------
__global__ void beta_ln_kernel(const float* __restrict__ wb,
                               const float* __restrict__ g3, const float* __restrict__ b3,
                               const float* __restrict__ qkvg) {
    int n = blockIdx.x, t = threadIdx.x;
    float o = g_aggout[n * DIMC + t] * 0.125f;
    float xr = qkvg[(size_t)n * NPROJ + 3072 + t];
    float part = o * (wb[t] + wb[256 + t]) + xr * (wb[128 + t] - wb[256 + t]);
    __shared__ float red[4];
    float s = warp_sum(part);
    if ((t & 31) == 0) red[t >> 5] = s;
    __syncthreads();
    float z = red[0] + red[1] + red[2] + red[3];
    float beta = 1.0f / (1.0f + expf(-z));
    float x2 = g_x1[n * DIMC + t] + beta * xr + (1.0f - beta) * o;
    g_x2[n * DIMC + t] = x2;
    __syncthreads();
    float sm = warp_sum(x2);
    if ((t & 31) == 0) red[t >> 5] = sm;
    __syncthreads();
    float mean = (red[0] + red[1] + red[2] + red[3]) * (1.0f / 128.0f);
    float d = x2 - mean;
    float s2 = warp_sum(d * d);
    __syncthreads();
    if ((t & 31) == 0) red[t >> 5] = s2;
    __syncthreads();
    float var = (red[0] + red[1] + red[2] + red[3]) * (1.0f / 128.0f);
    g_xn3[n * DIMC + t] = d * rsqrtf(var + 1e-5f) * g3[t] + b3[t];
}

// tile configs
#define WG_SMALL(MODE, KF)        wgemm<64,64,2,2,2,2,MODE,false,KF>
#define WG_NARROW(MODE, KF)       wgemm<64,32,2,2,2,1,MODE,false,KF>
#define WG_NARROW_DUAL(MODE, KF)  wgemm<64,32,2,2,2,1,MODE,true,KF>

// ---------------- launch ----------------
extern "C" void kernel_launch(void* const* d_in, const int* in_sizes, int n_in,
                              void* d_out, int out_size) {
    const float* x      = (const float*)d_in[0];
    const int*   ei     = (const int*)d_in[1];
    const float* eattr  = (const float*)d_in[2];
    const float* n1g = (const float*)d_in[3];  const float* n1b = (const float*)d_in[4];
    const float* n2g = (const float*)d_in[5];  const float* n2b = (const float*)d_in[6];
    const float* n3g = (const float*)d_in[7];  const float* n3b = (const float*)d_in[8];
    const float* w_qkv = (const float*)d_in[9];  const float* b_qkv = (const float*)d_in[10];
    const float* w_o   = (const float*)d_in[11]; const float* b_o   = (const float*)d_in[12];
    const float* w_query = (const float*)d_in[13]; const float* b_query = (const float*)d_in[14];
    const float* w_key   = (const float*)d_in[15]; const float* b_key   = (const float*)d_in[16];
    const float* w_value = (const float*)d_in[17]; const float* b_value = (const float*)d_in[18];
    const float* w_edge  = (const float*)d_in[19]; const float* b_edge  = (const float*)d_in[20];
    const float* w_skip  = (const float*)d_in[21]; const float* b_skip  = (const float*)d_in[22];
    const float* w_beta  = (const float*)d_in[23];
    const float* w_f1 = (const float*)d_in[24]; const float* b_f1 = (const float*)d_in[25];
    const float* w_f2 = (const float*)d_in[26]; const float* b_f2 = (const float*)d_in[27];
    const float* w_dyn = (const float*)d_in[28]; const float* b_dyn = (const float*)d_in[29];
    float* out = (float*)d_out;

    float *xn, *qkvb, *attnb, *x1, *xn2, *qkvg, *tb, *packB;
    float *cnorm, *vsum, *aggo, *xn3, *ffnb, *x3, *x2p;
    __nv_bfloat16 *packTh, *packCh, *packWh, *packQh;
    cudaGetSymbolAddress((void**)&xn,     g_xn);
    cudaGetSymbolAddress((void**)&qkvb,   g_qkv);
    cudaGetSymbolAddress((void**)&attnb,  g_attn);
    cudaGetSymbolAddress((void**)&x1,     g_x1);
    cudaGetSymbolAddress((void**)&xn2,    g_xn2);
    cudaGetSymbolAddress((void**)&qkvg,   g_qkvg);
    cudaGetSymbolAddress((void**)&tb,     g_t);
    cudaGetSymbolAddress((void**)&packTh, g_packTh);
    cudaGetSymbolAddress((void**)&packCh, g_packCh);
    cudaGetSymbolAddress((void**)&packWh, g_packWh);
    cudaGetSymbolAddress((void**)&packQh, g_packQh);
    cudaGetSymbolAddress((void**)&packB,  g_packB);
    cudaGetSymbolAddress((void**)&cnorm,  g_cnorm);
    cudaGetSymbolAddress((void**)&vsum,   g_vsum);
    cudaGetSymbolAddress((void**)&aggo,   g_aggout);
    cudaGetSymbolAddress((void**)&xn3,    g_xn3);
    cudaGetSymbolAddress((void**)&ffnb,   g_ffn);
    cudaGetSymbolAddress((void**)&x3,     g_x3);
    cudaGetSymbolAddress((void**)&x2p,    g_x2);
    float* qg = qkvg;

    // side stream for weight packing + CSR build
    static cudaStream_t s2 = nullptr;
    static cudaEvent_t evF = nullptr, evJ = nullptr;
    if (!s2) {
        cudaStreamCreateWithFlags(&s2, cudaStreamNonBlocking);
        cudaEventCreateWithFlags(&evF, cudaEventDisableTiming);
        cudaEventCreateWithFlags(&evJ, cudaEventDisableTiming);
    }
    cudaEventRecord(evF, 0);
    cudaStreamWaitEvent(s2, evF, 0);

    // ---- stream s2: packT, packw(+deg zero), hist, scan, scatter ----
    packT_kernel<<<dim3(4, 4, 8), dim3(32, 8), 0, s2>>>(w_edge);
    packw_kernel<<<512, 256, 0, s2>>>(w_query, w_key, w_value, w_skip,
                                      b_query, b_key, b_value, b_skip, w_edge);
    hist_kernel<<<256, 256, 0, s2>>>(ei);
    scan_kernel<<<1, 1024, 0, s2>>>();
    scatter_kernel<<<256, 256, 0, s2>>>(ei);
    cudaEventRecord(evJ, s2);

    // ---- main stream ----
    packq_kernel<<<64, 256>>>(w_qkv);
    ln_kernel<<<NN, 128>>>(x, n1g, n1b, xn);
    // QKV projection (bf16, 4096 x 384, K=128)
    hgemm<0, 128><<<dim3(6, 64, 1), 128>>>(xn, packQh, b_qkv, qkvb,
                                           128, 128, 384, 384, 0, 0, 0, nullptr);
    // dense MHA (bf16 wmma flash-style)
    attn_bf16_kernel<<<dim3(NN/128, HEADSC), 256>>>(qkvb, attnb);
    // out proj + residual (tf32)
    WG_NARROW(2, 128)<<<dim3(4, 64, 1), 128>>>(attnb, w_o, b_o, x1, 128, 128, 128, 128,
                                               0, 0, 0, 0, x, nullptr, nullptr);
    ln_kernel<<<NN, 128>>>(x1, n2g, n2b, xn2);

    cudaStreamWaitEvent(0, evJ, 0);

    // merged projections q|k|v|skip (bf16; MODE 6 side-writes g_kvh)
    hgemm<6, 128><<<dim3(NPROJ/64, 64, 1), 128>>>(xn2, packWh, packB, qkvg,
                                                  128, 128, NPROJ, NPROJ, 0, 0, 0, nullptr);
    // batched t-GEMM (bf16, direct store)
    hgemm<5, 128><<<dim3(2, 64, 8), 128>>>(qg, packTh, nullptr, tb,
                                           128, NPROJ, 128, HGC, 128, 128*128, 128, nullptr);
    // eg-free segment-softmax aggregation (bf16 gathers)
    graph_agg3_kernel<<<NN, 256>>>(ei, eattr, b_edge, qkvg);
    // c-GEMM (bf16): aggout = cnorm @ packC + vsum
    hgemm<4, 0><<<dim3(2, 64, 1), 128>>>(cnorm, packCh, nullptr, aggo,
                                         HGC, HGC, 128, 128, 0, 0, 0, vsum);
    // fused beta gate + combine + LN3
    beta_ln_kernel<<<NN, 128>>>(w_beta, n3g, n3b, qkvg);
    // FFN up + GELU (tf32)
    WG_SMALL(1, 128)<<<dim3(32, 64, 1), 128>>>(xn3, w_f1, b_f1, ffnb, 128, 128, FFNC, FFNC,
                                               0, 0, 0, 0, nullptr, nullptr, nullptr);
    // FFN down + residual (tf32)
    WG_NARROW(2, 0)<<<dim3(4, 64, 1), 128>>>(ffnb, w_f2, b_f2, x3, FFNC, FFNC, 128, 128,
                                             0, 0, 0, 0, x2p, nullptr, nullptr);
    // dyn gate (tf32, dual-A = [x3 | x])
    WG_NARROW_DUAL(3, 256)<<<dim3(4, 64, 1), 128>>>(x3, w_dyn, b_dyn, out, 256, 128, 128, 128,
                                                    0, 0, 0, 0, x3, x, x);
}